// round 9
// baseline (speedup 1.0000x reference)
#include <cuda_runtime.h>
#include <cuda_bf16.h>

typedef unsigned long long u64;

#define N_NODES 50000
#define N_EDGES 800000
#define HID 128
#define EH 64
#define FSTR 132            // floats per edge row in feat buffer (bank-spread)
#define EK_WARPS 16

// ---------------- scratch (no allocs allowed) ----------------
__device__ float g_h[N_NODES * HID];
__device__ float g_agg[N_NODES * EH];
__device__ int   g_mask_u8;
__device__ int   g_ne_c[2];                 // compacted edge counts
__device__ int   g_rows_c[2][N_EDGES];
__device__ int   g_cols_c[2][N_EDGES];
__device__ int   g_nn_c[2];                 // compacted node counts
__device__ int   g_nodes_c[2][N_NODES];

__device__ __forceinline__ float silu(float x) {
    return x / (1.0f + __expf(-x));
}
__device__ __forceinline__ u64 ffma2(u64 a, u64 b, u64 c) {
    u64 d;
    asm("fma.rn.f32x2 %0, %1, %2, %3;" : "=l"(d) : "l"(a), "l"(b), "l"(c));
    return d;
}
__device__ __forceinline__ float lo32(u64 a) { return __uint_as_float((unsigned)a); }
__device__ __forceinline__ float hi32(u64 a) { return __uint_as_float((unsigned)(a >> 32)); }
__device__ __forceinline__ u64 packf2(float lo, float hi) {
    return (u64)__float_as_uint(lo) | ((u64)__float_as_uint(hi) << 32);
}
__device__ __forceinline__ void cp16(unsigned dst_smem, const void* src) {
    asm volatile("cp.async.cg.shared.global [%0], [%1], 16;"
                 :: "r"(dst_smem), "l"(src));
}
__device__ __forceinline__ void cp_commit() {
    asm volatile("cp.async.commit_group;");
}
template<int N> __device__ __forceinline__ void cp_wait() {
    asm volatile("cp.async.wait_group %0;" :: "n"(N));
}
// vector fp32 reduction (sm_90+): one 8B atomic add, no return
__device__ __forceinline__ void red2(float* addr, float x, float y) {
    asm volatile("red.global.add.v2.f32 [%0], {%1, %2};"
                 :: "l"(addr), "f"(x), "f"(y) : "memory");
}

// ---------------- mask dtype detection + counter reset ----------------
__global__ void detect_mask_kernel(const unsigned int* __restrict__ m) {
    if (threadIdx.x < 2) { g_ne_c[threadIdx.x] = 0; g_nn_c[threadIdx.x] = 0; }
    int bad = 0;
    for (int i = threadIdx.x; i < N_NODES / 4; i += blockDim.x)
        if (m[i] > 1u) bad = 1;
    bad = __syncthreads_or(bad);
    if (threadIdx.x == 0) g_mask_u8 = bad;
}

// ---------------- edge compaction (warp-atomic, order-free) ----------------
__global__ void __launch_bounds__(256)
compact_kernel(const int* __restrict__ edges, const void* __restrict__ mask, int li) {
    const int* rows = edges;
    const int* cols = edges + N_EDGES;
    int e = blockIdx.x * 256 + threadIdx.x;
    int lane = threadIdx.x & 31;
    int mu8 = g_mask_u8;

    bool valid = false; int rv = 0, cv = 0;
    if (e < N_EDGES) {
        rv = rows[e]; cv = cols[e];
        valid = mu8 ? (((const unsigned char*)mask)[rv] != 0)
                    : (((const int*)mask)[rv] != 0);
    }
    unsigned bal = __ballot_sync(0xffffffffu, valid);
    int base = 0;
    if (lane == 0 && bal) base = atomicAdd(&g_ne_c[li], __popc(bal));
    base = __shfl_sync(0xffffffffu, base, 0);
    if (valid) {
        int p = base + __popc(bal & ((1u << lane) - 1u));
        g_rows_c[li][p] = rv;
        g_cols_c[li][p] = cv;
    }
}

// ---------------- node compaction (warp-atomic) ----------------
__global__ void __launch_bounds__(256)
compact_nodes_kernel(const void* __restrict__ mask, int li) {
    int n = blockIdx.x * 256 + threadIdx.x;
    int lane = threadIdx.x & 31;
    int mu8 = g_mask_u8;

    bool valid = false;
    if (n < N_NODES)
        valid = mu8 ? (((const unsigned char*)mask)[n] != 0)
                    : (((const int*)mask)[n] != 0);
    unsigned bal = __ballot_sync(0xffffffffu, valid);
    int base = 0;
    if (lane == 0 && bal) base = atomicAdd(&g_nn_c[li], __popc(bal));
    base = __shfl_sync(0xffffffffu, base, 0);
    if (valid)
        g_nodes_c[li][base + __popc(bal & ((1u << lane) - 1u))] = n;
}

// ---------------- zero aggregation buffer (once; nodes re-zero after use) ----------------
__global__ void zero_agg_kernel() {
    int i = blockIdx.x * blockDim.x + threadIdx.x;   // 800000 float4
    reinterpret_cast<float4*>(g_agg)[i] = make_float4(0.f, 0.f, 0.f, 0.f);
}

// ---------------- input embedding (FFMA2, 4 rows/warp) ----------------
__global__ void __launch_bounds__(512, 1)
embed_in_kernel(const float* __restrict__ h_in,
                const float* __restrict__ W,
                const float* __restrict__ b) {
    extern __shared__ char smraw[];
    u64* Wp = (u64*)smraw;              // 32 kk * 128 cols
    float* bs = (float*)(Wp + 4096);    // 128
    float* xAll = bs + 128;             // 16 warps * 4 rows * 72

    int tid = threadIdx.x;
    for (int i = tid; i < 4096; i += 512) {
        int kk = i >> 7, c = i & 127;
        Wp[i] = packf2(W[(2 * kk) * 128 + c], W[(2 * kk + 1) * 128 + c]);
    }
    if (tid < 128) bs[tid] = b[tid];
    __syncthreads();

    int wid = tid >> 5, lane = tid & 31;
    float* xS = xAll + wid * 288;
    int c0 = 2 * lane, c1 = 64 + 2 * lane;
    float bb[4] = {bs[c0], bs[c0 + 1], bs[c1], bs[c1 + 1]};

    for (int t = blockIdx.x * 16 + wid; t < N_NODES / 4; t += gridDim.x * 16) {
        int r0 = 4 * t;
        for (int i = lane; i < 64; i += 32) {         // 4 rows x 16 float4
            int rr = i >> 4, v = i & 15;
            *(float4*)(xS + rr * 72 + 4 * v) =
                *(const float4*)(h_in + (r0 + rr) * 64 + 4 * v);
        }
        __syncwarp();
        u64 acc[16];
#pragma unroll
        for (int j = 0; j < 16; j++) acc[j] = 0ull;
#pragma unroll 4
        for (int kk = 0; kk < 32; kk++) {
            const u64* wr = Wp + kk * 128;
            ulonglong2 wA = *(const ulonglong2*)(wr + c0);
            ulonglong2 wB = *(const ulonglong2*)(wr + c1);
#pragma unroll
            for (int j = 0; j < 4; j++) {
                u64 f = *(const u64*)(xS + j * 72 + 2 * kk);
                acc[4 * j]     = ffma2(f, wA.x, acc[4 * j]);
                acc[4 * j + 1] = ffma2(f, wA.y, acc[4 * j + 1]);
                acc[4 * j + 2] = ffma2(f, wB.x, acc[4 * j + 2]);
                acc[4 * j + 3] = ffma2(f, wB.y, acc[4 * j + 3]);
            }
        }
#pragma unroll
        for (int j = 0; j < 4; j++) {
            float2 oA, oB;
            oA.x = lo32(acc[4 * j])     + hi32(acc[4 * j])     + bb[0];
            oA.y = lo32(acc[4 * j + 1]) + hi32(acc[4 * j + 1]) + bb[1];
            oB.x = lo32(acc[4 * j + 2]) + hi32(acc[4 * j + 2]) + bb[2];
            oB.y = lo32(acc[4 * j + 3]) + hi32(acc[4 * j + 3]) + bb[3];
            *(float2*)(g_h + (r0 + j) * 128 + c0) = oA;
            *(float2*)(g_h + (r0 + j) * 128 + c1) = oB;
        }
        __syncwarp();
    }
}
#define EMBI_SMEM (4096 * 8 + 128 * 4 + 16 * 288 * 4)

// ---------------- output embedding (FFMA2, 8 rows/warp) ----------------
__global__ void __launch_bounds__(512, 1)
embed_out_kernel(const float* __restrict__ W,
                 const float* __restrict__ b,
                 float* __restrict__ out) {
    extern __shared__ char smraw[];
    u64* Wp = (u64*)smraw;              // 64 kk * 64 cols
    float* bs = (float*)(Wp + 4096);    // 64
    float* xAll = bs + 64;              // 16 warps * 8 rows * 136

    int tid = threadIdx.x;
    for (int i = tid; i < 4096; i += 512) {
        int kk = i >> 6, c = i & 63;
        Wp[i] = packf2(W[(2 * kk) * 64 + c], W[(2 * kk + 1) * 64 + c]);
    }
    if (tid < 64) bs[tid] = b[tid];
    __syncthreads();

    int wid = tid >> 5, lane = tid & 31;
    float* xS = xAll + wid * 1088;
    int c0 = 2 * lane;
    float bb0 = bs[c0], bb1 = bs[c0 + 1];

    for (int t = blockIdx.x * 16 + wid; t < N_NODES / 8; t += gridDim.x * 16) {
        int r0 = 8 * t;
        for (int i = lane; i < 256; i += 32) {        // 8 rows x 32 float4
            int rr = i >> 5, v = i & 31;
            *(float4*)(xS + rr * 136 + 4 * v) =
                *(const float4*)(g_h + (r0 + rr) * 128 + 4 * v);
        }
        __syncwarp();
        u64 acc[16];
#pragma unroll
        for (int j = 0; j < 16; j++) acc[j] = 0ull;
#pragma unroll 4
        for (int kk = 0; kk < 64; kk++) {
            ulonglong2 w = *(const ulonglong2*)(Wp + kk * 64 + c0);
#pragma unroll
            for (int j = 0; j < 8; j++) {
                u64 f = *(const u64*)(xS + j * 136 + 2 * kk);
                acc[2 * j]     = ffma2(f, w.x, acc[2 * j]);
                acc[2 * j + 1] = ffma2(f, w.y, acc[2 * j + 1]);
            }
        }
#pragma unroll
        for (int j = 0; j < 8; j++) {
            float2 o;
            o.x = lo32(acc[2 * j])     + hi32(acc[2 * j])     + bb0;
            o.y = lo32(acc[2 * j + 1]) + hi32(acc[2 * j + 1]) + bb1;
            *(float2*)(out + (r0 + j) * 64 + c0) = o;
        }
        __syncwarp();
    }
}
#define EMBO_SMEM (4096 * 8 + 64 * 4 + 16 * 1088 * 4)

// ---------------- edge MLP inner block (FFMA2) ----------------
template<int NKK>
__device__ __forceinline__ void mlp64(const float* f0p, const float* f1p,
                                      const u64* Wp, int cg, u64* acc) {
#pragma unroll 4
    for (int kk = 0; kk < NKK; kk++) {
        u64 f0 = *(const u64*)(f0p + 2 * kk);
        u64 f1 = *(const u64*)(f1p + 2 * kk);
        const u64* wr = Wp + kk * 64;
        ulonglong2 w0 = *(const ulonglong2*)(wr + 2 * cg);
        ulonglong2 w1 = *(const ulonglong2*)(wr + 16 + 2 * cg);
        ulonglong2 w2 = *(const ulonglong2*)(wr + 32 + 2 * cg);
        ulonglong2 w3 = *(const ulonglong2*)(wr + 48 + 2 * cg);
        acc[0] = ffma2(f0, w0.x, acc[0]);   acc[1] = ffma2(f0, w0.y, acc[1]);
        acc[2] = ffma2(f0, w1.x, acc[2]);   acc[3] = ffma2(f0, w1.y, acc[3]);
        acc[4] = ffma2(f0, w2.x, acc[4]);   acc[5] = ffma2(f0, w2.y, acc[5]);
        acc[6] = ffma2(f0, w3.x, acc[6]);   acc[7] = ffma2(f0, w3.y, acc[7]);
        acc[8] = ffma2(f1, w0.x, acc[8]);   acc[9] = ffma2(f1, w0.y, acc[9]);
        acc[10] = ffma2(f1, w1.x, acc[10]); acc[11] = ffma2(f1, w1.y, acc[11]);
        acc[12] = ffma2(f1, w2.x, acc[12]); acc[13] = ffma2(f1, w2.y, acc[13]);
        acc[14] = ffma2(f1, w3.x, acc[14]); acc[15] = ffma2(f1, w3.y, acc[15]);
    }
}

// ---------------- edge kernel (FFMA2 + cp.async double-buffered gather) ----------------
__global__ void __launch_bounds__(512, 1)
edge_kernel(int li,
            const float* __restrict__ W1, const float* __restrict__ b1,
            const float* __restrict__ W2, const float* __restrict__ b2,
            float C) {
    extern __shared__ char smraw[];
    u64* Wp1 = (u64*)smraw;                 // 8192 u64
    u64* Wp2 = Wp1 + 8192;                  // 2048 u64
    float* b1s = (float*)(Wp2 + 2048);      // 64
    float* b2s = b1s + 64;                  // 64
    float* bufA_all = b2s + 64;             // 16 * 8 * FSTR
    float* bufB_all = bufA_all + EK_WARPS * 8 * FSTR;
    __shared__ int idxS[EK_WARPS][2][16];

    int tid = threadIdx.x;
    for (int i = tid; i < 8192; i += 512) {
        int kk = i >> 6, c = i & 63;
        Wp1[i] = packf2(W1[(2 * kk) * 64 + c], W1[(2 * kk + 1) * 64 + c]);
    }
    for (int i = tid; i < 2048; i += 512) {
        int kk = i >> 6, c = i & 63;
        Wp2[i] = packf2(W2[(2 * kk) * 64 + c], W2[(2 * kk + 1) * 64 + c]);
    }
    if (tid < 64) { b1s[tid] = b1[tid]; b2s[tid] = b2[tid]; }
    __syncthreads();

    int wid = tid >> 5, lane = tid & 31;
    int er = lane >> 3, cg = lane & 7;
    float* bufA = bufA_all + wid * (8 * FSTR);
    float* bufB = bufB_all + wid * (8 * FSTR);
    unsigned bufA_s = (unsigned)__cvta_generic_to_shared(bufA);
    unsigned bufB_s = (unsigned)__cvta_generic_to_shared(bufB);

    int colb[4] = {2 * cg, 16 + 2 * cg, 32 + 2 * cg, 48 + 2 * cg};
    float bb1[8], bb2[8];
#pragma unroll
    for (int q = 0; q < 4; q++) {
        bb1[2 * q] = b1s[colb[q]]; bb1[2 * q + 1] = b1s[colb[q] + 1];
        bb2[2 * q] = b2s[colb[q]]; bb2[2 * q + 1] = b2s[colb[q] + 1];
    }

    int nE = g_ne_c[li];
    const int* rows = g_rows_c[li];
    const int* cols = g_cols_c[li];
    int ngroups = (nE + 7) >> 3;
    int nw = gridDim.x * EK_WARPS;
    int g = blockIdx.x * EK_WARPS + wid;
    int cur = 0;

    const float* fA0 = bufA + er * FSTR;
    const float* fA1 = bufA + (er + 4) * FSTR;
    const float* fB0 = bufB + er * FSTR;
    const float* fB1 = bufB + (er + 4) * FSTR;

    if (g < ngroups) {
        if (lane < 16) {
            int e = g * 8 + (lane & 7);
            if (e >= nE) e = nE - 1;
            idxS[wid][0][lane] = (lane < 8) ? rows[e] : cols[e];
        }
        __syncwarp();
#pragma unroll
        for (int e = 0; e < 8; e++)
            cp16(bufA_s + (e * FSTR + 4 * lane) * 4,
                 g_h + (size_t)idxS[wid][0][e] * 128 + 4 * lane);
    }
    cp_commit();

    for (; g < ngroups; g += nw) {
        int* idx = idxS[wid][cur];
        // prefetch cols(current) -> bufB
#pragma unroll
        for (int e = 0; e < 8; e++)
            cp16(bufB_s + (e * FSTR + 4 * lane) * 4,
                 g_h + (size_t)idx[8 + e] * 128 + 4 * lane);
        cp_commit();
        cp_wait<1>(); __syncwarp();          // bufA (rows) ready

        u64 acc[16];
#pragma unroll
        for (int j = 0; j < 16; j++) acc[j] = 0ull;
        mlp64<64>(fA0, fA1, Wp1, cg, acc);   // layer1 pass1 (k 0..127)
        __syncwarp();                        // all lanes done reading bufA

        int gn = g + nw;
        int* idxn = idxS[wid][cur ^ 1];
        if (gn < ngroups) {
            if (lane < 16) {
                int e = gn * 8 + (lane & 7);
                if (e >= nE) e = nE - 1;
                idxn[lane] = (lane < 8) ? rows[e] : cols[e];
            }
            __syncwarp();
#pragma unroll
            for (int e = 0; e < 8; e++)
                cp16(bufA_s + (e * FSTR + 4 * lane) * 4,
                     g_h + (size_t)idxn[e] * 128 + 4 * lane);
        }
        cp_commit();
        cp_wait<1>(); __syncwarp();          // bufB (cols) ready

        mlp64<64>(fB0, fB1, Wp1 + 4096, cg, acc);  // layer1 pass2 (k 128..255)
        __syncwarp();

        // finalize layer1: m = silu(lo+hi+b1), stored into bufB
#pragma unroll
        for (int q = 0; q < 4; q++) {
            float2 m0, m1;
            m0.x = silu(lo32(acc[2*q])     + hi32(acc[2*q])     + bb1[2*q]);
            m0.y = silu(lo32(acc[2*q+1])   + hi32(acc[2*q+1])   + bb1[2*q+1]);
            m1.x = silu(lo32(acc[8+2*q])   + hi32(acc[8+2*q])   + bb1[2*q]);
            m1.y = silu(lo32(acc[8+2*q+1]) + hi32(acc[8+2*q+1]) + bb1[2*q+1]);
            *(float2*)(bufB + er * FSTR + colb[q]) = m0;
            *(float2*)(bufB + (er + 4) * FSTR + colb[q]) = m1;
        }
        __syncwarp();

        // layer2 (64 -> 64)
        u64 acc2[16];
#pragma unroll
        for (int j = 0; j < 16; j++) acc2[j] = 0ull;
        mlp64<32>(fB0, fB1, Wp2, cg, acc2);

        // scatter: agg[row] += silu(out) * C  (vector red, 8B per op)
        int e0g = g * 8;
        bool vA = (e0g + er) < nE;
        bool vB = (e0g + er + 4) < nE;
        int rA = idx[er], rB = idx[er + 4];
#pragma unroll
        for (int q = 0; q < 4; q++) {
            if (vA) {
                float* a = g_agg + rA * 64 + colb[q];
                red2(a, silu(lo32(acc2[2*q])   + hi32(acc2[2*q])   + bb2[2*q])   * C,
                        silu(lo32(acc2[2*q+1]) + hi32(acc2[2*q+1]) + bb2[2*q+1]) * C);
            }
            if (vB) {
                float* a = g_agg + rB * 64 + colb[q];
                red2(a, silu(lo32(acc2[8+2*q])   + hi32(acc2[8+2*q])   + bb2[2*q])   * C,
                        silu(lo32(acc2[8+2*q+1]) + hi32(acc2[8+2*q+1]) + bb2[2*q+1]) * C);
            }
        }
        __syncwarp();   // bufB reads done before next iteration's cols prefetch
        cur ^= 1;
    }
}
#define EDGE_SMEM_BYTES (8192*8 + 2048*8 + 128*4 + 2*EK_WARPS*8*FSTR*4)

// ---------------- node kernel (FFMA2, 4 compacted rows/warp; re-zeroes agg) ----------------
__global__ void __launch_bounds__(512, 1)
node_kernel(int li,
            const float* __restrict__ W1, const float* __restrict__ b1,
            const float* __restrict__ W2, const float* __restrict__ b2) {
    extern __shared__ char smraw[];
    u64* Wp1 = (u64*)smraw;                 // 96 kk * 128 cols
    u64* Wp2 = Wp1 + 12288;                 // 64 kk * 128 cols
    float* b1s = (float*)(Wp2 + 8192);      // 128
    float* b2s = b1s + 128;                 // 128
    float* xAll = b2s + 128;                // 16 warps * 4 rows * 200

    int tid = threadIdx.x;
    for (int i = tid; i < 12288; i += 512) {
        int kk = i >> 7, c = i & 127;
        Wp1[i] = packf2(W1[(2 * kk) * 128 + c], W1[(2 * kk + 1) * 128 + c]);
    }
    for (int i = tid; i < 8192; i += 512) {
        int kk = i >> 7, c = i & 127;
        Wp2[i] = packf2(W2[(2 * kk) * 128 + c], W2[(2 * kk + 1) * 128 + c]);
    }
    if (tid < 128) { b1s[tid] = b1[tid]; b2s[tid] = b2[tid]; }
    __syncthreads();

    int wid = tid >> 5, lane = tid & 31;
    float* xS = xAll + wid * 800;
    int c0 = 2 * lane, c1 = 64 + 2 * lane;
    float bb1[4] = {b1s[c0], b1s[c0 + 1], b1s[c1], b1s[c1 + 1]};
    float bb2[4] = {b2s[c0], b2s[c0 + 1], b2s[c1], b2s[c1 + 1]};

    int nn = g_nn_c[li];
    const int* list = g_nodes_c[li];
    int ntiles = (nn + 3) >> 2;
    for (int t = blockIdx.x * 16 + wid; t < ntiles; t += gridDim.x * 16) {
        int rid[4]; bool rv[4];
#pragma unroll
        for (int j = 0; j < 4; j++) {
            int p = 4 * t + j;
            rv[j] = p < nn;
            rid[j] = list[rv[j] ? p : (nn - 1)];
        }
        // gather x = [h || agg]
#pragma unroll
        for (int j = 0; j < 4; j++) {
            for (int v = lane; v < 48; v += 32) {
                float4 val = (v < 32) ? *(const float4*)(g_h + (size_t)rid[j] * 128 + 4 * v)
                                      : *(const float4*)(g_agg + (size_t)rid[j] * 64 + 4 * (v - 32));
                *(float4*)(xS + j * 200 + 4 * v) = val;
            }
        }
        __syncwarp();

        u64 acc[16];
#pragma unroll
        for (int j = 0; j < 16; j++) acc[j] = 0ull;
#pragma unroll 2
        for (int kk = 0; kk < 96; kk++) {
            const u64* wr = Wp1 + kk * 128;
            ulonglong2 wA = *(const ulonglong2*)(wr + c0);
            ulonglong2 wB = *(const ulonglong2*)(wr + c1);
#pragma unroll
            for (int j = 0; j < 4; j++) {
                u64 f = *(const u64*)(xS + j * 200 + 2 * kk);
                acc[4 * j]     = ffma2(f, wA.x, acc[4 * j]);
                acc[4 * j + 1] = ffma2(f, wA.y, acc[4 * j + 1]);
                acc[4 * j + 2] = ffma2(f, wB.x, acc[4 * j + 2]);
                acc[4 * j + 3] = ffma2(f, wB.y, acc[4 * j + 3]);
            }
        }
        __syncwarp();   // all lanes done reading x before m overwrites

        float res[16];
#pragma unroll
        for (int j = 0; j < 4; j++) {
            res[4 * j]     = xS[j * 200 + c0];
            res[4 * j + 1] = xS[j * 200 + c0 + 1];
            res[4 * j + 2] = xS[j * 200 + c1];
            res[4 * j + 3] = xS[j * 200 + c1 + 1];
        }
#pragma unroll
        for (int j = 0; j < 4; j++) {
            float2 mA, mB;
            mA.x = silu(lo32(acc[4*j])     + hi32(acc[4*j])     + bb1[0]);
            mA.y = silu(lo32(acc[4*j+1])   + hi32(acc[4*j+1])   + bb1[1]);
            mB.x = silu(lo32(acc[4*j+2])   + hi32(acc[4*j+2])   + bb1[2]);
            mB.y = silu(lo32(acc[4*j+3])   + hi32(acc[4*j+3])   + bb1[3]);
            *(float2*)(xS + j * 200 + c0) = mA;
            *(float2*)(xS + j * 200 + c1) = mB;
        }
        __syncwarp();

#pragma unroll
        for (int j = 0; j < 16; j++) acc[j] = 0ull;
#pragma unroll 2
        for (int kk = 0; kk < 64; kk++) {
            const u64* wr = Wp2 + kk * 128;
            ulonglong2 wA = *(const ulonglong2*)(wr + c0);
            ulonglong2 wB = *(const ulonglong2*)(wr + c1);
#pragma unroll
            for (int j = 0; j < 4; j++) {
                u64 f = *(const u64*)(xS + j * 200 + 2 * kk);
                acc[4 * j]     = ffma2(f, wA.x, acc[4 * j]);
                acc[4 * j + 1] = ffma2(f, wA.y, acc[4 * j + 1]);
                acc[4 * j + 2] = ffma2(f, wB.x, acc[4 * j + 2]);
                acc[4 * j + 3] = ffma2(f, wB.y, acc[4 * j + 3]);
            }
        }
#pragma unroll
        for (int j = 0; j < 4; j++) {
            if (!rv[j]) continue;
            float2 oA, oB;
            oA.x = res[4*j]     + lo32(acc[4*j])     + hi32(acc[4*j])     + bb2[0];
            oA.y = res[4*j+1]   + lo32(acc[4*j+1])   + hi32(acc[4*j+1])   + bb2[1];
            oB.x = res[4*j+2]   + lo32(acc[4*j+2])   + hi32(acc[4*j+2])   + bb2[2];
            oB.y = res[4*j+3]   + lo32(acc[4*j+3])   + hi32(acc[4*j+3])   + bb2[3];
            *(float2*)(g_h + (size_t)rid[j] * 128 + c0) = oA;
            *(float2*)(g_h + (size_t)rid[j] * 128 + c1) = oB;
        }
        // consume-and-zero: restore agg rows of this tile to 0 for the next layer
#pragma unroll
        for (int j = 0; j < 4; j++) {
            if (rv[j] && lane < 16)
                *(float4*)(g_agg + (size_t)rid[j] * 64 + 4 * lane) =
                    make_float4(0.f, 0.f, 0.f, 0.f);
        }
        __syncwarp();
    }
}
#define NODE_SMEM_BYTES (12288*8 + 8192*8 + 256*4 + 16*800*4)

// ---------------- launch ----------------
extern "C" void kernel_launch(void* const* d_in, const int* in_sizes, int n_in,
                              void* d_out, int out_size) {
    const float* h_in = (const float*)d_in[0];
    const int*   eA   = (const int*)d_in[1];
    const int*   eB   = (const int*)d_in[2];
    const void*  mA   = d_in[3];
    const void*  mB   = d_in[4];
    const float* Wi   = (const float*)d_in[5];
    const float* bi   = (const float*)d_in[6];
    const float* Wo   = (const float*)d_in[7];
    const float* bo   = (const float*)d_in[8];
    const float* ew1  = (const float*)d_in[9];
    const float* eb1  = (const float*)d_in[10];
    const float* ew2  = (const float*)d_in[11];
    const float* eb2  = (const float*)d_in[12];
    const float* nw1  = (const float*)d_in[13];
    const float* nb1  = (const float*)d_in[14];
    const float* nw2  = (const float*)d_in[15];
    const float* nb2  = (const float*)d_in[16];
    float* out = (float*)d_out;

    cudaFuncSetAttribute(edge_kernel, cudaFuncAttributeMaxDynamicSharedMemorySize,
                         EDGE_SMEM_BYTES);
    cudaFuncSetAttribute(node_kernel, cudaFuncAttributeMaxDynamicSharedMemorySize,
                         NODE_SMEM_BYTES);
    cudaFuncSetAttribute(embed_in_kernel, cudaFuncAttributeMaxDynamicSharedMemorySize,
                         EMBI_SMEM);
    cudaFuncSetAttribute(embed_out_kernel, cudaFuncAttributeMaxDynamicSharedMemorySize,
                         EMBO_SMEM);

    detect_mask_kernel<<<1, 256>>>((const unsigned int*)mA);
    compact_kernel<<<3125, 256>>>(eA, mA, 0);
    compact_kernel<<<3125, 256>>>(eB, mB, 1);
    compact_nodes_kernel<<<196, 256>>>(mA, 0);
    compact_nodes_kernel<<<196, 256>>>(mB, 1);
    zero_agg_kernel<<<3125, 256>>>();        // once; node kernels keep it clean
    embed_in_kernel<<<148, 512, EMBI_SMEM>>>(h_in, Wi, bi);

    for (int i = 0; i < 4; i++) {
        int li = i % 2;
        float C = (li == 0) ? 1.0f : (2.0f / 64.0f);

        edge_kernel<<<148, 512, EDGE_SMEM_BYTES>>>(
            li, ew1 + i * 256 * 64, eb1 + i * 64,
            ew2 + i * 64 * 64, eb2 + i * 64, C);
        node_kernel<<<148, 512, NODE_SMEM_BYTES>>>(
            li, nw1 + i * 192 * 128, nb1 + i * 128,
            nw2 + i * 128 * 128, nb2 + i * 128);
    }

    embed_out_kernel<<<148, 512, EMBO_SMEM>>>(Wo, bo, out);
}

// round 10
// speedup vs baseline: 1.0574x; 1.0574x over previous
#include <cuda_runtime.h>
#include <cuda_bf16.h>

typedef unsigned long long u64;

#define N_NODES 50000
#define N_EDGES 800000
#define HID 128
#define EH 64
#define FSTR 132            // floats per edge row in feat buffer (bank-spread)
#define EK_WARPS 16

// ---------------- scratch (no allocs allowed) ----------------
__device__ float g_h[N_NODES * HID];
__device__ float g_agg[N_NODES * EH];
__device__ int   g_mask_u8;
__device__ int   g_ne_c[2];                 // compacted edge counts
__device__ int   g_rows_c[2][N_EDGES];
__device__ int   g_cols_c[2][N_EDGES];
__device__ int   g_nn_c[2];                 // compacted node counts
__device__ int   g_nodes_c[2][N_NODES];

__device__ __forceinline__ float silu(float x) {
    return x / (1.0f + __expf(-x));
}
__device__ __forceinline__ u64 ffma2(u64 a, u64 b, u64 c) {
    u64 d;
    asm("fma.rn.f32x2 %0, %1, %2, %3;" : "=l"(d) : "l"(a), "l"(b), "l"(c));
    return d;
}
__device__ __forceinline__ float lo32(u64 a) { return __uint_as_float((unsigned)a); }
__device__ __forceinline__ float hi32(u64 a) { return __uint_as_float((unsigned)(a >> 32)); }
__device__ __forceinline__ u64 packf2(float lo, float hi) {
    return (u64)__float_as_uint(lo) | ((u64)__float_as_uint(hi) << 32);
}
__device__ __forceinline__ void cp16(unsigned dst_smem, const void* src) {
    asm volatile("cp.async.cg.shared.global [%0], [%1], 16;"
                 :: "r"(dst_smem), "l"(src));
}
__device__ __forceinline__ void cp_commit() {
    asm volatile("cp.async.commit_group;");
}
template<int N> __device__ __forceinline__ void cp_wait() {
    asm volatile("cp.async.wait_group %0;" :: "n"(N));
}
// vector fp32 reduction (sm_90+): one 8B atomic add, no return
__device__ __forceinline__ void red2(float* addr, float x, float y) {
    asm volatile("red.global.add.v2.f32 [%0], {%1, %2};"
                 :: "l"(addr), "f"(x), "f"(y) : "memory");
}

// ---------------- mask dtype detection + counter reset ----------------
__global__ void detect_mask_kernel(const unsigned int* __restrict__ m) {
    if (threadIdx.x < 2) { g_ne_c[threadIdx.x] = 0; g_nn_c[threadIdx.x] = 0; }
    int bad = 0;
    for (int i = threadIdx.x; i < N_NODES / 4; i += blockDim.x)
        if (m[i] > 1u) bad = 1;
    bad = __syncthreads_or(bad);
    if (threadIdx.x == 0) g_mask_u8 = bad;
}

// ---------------- edge compaction (warp-atomic, order-free) ----------------
__global__ void __launch_bounds__(256)
compact_kernel(const int* __restrict__ edges, const void* __restrict__ mask, int li) {
    const int* rows = edges;
    const int* cols = edges + N_EDGES;
    int e = blockIdx.x * 256 + threadIdx.x;
    int lane = threadIdx.x & 31;
    int mu8 = g_mask_u8;

    bool valid = false; int rv = 0, cv = 0;
    if (e < N_EDGES) {
        rv = rows[e]; cv = cols[e];
        valid = mu8 ? (((const unsigned char*)mask)[rv] != 0)
                    : (((const int*)mask)[rv] != 0);
    }
    unsigned bal = __ballot_sync(0xffffffffu, valid);
    int base = 0;
    if (lane == 0 && bal) base = atomicAdd(&g_ne_c[li], __popc(bal));
    base = __shfl_sync(0xffffffffu, base, 0);
    if (valid) {
        int p = base + __popc(bal & ((1u << lane) - 1u));
        g_rows_c[li][p] = rv;
        g_cols_c[li][p] = cv;
    }
}

// ---------------- node compaction (warp-atomic) ----------------
__global__ void __launch_bounds__(256)
compact_nodes_kernel(const void* __restrict__ mask, int li) {
    int n = blockIdx.x * 256 + threadIdx.x;
    int lane = threadIdx.x & 31;
    int mu8 = g_mask_u8;

    bool valid = false;
    if (n < N_NODES)
        valid = mu8 ? (((const unsigned char*)mask)[n] != 0)
                    : (((const int*)mask)[n] != 0);
    unsigned bal = __ballot_sync(0xffffffffu, valid);
    int base = 0;
    if (lane == 0 && bal) base = atomicAdd(&g_nn_c[li], __popc(bal));
    base = __shfl_sync(0xffffffffu, base, 0);
    if (valid)
        g_nodes_c[li][base + __popc(bal & ((1u << lane) - 1u))] = n;
}

// ---------------- input embedding (FFMA2, 4 rows/warp) + agg zero-init ----------------
// g_h[r] = h_in[r] @ Wi + bi ; also zeroes g_agg rows (replaces zero_agg kernel)
__global__ void __launch_bounds__(512, 1)
embed_in_kernel(const float* __restrict__ h_in,
                const float* __restrict__ W,
                const float* __restrict__ b) {
    extern __shared__ char smraw[];
    u64* Wp = (u64*)smraw;              // 32 kk * 128 cols
    float* bs = (float*)(Wp + 4096);    // 128
    float* xAll = bs + 128;             // 16 warps * 4 rows * 72

    int tid = threadIdx.x;
    for (int i = tid; i < 4096; i += 512) {
        int kk = i >> 7, c = i & 127;
        Wp[i] = packf2(W[(2 * kk) * 128 + c], W[(2 * kk + 1) * 128 + c]);
    }
    if (tid < 128) bs[tid] = b[tid];
    __syncthreads();

    int wid = tid >> 5, lane = tid & 31;
    float* xS = xAll + wid * 288;
    int c0 = 2 * lane, c1 = 64 + 2 * lane;
    float bb[4] = {bs[c0], bs[c0 + 1], bs[c1], bs[c1 + 1]};

    for (int t = blockIdx.x * 16 + wid; t < N_NODES / 4; t += gridDim.x * 16) {
        int r0 = 4 * t;
        for (int i = lane; i < 64; i += 32) {         // 4 rows x 16 float4
            int rr = i >> 4, v = i & 15;
            *(float4*)(xS + rr * 72 + 4 * v) =
                *(const float4*)(h_in + (r0 + rr) * 64 + 4 * v);
        }
        // zero the agg rows of this tile (4 rows x 64 floats = 64 float4)
        for (int i = lane; i < 64; i += 32)
            *(float4*)(g_agg + (size_t)r0 * 64 + 4 * i) =
                make_float4(0.f, 0.f, 0.f, 0.f);
        __syncwarp();
        u64 acc[16];
#pragma unroll
        for (int j = 0; j < 16; j++) acc[j] = 0ull;
#pragma unroll 4
        for (int kk = 0; kk < 32; kk++) {
            const u64* wr = Wp + kk * 128;
            ulonglong2 wA = *(const ulonglong2*)(wr + c0);
            ulonglong2 wB = *(const ulonglong2*)(wr + c1);
#pragma unroll
            for (int j = 0; j < 4; j++) {
                u64 f = *(const u64*)(xS + j * 72 + 2 * kk);
                acc[4 * j]     = ffma2(f, wA.x, acc[4 * j]);
                acc[4 * j + 1] = ffma2(f, wA.y, acc[4 * j + 1]);
                acc[4 * j + 2] = ffma2(f, wB.x, acc[4 * j + 2]);
                acc[4 * j + 3] = ffma2(f, wB.y, acc[4 * j + 3]);
            }
        }
#pragma unroll
        for (int j = 0; j < 4; j++) {
            float2 oA, oB;
            oA.x = lo32(acc[4 * j])     + hi32(acc[4 * j])     + bb[0];
            oA.y = lo32(acc[4 * j + 1]) + hi32(acc[4 * j + 1]) + bb[1];
            oB.x = lo32(acc[4 * j + 2]) + hi32(acc[4 * j + 2]) + bb[2];
            oB.y = lo32(acc[4 * j + 3]) + hi32(acc[4 * j + 3]) + bb[3];
            *(float2*)(g_h + (r0 + j) * 128 + c0) = oA;
            *(float2*)(g_h + (r0 + j) * 128 + c1) = oB;
        }
        __syncwarp();
    }
}
#define EMBI_SMEM (4096 * 8 + 128 * 4 + 16 * 288 * 4)

// ---------------- output embedding (FFMA2, 8 rows/warp) ----------------
__global__ void __launch_bounds__(512, 1)
embed_out_kernel(const float* __restrict__ W,
                 const float* __restrict__ b,
                 float* __restrict__ out) {
    extern __shared__ char smraw[];
    u64* Wp = (u64*)smraw;              // 64 kk * 64 cols
    float* bs = (float*)(Wp + 4096);    // 64
    float* xAll = bs + 64;              // 16 warps * 8 rows * 136

    int tid = threadIdx.x;
    for (int i = tid; i < 4096; i += 512) {
        int kk = i >> 6, c = i & 63;
        Wp[i] = packf2(W[(2 * kk) * 64 + c], W[(2 * kk + 1) * 64 + c]);
    }
    if (tid < 64) bs[tid] = b[tid];
    __syncthreads();

    int wid = tid >> 5, lane = tid & 31;
    float* xS = xAll + wid * 1088;
    int c0 = 2 * lane;
    float bb0 = bs[c0], bb1 = bs[c0 + 1];

    for (int t = blockIdx.x * 16 + wid; t < N_NODES / 8; t += gridDim.x * 16) {
        int r0 = 8 * t;
        for (int i = lane; i < 256; i += 32) {        // 8 rows x 32 float4
            int rr = i >> 5, v = i & 31;
            *(float4*)(xS + rr * 136 + 4 * v) =
                *(const float4*)(g_h + (r0 + rr) * 128 + 4 * v);
        }
        __syncwarp();
        u64 acc[16];
#pragma unroll
        for (int j = 0; j < 16; j++) acc[j] = 0ull;
#pragma unroll 4
        for (int kk = 0; kk < 64; kk++) {
            ulonglong2 w = *(const ulonglong2*)(Wp + kk * 64 + c0);
#pragma unroll
            for (int j = 0; j < 8; j++) {
                u64 f = *(const u64*)(xS + j * 136 + 2 * kk);
                acc[2 * j]     = ffma2(f, w.x, acc[2 * j]);
                acc[2 * j + 1] = ffma2(f, w.y, acc[2 * j + 1]);
            }
        }
#pragma unroll
        for (int j = 0; j < 8; j++) {
            float2 o;
            o.x = lo32(acc[2 * j])     + hi32(acc[2 * j])     + bb0;
            o.y = lo32(acc[2 * j + 1]) + hi32(acc[2 * j + 1]) + bb1;
            *(float2*)(out + (r0 + j) * 64 + c0) = o;
        }
        __syncwarp();
    }
}
#define EMBO_SMEM (4096 * 8 + 64 * 4 + 16 * 1088 * 4)

// ---------------- edge MLP inner block (FFMA2) ----------------
template<int NKK>
__device__ __forceinline__ void mlp64(const float* f0p, const float* f1p,
                                      const u64* Wp, int cg, u64* acc) {
#pragma unroll 4
    for (int kk = 0; kk < NKK; kk++) {
        u64 f0 = *(const u64*)(f0p + 2 * kk);
        u64 f1 = *(const u64*)(f1p + 2 * kk);
        const u64* wr = Wp + kk * 64;
        ulonglong2 w0 = *(const ulonglong2*)(wr + 2 * cg);
        ulonglong2 w1 = *(const ulonglong2*)(wr + 16 + 2 * cg);
        ulonglong2 w2 = *(const ulonglong2*)(wr + 32 + 2 * cg);
        ulonglong2 w3 = *(const ulonglong2*)(wr + 48 + 2 * cg);
        acc[0] = ffma2(f0, w0.x, acc[0]);   acc[1] = ffma2(f0, w0.y, acc[1]);
        acc[2] = ffma2(f0, w1.x, acc[2]);   acc[3] = ffma2(f0, w1.y, acc[3]);
        acc[4] = ffma2(f0, w2.x, acc[4]);   acc[5] = ffma2(f0, w2.y, acc[5]);
        acc[6] = ffma2(f0, w3.x, acc[6]);   acc[7] = ffma2(f0, w3.y, acc[7]);
        acc[8] = ffma2(f1, w0.x, acc[8]);   acc[9] = ffma2(f1, w0.y, acc[9]);
        acc[10] = ffma2(f1, w1.x, acc[10]); acc[11] = ffma2(f1, w1.y, acc[11]);
        acc[12] = ffma2(f1, w2.x, acc[12]); acc[13] = ffma2(f1, w2.y, acc[13]);
        acc[14] = ffma2(f1, w3.x, acc[14]); acc[15] = ffma2(f1, w3.y, acc[15]);
    }
}

// ---------------- edge kernel (FFMA2 + cp.async double-buffered gather) ----------------
__global__ void __launch_bounds__(512, 1)
edge_kernel(int li,
            const float* __restrict__ W1, const float* __restrict__ b1,
            const float* __restrict__ W2, const float* __restrict__ b2,
            float C) {
    extern __shared__ char smraw[];
    u64* Wp1 = (u64*)smraw;                 // 8192 u64
    u64* Wp2 = Wp1 + 8192;                  // 2048 u64
    float* b1s = (float*)(Wp2 + 2048);      // 64
    float* b2s = b1s + 64;                  // 64
    float* bufA_all = b2s + 64;             // 16 * 8 * FSTR
    float* bufB_all = bufA_all + EK_WARPS * 8 * FSTR;
    __shared__ int idxS[EK_WARPS][2][16];

    int tid = threadIdx.x;
    for (int i = tid; i < 8192; i += 512) {
        int kk = i >> 6, c = i & 63;
        Wp1[i] = packf2(W1[(2 * kk) * 64 + c], W1[(2 * kk + 1) * 64 + c]);
    }
    for (int i = tid; i < 2048; i += 512) {
        int kk = i >> 6, c = i & 63;
        Wp2[i] = packf2(W2[(2 * kk) * 64 + c], W2[(2 * kk + 1) * 64 + c]);
    }
    if (tid < 64) { b1s[tid] = b1[tid]; b2s[tid] = b2[tid]; }
    __syncthreads();

    int wid = tid >> 5, lane = tid & 31;
    int er = lane >> 3, cg = lane & 7;
    float* bufA = bufA_all + wid * (8 * FSTR);
    float* bufB = bufB_all + wid * (8 * FSTR);
    unsigned bufA_s = (unsigned)__cvta_generic_to_shared(bufA);
    unsigned bufB_s = (unsigned)__cvta_generic_to_shared(bufB);

    int colb[4] = {2 * cg, 16 + 2 * cg, 32 + 2 * cg, 48 + 2 * cg};
    float bb1[8], bb2[8];
#pragma unroll
    for (int q = 0; q < 4; q++) {
        bb1[2 * q] = b1s[colb[q]]; bb1[2 * q + 1] = b1s[colb[q] + 1];
        bb2[2 * q] = b2s[colb[q]]; bb2[2 * q + 1] = b2s[colb[q] + 1];
    }

    int nE = g_ne_c[li];
    const int* rows = g_rows_c[li];
    const int* cols = g_cols_c[li];
    int ngroups = (nE + 7) >> 3;
    int nw = gridDim.x * EK_WARPS;
    int g = blockIdx.x * EK_WARPS + wid;
    int cur = 0;

    const float* fA0 = bufA + er * FSTR;
    const float* fA1 = bufA + (er + 4) * FSTR;
    const float* fB0 = bufB + er * FSTR;
    const float* fB1 = bufB + (er + 4) * FSTR;

    if (g < ngroups) {
        if (lane < 16) {
            int e = g * 8 + (lane & 7);
            if (e >= nE) e = nE - 1;
            idxS[wid][0][lane] = (lane < 8) ? rows[e] : cols[e];
        }
        __syncwarp();
#pragma unroll
        for (int e = 0; e < 8; e++)
            cp16(bufA_s + (e * FSTR + 4 * lane) * 4,
                 g_h + (size_t)idxS[wid][0][e] * 128 + 4 * lane);
    }
    cp_commit();

    for (; g < ngroups; g += nw) {
        int* idx = idxS[wid][cur];
        // prefetch cols(current) -> bufB
#pragma unroll
        for (int e = 0; e < 8; e++)
            cp16(bufB_s + (e * FSTR + 4 * lane) * 4,
                 g_h + (size_t)idx[8 + e] * 128 + 4 * lane);
        cp_commit();
        cp_wait<1>(); __syncwarp();          // bufA (rows) ready

        u64 acc[16];
#pragma unroll
        for (int j = 0; j < 16; j++) acc[j] = 0ull;
        mlp64<64>(fA0, fA1, Wp1, cg, acc);   // layer1 pass1 (k 0..127)
        __syncwarp();                        // all lanes done reading bufA

        int gn = g + nw;
        int* idxn = idxS[wid][cur ^ 1];
        if (gn < ngroups) {
            if (lane < 16) {
                int e = gn * 8 + (lane & 7);
                if (e >= nE) e = nE - 1;
                idxn[lane] = (lane < 8) ? rows[e] : cols[e];
            }
            __syncwarp();
#pragma unroll
            for (int e = 0; e < 8; e++)
                cp16(bufA_s + (e * FSTR + 4 * lane) * 4,
                     g_h + (size_t)idxn[e] * 128 + 4 * lane);
        }
        cp_commit();
        cp_wait<1>(); __syncwarp();          // bufB (cols) ready

        mlp64<64>(fB0, fB1, Wp1 + 4096, cg, acc);  // layer1 pass2 (k 128..255)
        __syncwarp();

        // finalize layer1: m = silu(lo+hi+b1), stored into bufB
#pragma unroll
        for (int q = 0; q < 4; q++) {
            float2 m0, m1;
            m0.x = silu(lo32(acc[2*q])     + hi32(acc[2*q])     + bb1[2*q]);
            m0.y = silu(lo32(acc[2*q+1])   + hi32(acc[2*q+1])   + bb1[2*q+1]);
            m1.x = silu(lo32(acc[8+2*q])   + hi32(acc[8+2*q])   + bb1[2*q]);
            m1.y = silu(lo32(acc[8+2*q+1]) + hi32(acc[8+2*q+1]) + bb1[2*q+1]);
            *(float2*)(bufB + er * FSTR + colb[q]) = m0;
            *(float2*)(bufB + (er + 4) * FSTR + colb[q]) = m1;
        }
        __syncwarp();

        // layer2 (64 -> 64)
        u64 acc2[16];
#pragma unroll
        for (int j = 0; j < 16; j++) acc2[j] = 0ull;
        mlp64<32>(fB0, fB1, Wp2, cg, acc2);

        // scatter: agg[row] += silu(out) * C  (vector red, 8B per op)
        int e0g = g * 8;
        bool vA = (e0g + er) < nE;
        bool vB = (e0g + er + 4) < nE;
        int rA = idx[er], rB = idx[er + 4];
#pragma unroll
        for (int q = 0; q < 4; q++) {
            if (vA) {
                float* a = g_agg + rA * 64 + colb[q];
                red2(a, silu(lo32(acc2[2*q])   + hi32(acc2[2*q])   + bb2[2*q])   * C,
                        silu(lo32(acc2[2*q+1]) + hi32(acc2[2*q+1]) + bb2[2*q+1]) * C);
            }
            if (vB) {
                float* a = g_agg + rB * 64 + colb[q];
                red2(a, silu(lo32(acc2[8+2*q])   + hi32(acc2[8+2*q])   + bb2[2*q])   * C,
                        silu(lo32(acc2[8+2*q+1]) + hi32(acc2[8+2*q+1]) + bb2[2*q+1]) * C);
            }
        }
        __syncwarp();   // bufB reads done before next iteration's cols prefetch
        cur ^= 1;
    }
}
#define EDGE_SMEM_BYTES (8192*8 + 2048*8 + 128*4 + 2*EK_WARPS*8*FSTR*4)

// ---------------- node kernel (FFMA2, 4 compacted rows/warp; re-zeroes agg) ----------------
__global__ void __launch_bounds__(512, 1)
node_kernel(int li,
            const float* __restrict__ W1, const float* __restrict__ b1,
            const float* __restrict__ W2, const float* __restrict__ b2) {
    extern __shared__ char smraw[];
    u64* Wp1 = (u64*)smraw;                 // 96 kk * 128 cols
    u64* Wp2 = Wp1 + 12288;                 // 64 kk * 128 cols
    float* b1s = (float*)(Wp2 + 8192);      // 128
    float* b2s = b1s + 128;                 // 128
    float* xAll = b2s + 128;                // 16 warps * 4 rows * 200

    int tid = threadIdx.x;
    for (int i = tid; i < 12288; i += 512) {
        int kk = i >> 7, c = i & 127;
        Wp1[i] = packf2(W1[(2 * kk) * 128 + c], W1[(2 * kk + 1) * 128 + c]);
    }
    for (int i = tid; i < 8192; i += 512) {
        int kk = i >> 7, c = i & 127;
        Wp2[i] = packf2(W2[(2 * kk) * 128 + c], W2[(2 * kk + 1) * 128 + c]);
    }
    if (tid < 128) { b1s[tid] = b1[tid]; b2s[tid] = b2[tid]; }
    __syncthreads();

    int wid = tid >> 5, lane = tid & 31;
    float* xS = xAll + wid * 800;
    int c0 = 2 * lane, c1 = 64 + 2 * lane;
    float bb1[4] = {b1s[c0], b1s[c0 + 1], b1s[c1], b1s[c1 + 1]};
    float bb2[4] = {b2s[c0], b2s[c0 + 1], b2s[c1], b2s[c1 + 1]};

    int nn = g_nn_c[li];
    const int* list = g_nodes_c[li];
    int ntiles = (nn + 3) >> 2;
    for (int t = blockIdx.x * 16 + wid; t < ntiles; t += gridDim.x * 16) {
        int rid[4]; bool rv[4];
#pragma unroll
        for (int j = 0; j < 4; j++) {
            int p = 4 * t + j;
            rv[j] = p < nn;
            rid[j] = list[rv[j] ? p : (nn - 1)];
        }
        // gather x = [h || agg]
#pragma unroll
        for (int j = 0; j < 4; j++) {
            for (int v = lane; v < 48; v += 32) {
                float4 val = (v < 32) ? *(const float4*)(g_h + (size_t)rid[j] * 128 + 4 * v)
                                      : *(const float4*)(g_agg + (size_t)rid[j] * 64 + 4 * (v - 32));
                *(float4*)(xS + j * 200 + 4 * v) = val;
            }
        }
        __syncwarp();

        u64 acc[16];
#pragma unroll
        for (int j = 0; j < 16; j++) acc[j] = 0ull;
#pragma unroll 2
        for (int kk = 0; kk < 96; kk++) {
            const u64* wr = Wp1 + kk * 128;
            ulonglong2 wA = *(const ulonglong2*)(wr + c0);
            ulonglong2 wB = *(const ulonglong2*)(wr + c1);
#pragma unroll
            for (int j = 0; j < 4; j++) {
                u64 f = *(const u64*)(xS + j * 200 + 2 * kk);
                acc[4 * j]     = ffma2(f, wA.x, acc[4 * j]);
                acc[4 * j + 1] = ffma2(f, wA.y, acc[4 * j + 1]);
                acc[4 * j + 2] = ffma2(f, wB.x, acc[4 * j + 2]);
                acc[4 * j + 3] = ffma2(f, wB.y, acc[4 * j + 3]);
            }
        }
        __syncwarp();   // all lanes done reading x before m overwrites

        float res[16];
#pragma unroll
        for (int j = 0; j < 4; j++) {
            res[4 * j]     = xS[j * 200 + c0];
            res[4 * j + 1] = xS[j * 200 + c0 + 1];
            res[4 * j + 2] = xS[j * 200 + c1];
            res[4 * j + 3] = xS[j * 200 + c1 + 1];
        }
#pragma unroll
        for (int j = 0; j < 4; j++) {
            float2 mA, mB;
            mA.x = silu(lo32(acc[4*j])     + hi32(acc[4*j])     + bb1[0]);
            mA.y = silu(lo32(acc[4*j+1])   + hi32(acc[4*j+1])   + bb1[1]);
            mB.x = silu(lo32(acc[4*j+2])   + hi32(acc[4*j+2])   + bb1[2]);
            mB.y = silu(lo32(acc[4*j+3])   + hi32(acc[4*j+3])   + bb1[3]);
            *(float2*)(xS + j * 200 + c0) = mA;
            *(float2*)(xS + j * 200 + c1) = mB;
        }
        __syncwarp();

#pragma unroll
        for (int j = 0; j < 16; j++) acc[j] = 0ull;
#pragma unroll 2
        for (int kk = 0; kk < 64; kk++) {
            const u64* wr = Wp2 + kk * 128;
            ulonglong2 wA = *(const ulonglong2*)(wr + c0);
            ulonglong2 wB = *(const ulonglong2*)(wr + c1);
#pragma unroll
            for (int j = 0; j < 4; j++) {
                u64 f = *(const u64*)(xS + j * 200 + 2 * kk);
                acc[4 * j]     = ffma2(f, wA.x, acc[4 * j]);
                acc[4 * j + 1] = ffma2(f, wA.y, acc[4 * j + 1]);
                acc[4 * j + 2] = ffma2(f, wB.x, acc[4 * j + 2]);
                acc[4 * j + 3] = ffma2(f, wB.y, acc[4 * j + 3]);
            }
        }
#pragma unroll
        for (int j = 0; j < 4; j++) {
            if (!rv[j]) continue;
            float2 oA, oB;
            oA.x = res[4*j]     + lo32(acc[4*j])     + hi32(acc[4*j])     + bb2[0];
            oA.y = res[4*j+1]   + lo32(acc[4*j+1])   + hi32(acc[4*j+1])   + bb2[1];
            oB.x = res[4*j+2]   + lo32(acc[4*j+2])   + hi32(acc[4*j+2])   + bb2[2];
            oB.y = res[4*j+3]   + lo32(acc[4*j+3])   + hi32(acc[4*j+3])   + bb2[3];
            *(float2*)(g_h + (size_t)rid[j] * 128 + c0) = oA;
            *(float2*)(g_h + (size_t)rid[j] * 128 + c1) = oB;
        }
        // consume-and-zero: restore agg rows of this tile to 0 for the next layer
#pragma unroll
        for (int j = 0; j < 4; j++) {
            if (rv[j] && lane < 16)
                *(float4*)(g_agg + (size_t)rid[j] * 64 + 4 * lane) =
                    make_float4(0.f, 0.f, 0.f, 0.f);
        }
        __syncwarp();
    }
}
#define NODE_SMEM_BYTES (12288*8 + 8192*8 + 256*4 + 16*800*4)

// ---------------- launch ----------------
// Order chosen so the FIRST edge_kernel is launch index 3 (ncu capture slot).
extern "C" void kernel_launch(void* const* d_in, const int* in_sizes, int n_in,
                              void* d_out, int out_size) {
    const float* h_in = (const float*)d_in[0];
    const int*   eA   = (const int*)d_in[1];
    const int*   eB   = (const int*)d_in[2];
    const void*  mA   = d_in[3];
    const void*  mB   = d_in[4];
    const float* Wi   = (const float*)d_in[5];
    const float* bi   = (const float*)d_in[6];
    const float* Wo   = (const float*)d_in[7];
    const float* bo   = (const float*)d_in[8];
    const float* ew1  = (const float*)d_in[9];
    const float* eb1  = (const float*)d_in[10];
    const float* ew2  = (const float*)d_in[11];
    const float* eb2  = (const float*)d_in[12];
    const float* nw1  = (const float*)d_in[13];
    const float* nb1  = (const float*)d_in[14];
    const float* nw2  = (const float*)d_in[15];
    const float* nb2  = (const float*)d_in[16];
    float* out = (float*)d_out;

    cudaFuncSetAttribute(edge_kernel, cudaFuncAttributeMaxDynamicSharedMemorySize,
                         EDGE_SMEM_BYTES);
    cudaFuncSetAttribute(node_kernel, cudaFuncAttributeMaxDynamicSharedMemorySize,
                         NODE_SMEM_BYTES);
    cudaFuncSetAttribute(embed_in_kernel, cudaFuncAttributeMaxDynamicSharedMemorySize,
                         EMBI_SMEM);
    cudaFuncSetAttribute(embed_out_kernel, cudaFuncAttributeMaxDynamicSharedMemorySize,
                         EMBO_SMEM);

    // 0: mask detect + counter reset
    detect_mask_kernel<<<1, 256>>>((const unsigned int*)mA);
    // 1: compact edges for even layers
    compact_kernel<<<3125, 256>>>(eA, mA, 0);
    // 2: input embedding (also zeroes g_agg)
    embed_in_kernel<<<148, 512, EMBI_SMEM>>>(h_in, Wi, bi);
    // 3: layer 0 edge kernel  <-- ncu capture slot
    edge_kernel<<<148, 512, EDGE_SMEM_BYTES>>>(
        0, ew1, eb1, ew2, eb2, 1.0f);
    // remaining compactions (needed from node0 / edge1 onward)
    compact_nodes_kernel<<<196, 256>>>(mA, 0);
    node_kernel<<<148, 512, NODE_SMEM_BYTES>>>(0, nw1, nb1, nw2, nb2);
    compact_kernel<<<3125, 256>>>(eB, mB, 1);
    compact_nodes_kernel<<<196, 256>>>(mB, 1);

    for (int i = 1; i < 4; i++) {
        int li = i % 2;
        float C = (li == 0) ? 1.0f : (2.0f / 64.0f);
        edge_kernel<<<148, 512, EDGE_SMEM_BYTES>>>(
            li, ew1 + i * 256 * 64, eb1 + i * 64,
            ew2 + i * 64 * 64, eb2 + i * 64, C);
        node_kernel<<<148, 512, NODE_SMEM_BYTES>>>(
            li, nw1 + i * 192 * 128, nb1 + i * 128,
            nw2 + i * 128 * 128, nb2 + i * 128);
    }

    embed_out_kernel<<<148, 512, EMBO_SMEM>>>(Wo, bo, out);
}

// round 11
// speedup vs baseline: 1.0678x; 1.0099x over previous
#include <cuda_runtime.h>
#include <cuda_bf16.h>

typedef unsigned long long u64;

#define N_NODES 50000
#define N_EDGES 800000
#define HID 128
#define EH 64
#define FSTR 132            // floats per edge row in feat buffer (bank-spread)
#define EK_WARPS 16

// ---------------- scratch (no allocs allowed) ----------------
__device__ float g_h[N_NODES * HID];
__device__ float g_agg[N_NODES * EH];
__device__ int   g_mask_u8;
__device__ int   g_ne_c[2];                 // compacted edge counts
__device__ int   g_rows_c[2][N_EDGES];
__device__ int   g_cols_c[2][N_EDGES];
__device__ int   g_nn_c[2];                 // compacted node counts
__device__ int   g_nodes_c[2][N_NODES];

__device__ __forceinline__ float silu(float x) {
    return x / (1.0f + __expf(-x));
}
__device__ __forceinline__ u64 ffma2(u64 a, u64 b, u64 c) {
    u64 d;
    asm("fma.rn.f32x2 %0, %1, %2, %3;" : "=l"(d) : "l"(a), "l"(b), "l"(c));
    return d;
}
__device__ __forceinline__ float lo32(u64 a) { return __uint_as_float((unsigned)a); }
__device__ __forceinline__ float hi32(u64 a) { return __uint_as_float((unsigned)(a >> 32)); }
__device__ __forceinline__ u64 packf2(float lo, float hi) {
    return (u64)__float_as_uint(lo) | ((u64)__float_as_uint(hi) << 32);
}
__device__ __forceinline__ void cp16(unsigned dst_smem, const void* src) {
    asm volatile("cp.async.cg.shared.global [%0], [%1], 16;"
                 :: "r"(dst_smem), "l"(src));
}
__device__ __forceinline__ void cp_commit() {
    asm volatile("cp.async.commit_group;");
}
template<int N> __device__ __forceinline__ void cp_wait() {
    asm volatile("cp.async.wait_group %0;" :: "n"(N));
}
// vector fp32 reduction (sm_90+): one 8B atomic add, no return
__device__ __forceinline__ void red2(float* addr, float x, float y) {
    asm volatile("red.global.add.v2.f32 [%0], {%1, %2};"
                 :: "l"(addr), "f"(x), "f"(y) : "memory");
}

// ---------------- mask dtype detection + counter reset ----------------
__global__ void detect_mask_kernel(const unsigned int* __restrict__ m) {
    if (threadIdx.x < 2) { g_ne_c[threadIdx.x] = 0; g_nn_c[threadIdx.x] = 0; }
    int bad = 0;
    for (int i = threadIdx.x; i < N_NODES / 4; i += blockDim.x)
        if (m[i] > 1u) bad = 1;
    bad = __syncthreads_or(bad);
    if (threadIdx.x == 0) g_mask_u8 = bad;
}

// ---------------- edge compaction (warp-atomic, order-free) ----------------
__global__ void __launch_bounds__(256)
compact_kernel(const int* __restrict__ edges, const void* __restrict__ mask, int li) {
    const int* rows = edges;
    const int* cols = edges + N_EDGES;
    int e = blockIdx.x * 256 + threadIdx.x;
    int lane = threadIdx.x & 31;
    int mu8 = g_mask_u8;

    bool valid = false; int rv = 0, cv = 0;
    if (e < N_EDGES) {
        rv = rows[e]; cv = cols[e];
        valid = mu8 ? (((const unsigned char*)mask)[rv] != 0)
                    : (((const int*)mask)[rv] != 0);
    }
    unsigned bal = __ballot_sync(0xffffffffu, valid);
    int base = 0;
    if (lane == 0 && bal) base = atomicAdd(&g_ne_c[li], __popc(bal));
    base = __shfl_sync(0xffffffffu, base, 0);
    if (valid) {
        int p = base + __popc(bal & ((1u << lane) - 1u));
        g_rows_c[li][p] = rv;
        g_cols_c[li][p] = cv;
    }
}

// ---------------- node compaction (warp-atomic) ----------------
__global__ void __launch_bounds__(256)
compact_nodes_kernel(const void* __restrict__ mask, int li) {
    int n = blockIdx.x * 256 + threadIdx.x;
    int lane = threadIdx.x & 31;
    int mu8 = g_mask_u8;

    bool valid = false;
    if (n < N_NODES)
        valid = mu8 ? (((const unsigned char*)mask)[n] != 0)
                    : (((const int*)mask)[n] != 0);
    unsigned bal = __ballot_sync(0xffffffffu, valid);
    int base = 0;
    if (lane == 0 && bal) base = atomicAdd(&g_nn_c[li], __popc(bal));
    base = __shfl_sync(0xffffffffu, base, 0);
    if (valid)
        g_nodes_c[li][base + __popc(bal & ((1u << lane) - 1u))] = n;
}

// ---------------- input embedding (FFMA2, 4 rows/warp) + agg zero-init ----------------
// g_h[r] = h_in[r] @ Wi + bi ; also zeroes g_agg rows (replaces zero_agg kernel)
__global__ void __launch_bounds__(512, 1)
embed_in_kernel(const float* __restrict__ h_in,
                const float* __restrict__ W,
                const float* __restrict__ b) {
    extern __shared__ char smraw[];
    u64* Wp = (u64*)smraw;              // 32 kk * 128 cols
    float* bs = (float*)(Wp + 4096);    // 128
    float* xAll = bs + 128;             // 16 warps * 4 rows * 72

    int tid = threadIdx.x;
    for (int i = tid; i < 4096; i += 512) {
        int kk = i >> 7, c = i & 127;
        Wp[i] = packf2(W[(2 * kk) * 128 + c], W[(2 * kk + 1) * 128 + c]);
    }
    if (tid < 128) bs[tid] = b[tid];
    __syncthreads();

    int wid = tid >> 5, lane = tid & 31;
    float* xS = xAll + wid * 288;
    int c0 = 2 * lane, c1 = 64 + 2 * lane;
    float bb[4] = {bs[c0], bs[c0 + 1], bs[c1], bs[c1 + 1]};

    for (int t = blockIdx.x * 16 + wid; t < N_NODES / 4; t += gridDim.x * 16) {
        int r0 = 4 * t;
        for (int i = lane; i < 64; i += 32) {         // 4 rows x 16 float4
            int rr = i >> 4, v = i & 15;
            *(float4*)(xS + rr * 72 + 4 * v) =
                *(const float4*)(h_in + (r0 + rr) * 64 + 4 * v);
        }
        // zero the agg rows of this tile (4 rows x 64 floats = 64 float4)
        for (int i = lane; i < 64; i += 32)
            *(float4*)(g_agg + (size_t)r0 * 64 + 4 * i) =
                make_float4(0.f, 0.f, 0.f, 0.f);
        __syncwarp();
        u64 acc[16];
#pragma unroll
        for (int j = 0; j < 16; j++) acc[j] = 0ull;
#pragma unroll 4
        for (int kk = 0; kk < 32; kk++) {
            const u64* wr = Wp + kk * 128;
            ulonglong2 wA = *(const ulonglong2*)(wr + c0);
            ulonglong2 wB = *(const ulonglong2*)(wr + c1);
#pragma unroll
            for (int j = 0; j < 4; j++) {
                u64 f = *(const u64*)(xS + j * 72 + 2 * kk);
                acc[4 * j]     = ffma2(f, wA.x, acc[4 * j]);
                acc[4 * j + 1] = ffma2(f, wA.y, acc[4 * j + 1]);
                acc[4 * j + 2] = ffma2(f, wB.x, acc[4 * j + 2]);
                acc[4 * j + 3] = ffma2(f, wB.y, acc[4 * j + 3]);
            }
        }
#pragma unroll
        for (int j = 0; j < 4; j++) {
            float2 oA, oB;
            oA.x = lo32(acc[4 * j])     + hi32(acc[4 * j])     + bb[0];
            oA.y = lo32(acc[4 * j + 1]) + hi32(acc[4 * j + 1]) + bb[1];
            oB.x = lo32(acc[4 * j + 2]) + hi32(acc[4 * j + 2]) + bb[2];
            oB.y = lo32(acc[4 * j + 3]) + hi32(acc[4 * j + 3]) + bb[3];
            *(float2*)(g_h + (r0 + j) * 128 + c0) = oA;
            *(float2*)(g_h + (r0 + j) * 128 + c1) = oB;
        }
        __syncwarp();
    }
}
#define EMBI_SMEM (4096 * 8 + 128 * 4 + 16 * 288 * 4)

// ---------------- output embedding (FFMA2, 8 rows/warp) ----------------
__global__ void __launch_bounds__(512, 1)
embed_out_kernel(const float* __restrict__ W,
                 const float* __restrict__ b,
                 float* __restrict__ out) {
    extern __shared__ char smraw[];
    u64* Wp = (u64*)smraw;              // 64 kk * 64 cols
    float* bs = (float*)(Wp + 4096);    // 64
    float* xAll = bs + 64;              // 16 warps * 8 rows * 136

    int tid = threadIdx.x;
    for (int i = tid; i < 4096; i += 512) {
        int kk = i >> 6, c = i & 63;
        Wp[i] = packf2(W[(2 * kk) * 64 + c], W[(2 * kk + 1) * 64 + c]);
    }
    if (tid < 64) bs[tid] = b[tid];
    __syncthreads();

    int wid = tid >> 5, lane = tid & 31;
    float* xS = xAll + wid * 1088;
    int c0 = 2 * lane;
    float bb0 = bs[c0], bb1 = bs[c0 + 1];

    for (int t = blockIdx.x * 16 + wid; t < N_NODES / 8; t += gridDim.x * 16) {
        int r0 = 8 * t;
        for (int i = lane; i < 256; i += 32) {        // 8 rows x 32 float4
            int rr = i >> 5, v = i & 31;
            *(float4*)(xS + rr * 136 + 4 * v) =
                *(const float4*)(g_h + (r0 + rr) * 128 + 4 * v);
        }
        __syncwarp();
        u64 acc[16];
#pragma unroll
        for (int j = 0; j < 16; j++) acc[j] = 0ull;
#pragma unroll 4
        for (int kk = 0; kk < 64; kk++) {
            ulonglong2 w = *(const ulonglong2*)(Wp + kk * 64 + c0);
#pragma unroll
            for (int j = 0; j < 8; j++) {
                u64 f = *(const u64*)(xS + j * 136 + 2 * kk);
                acc[2 * j]     = ffma2(f, w.x, acc[2 * j]);
                acc[2 * j + 1] = ffma2(f, w.y, acc[2 * j + 1]);
            }
        }
#pragma unroll
        for (int j = 0; j < 8; j++) {
            float2 o;
            o.x = lo32(acc[2 * j])     + hi32(acc[2 * j])     + bb0;
            o.y = lo32(acc[2 * j + 1]) + hi32(acc[2 * j + 1]) + bb1;
            *(float2*)(out + (r0 + j) * 64 + c0) = o;
        }
        __syncwarp();
    }
}
#define EMBO_SMEM (4096 * 8 + 64 * 4 + 16 * 1088 * 4)

// ---------------- edge MLP inner block (FFMA2) ----------------
template<int NKK>
__device__ __forceinline__ void mlp64(const float* f0p, const float* f1p,
                                      const u64* Wp, int cg, u64* acc) {
#pragma unroll 4
    for (int kk = 0; kk < NKK; kk++) {
        u64 f0 = *(const u64*)(f0p + 2 * kk);
        u64 f1 = *(const u64*)(f1p + 2 * kk);
        const u64* wr = Wp + kk * 64;
        ulonglong2 w0 = *(const ulonglong2*)(wr + 2 * cg);
        ulonglong2 w1 = *(const ulonglong2*)(wr + 16 + 2 * cg);
        ulonglong2 w2 = *(const ulonglong2*)(wr + 32 + 2 * cg);
        ulonglong2 w3 = *(const ulonglong2*)(wr + 48 + 2 * cg);
        acc[0] = ffma2(f0, w0.x, acc[0]);   acc[1] = ffma2(f0, w0.y, acc[1]);
        acc[2] = ffma2(f0, w1.x, acc[2]);   acc[3] = ffma2(f0, w1.y, acc[3]);
        acc[4] = ffma2(f0, w2.x, acc[4]);   acc[5] = ffma2(f0, w2.y, acc[5]);
        acc[6] = ffma2(f0, w3.x, acc[6]);   acc[7] = ffma2(f0, w3.y, acc[7]);
        acc[8] = ffma2(f1, w0.x, acc[8]);   acc[9] = ffma2(f1, w0.y, acc[9]);
        acc[10] = ffma2(f1, w1.x, acc[10]); acc[11] = ffma2(f1, w1.y, acc[11]);
        acc[12] = ffma2(f1, w2.x, acc[12]); acc[13] = ffma2(f1, w2.y, acc[13]);
        acc[14] = ffma2(f1, w3.x, acc[14]); acc[15] = ffma2(f1, w3.y, acc[15]);
    }
}

// ---------------- edge kernel (FFMA2 + cp.async double-buffered gather) ----------------
__global__ void __launch_bounds__(512, 1)
edge_kernel(int li,
            const float* __restrict__ W1, const float* __restrict__ b1,
            const float* __restrict__ W2, const float* __restrict__ b2,
            float C) {
    extern __shared__ char smraw[];
    u64* Wp1 = (u64*)smraw;                 // 8192 u64
    u64* Wp2 = Wp1 + 8192;                  // 2048 u64
    float* b1s = (float*)(Wp2 + 2048);      // 64
    float* b2s = b1s + 64;                  // 64
    float* bufA_all = b2s + 64;             // 16 * 8 * FSTR
    float* bufB_all = bufA_all + EK_WARPS * 8 * FSTR;
    __shared__ int idxS[EK_WARPS][2][16];

    int tid = threadIdx.x;
    for (int i = tid; i < 8192; i += 512) {
        int kk = i >> 6, c = i & 63;
        Wp1[i] = packf2(W1[(2 * kk) * 64 + c], W1[(2 * kk + 1) * 64 + c]);
    }
    for (int i = tid; i < 2048; i += 512) {
        int kk = i >> 6, c = i & 63;
        Wp2[i] = packf2(W2[(2 * kk) * 64 + c], W2[(2 * kk + 1) * 64 + c]);
    }
    if (tid < 64) { b1s[tid] = b1[tid]; b2s[tid] = b2[tid]; }
    __syncthreads();

    int wid = tid >> 5, lane = tid & 31;
    int er = lane >> 3, cg = lane & 7;
    float* bufA = bufA_all + wid * (8 * FSTR);
    float* bufB = bufB_all + wid * (8 * FSTR);
    unsigned bufA_s = (unsigned)__cvta_generic_to_shared(bufA);
    unsigned bufB_s = (unsigned)__cvta_generic_to_shared(bufB);

    int colb[4] = {2 * cg, 16 + 2 * cg, 32 + 2 * cg, 48 + 2 * cg};
    float bb1[8], bb2[8];
#pragma unroll
    for (int q = 0; q < 4; q++) {
        bb1[2 * q] = b1s[colb[q]]; bb1[2 * q + 1] = b1s[colb[q] + 1];
        bb2[2 * q] = b2s[colb[q]]; bb2[2 * q + 1] = b2s[colb[q] + 1];
    }

    int nE = g_ne_c[li];
    const int* rows = g_rows_c[li];
    const int* cols = g_cols_c[li];
    int ngroups = (nE + 7) >> 3;
    int nw = gridDim.x * EK_WARPS;
    int g = blockIdx.x * EK_WARPS + wid;
    int cur = 0;

    const float* fA0 = bufA + er * FSTR;
    const float* fA1 = bufA + (er + 4) * FSTR;
    const float* fB0 = bufB + er * FSTR;
    const float* fB1 = bufB + (er + 4) * FSTR;

    if (g < ngroups) {
        if (lane < 16) {
            int e = g * 8 + (lane & 7);
            if (e >= nE) e = nE - 1;
            idxS[wid][0][lane] = (lane < 8) ? rows[e] : cols[e];
        }
        __syncwarp();
#pragma unroll
        for (int e = 0; e < 8; e++)
            cp16(bufA_s + (e * FSTR + 4 * lane) * 4,
                 g_h + (size_t)idxS[wid][0][e] * 128 + 4 * lane);
    }
    cp_commit();

    for (; g < ngroups; g += nw) {
        int* idx = idxS[wid][cur];
        // prefetch cols(current) -> bufB
#pragma unroll
        for (int e = 0; e < 8; e++)
            cp16(bufB_s + (e * FSTR + 4 * lane) * 4,
                 g_h + (size_t)idx[8 + e] * 128 + 4 * lane);
        cp_commit();
        cp_wait<1>(); __syncwarp();          // bufA (rows) ready

        u64 acc[16];
#pragma unroll
        for (int j = 0; j < 16; j++) acc[j] = 0ull;
        mlp64<64>(fA0, fA1, Wp1, cg, acc);   // layer1 pass1 (k 0..127)
        __syncwarp();                        // all lanes done reading bufA

        int gn = g + nw;
        int* idxn = idxS[wid][cur ^ 1];
        if (gn < ngroups) {
            if (lane < 16) {
                int e = gn * 8 + (lane & 7);
                if (e >= nE) e = nE - 1;
                idxn[lane] = (lane < 8) ? rows[e] : cols[e];
            }
            __syncwarp();
#pragma unroll
            for (int e = 0; e < 8; e++)
                cp16(bufA_s + (e * FSTR + 4 * lane) * 4,
                     g_h + (size_t)idxn[e] * 128 + 4 * lane);
        }
        cp_commit();
        cp_wait<1>(); __syncwarp();          // bufB (cols) ready

        mlp64<64>(fB0, fB1, Wp1 + 4096, cg, acc);  // layer1 pass2 (k 128..255)
        __syncwarp();

        // finalize layer1: m = silu(lo+hi+b1), stored into bufB
#pragma unroll
        for (int q = 0; q < 4; q++) {
            float2 m0, m1;
            m0.x = silu(lo32(acc[2*q])     + hi32(acc[2*q])     + bb1[2*q]);
            m0.y = silu(lo32(acc[2*q+1])   + hi32(acc[2*q+1])   + bb1[2*q+1]);
            m1.x = silu(lo32(acc[8+2*q])   + hi32(acc[8+2*q])   + bb1[2*q]);
            m1.y = silu(lo32(acc[8+2*q+1]) + hi32(acc[8+2*q+1]) + bb1[2*q+1]);
            *(float2*)(bufB + er * FSTR + colb[q]) = m0;
            *(float2*)(bufB + (er + 4) * FSTR + colb[q]) = m1;
        }
        __syncwarp();

        // layer2 (64 -> 64)
        u64 acc2[16];
#pragma unroll
        for (int j = 0; j < 16; j++) acc2[j] = 0ull;
        mlp64<32>(fB0, fB1, Wp2, cg, acc2);

        // scatter: agg[row] += silu(out) * C  (vector red, 8B per op)
        int e0g = g * 8;
        bool vA = (e0g + er) < nE;
        bool vB = (e0g + er + 4) < nE;
        int rA = idx[er], rB = idx[er + 4];
#pragma unroll
        for (int q = 0; q < 4; q++) {
            if (vA) {
                float* a = g_agg + rA * 64 + colb[q];
                red2(a, silu(lo32(acc2[2*q])   + hi32(acc2[2*q])   + bb2[2*q])   * C,
                        silu(lo32(acc2[2*q+1]) + hi32(acc2[2*q+1]) + bb2[2*q+1]) * C);
            }
            if (vB) {
                float* a = g_agg + rB * 64 + colb[q];
                red2(a, silu(lo32(acc2[8+2*q])   + hi32(acc2[8+2*q])   + bb2[2*q])   * C,
                        silu(lo32(acc2[8+2*q+1]) + hi32(acc2[8+2*q+1]) + bb2[2*q+1]) * C);
            }
        }
        __syncwarp();   // bufB reads done before next iteration's cols prefetch
        cur ^= 1;
    }
}
#define EDGE_SMEM_BYTES (8192*8 + 2048*8 + 128*4 + 2*EK_WARPS*8*FSTR*4)

// ---------------- node kernel (FFMA2, 4 compacted rows/warp; re-zeroes agg) ----------------
__global__ void __launch_bounds__(512, 1)
node_kernel(int li,
            const float* __restrict__ W1, const float* __restrict__ b1,
            const float* __restrict__ W2, const float* __restrict__ b2) {
    extern __shared__ char smraw[];
    u64* Wp1 = (u64*)smraw;                 // 96 kk * 128 cols
    u64* Wp2 = Wp1 + 12288;                 // 64 kk * 128 cols
    float* b1s = (float*)(Wp2 + 8192);      // 128
    float* b2s = b1s + 128;                 // 128
    float* xAll = b2s + 128;                // 16 warps * 4 rows * 200

    int tid = threadIdx.x;
    for (int i = tid; i < 12288; i += 512) {
        int kk = i >> 7, c = i & 127;
        Wp1[i] = packf2(W1[(2 * kk) * 128 + c], W1[(2 * kk + 1) * 128 + c]);
    }
    for (int i = tid; i < 8192; i += 512) {
        int kk = i >> 7, c = i & 127;
        Wp2[i] = packf2(W2[(2 * kk) * 128 + c], W2[(2 * kk + 1) * 128 + c]);
    }
    if (tid < 128) { b1s[tid] = b1[tid]; b2s[tid] = b2[tid]; }
    __syncthreads();

    int wid = tid >> 5, lane = tid & 31;
    float* xS = xAll + wid * 800;
    int c0 = 2 * lane, c1 = 64 + 2 * lane;
    float bb1[4] = {b1s[c0], b1s[c0 + 1], b1s[c1], b1s[c1 + 1]};
    float bb2[4] = {b2s[c0], b2s[c0 + 1], b2s[c1], b2s[c1 + 1]};

    int nn = g_nn_c[li];
    const int* list = g_nodes_c[li];
    int ntiles = (nn + 3) >> 2;
    for (int t = blockIdx.x * 16 + wid; t < ntiles; t += gridDim.x * 16) {
        int rid[4]; bool rv[4];
#pragma unroll
        for (int j = 0; j < 4; j++) {
            int p = 4 * t + j;
            rv[j] = p < nn;
            rid[j] = list[rv[j] ? p : (nn - 1)];
        }
        // gather x = [h || agg]
#pragma unroll
        for (int j = 0; j < 4; j++) {
            for (int v = lane; v < 48; v += 32) {
                float4 val = (v < 32) ? *(const float4*)(g_h + (size_t)rid[j] * 128 + 4 * v)
                                      : *(const float4*)(g_agg + (size_t)rid[j] * 64 + 4 * (v - 32));
                *(float4*)(xS + j * 200 + 4 * v) = val;
            }
        }
        __syncwarp();

        u64 acc[16];
#pragma unroll
        for (int j = 0; j < 16; j++) acc[j] = 0ull;
#pragma unroll 2
        for (int kk = 0; kk < 96; kk++) {
            const u64* wr = Wp1 + kk * 128;
            ulonglong2 wA = *(const ulonglong2*)(wr + c0);
            ulonglong2 wB = *(const ulonglong2*)(wr + c1);
#pragma unroll
            for (int j = 0; j < 4; j++) {
                u64 f = *(const u64*)(xS + j * 200 + 2 * kk);
                acc[4 * j]     = ffma2(f, wA.x, acc[4 * j]);
                acc[4 * j + 1] = ffma2(f, wA.y, acc[4 * j + 1]);
                acc[4 * j + 2] = ffma2(f, wB.x, acc[4 * j + 2]);
                acc[4 * j + 3] = ffma2(f, wB.y, acc[4 * j + 3]);
            }
        }
        __syncwarp();   // all lanes done reading x before m overwrites

        float res[16];
#pragma unroll
        for (int j = 0; j < 4; j++) {
            res[4 * j]     = xS[j * 200 + c0];
            res[4 * j + 1] = xS[j * 200 + c0 + 1];
            res[4 * j + 2] = xS[j * 200 + c1];
            res[4 * j + 3] = xS[j * 200 + c1 + 1];
        }
#pragma unroll
        for (int j = 0; j < 4; j++) {
            float2 mA, mB;
            mA.x = silu(lo32(acc[4*j])     + hi32(acc[4*j])     + bb1[0]);
            mA.y = silu(lo32(acc[4*j+1])   + hi32(acc[4*j+1])   + bb1[1]);
            mB.x = silu(lo32(acc[4*j+2])   + hi32(acc[4*j+2])   + bb1[2]);
            mB.y = silu(lo32(acc[4*j+3])   + hi32(acc[4*j+3])   + bb1[3]);
            *(float2*)(xS + j * 200 + c0) = mA;
            *(float2*)(xS + j * 200 + c1) = mB;
        }
        __syncwarp();

#pragma unroll
        for (int j = 0; j < 16; j++) acc[j] = 0ull;
#pragma unroll 2
        for (int kk = 0; kk < 64; kk++) {
            const u64* wr = Wp2 + kk * 128;
            ulonglong2 wA = *(const ulonglong2*)(wr + c0);
            ulonglong2 wB = *(const ulonglong2*)(wr + c1);
#pragma unroll
            for (int j = 0; j < 4; j++) {
                u64 f = *(const u64*)(xS + j * 200 + 2 * kk);
                acc[4 * j]     = ffma2(f, wA.x, acc[4 * j]);
                acc[4 * j + 1] = ffma2(f, wA.y, acc[4 * j + 1]);
                acc[4 * j + 2] = ffma2(f, wB.x, acc[4 * j + 2]);
                acc[4 * j + 3] = ffma2(f, wB.y, acc[4 * j + 3]);
            }
        }
#pragma unroll
        for (int j = 0; j < 4; j++) {
            if (!rv[j]) continue;
            float2 oA, oB;
            oA.x = res[4*j]     + lo32(acc[4*j])     + hi32(acc[4*j])     + bb2[0];
            oA.y = res[4*j+1]   + lo32(acc[4*j+1])   + hi32(acc[4*j+1])   + bb2[1];
            oB.x = res[4*j+2]   + lo32(acc[4*j+2])   + hi32(acc[4*j+2])   + bb2[2];
            oB.y = res[4*j+3]   + lo32(acc[4*j+3])   + hi32(acc[4*j+3])   + bb2[3];
            *(float2*)(g_h + (size_t)rid[j] * 128 + c0) = oA;
            *(float2*)(g_h + (size_t)rid[j] * 128 + c1) = oB;
        }
        // consume-and-zero: restore agg rows of this tile to 0 for the next layer
#pragma unroll
        for (int j = 0; j < 4; j++) {
            if (rv[j] && lane < 16)
                *(float4*)(g_agg + (size_t)rid[j] * 64 + 4 * lane) =
                    make_float4(0.f, 0.f, 0.f, 0.f);
        }
        __syncwarp();
    }
}
#define NODE_SMEM_BYTES (12288*8 + 8192*8 + 256*4 + 16*800*4)

// ---------------- launch ----------------
// Order chosen so the FIRST edge_kernel is launch index 3 (ncu capture slot).
extern "C" void kernel_launch(void* const* d_in, const int* in_sizes, int n_in,
                              void* d_out, int out_size) {
    const float* h_in = (const float*)d_in[0];
    const int*   eA   = (const int*)d_in[1];
    const int*   eB   = (const int*)d_in[2];
    const void*  mA   = d_in[3];
    const void*  mB   = d_in[4];
    const float* Wi   = (const float*)d_in[5];
    const float* bi   = (const float*)d_in[6];
    const float* Wo   = (const float*)d_in[7];
    const float* bo   = (const float*)d_in[8];
    const float* ew1  = (const float*)d_in[9];
    const float* eb1  = (const float*)d_in[10];
    const float* ew2  = (const float*)d_in[11];
    const float* eb2  = (const float*)d_in[12];
    const float* nw1  = (const float*)d_in[13];
    const float* nb1  = (const float*)d_in[14];
    const float* nw2  = (const float*)d_in[15];
    const float* nb2  = (const float*)d_in[16];
    float* out = (float*)d_out;

    cudaFuncSetAttribute(edge_kernel, cudaFuncAttributeMaxDynamicSharedMemorySize,
                         EDGE_SMEM_BYTES);
    cudaFuncSetAttribute(node_kernel, cudaFuncAttributeMaxDynamicSharedMemorySize,
                         NODE_SMEM_BYTES);
    cudaFuncSetAttribute(embed_in_kernel, cudaFuncAttributeMaxDynamicSharedMemorySize,
                         EMBI_SMEM);
    cudaFuncSetAttribute(embed_out_kernel, cudaFuncAttributeMaxDynamicSharedMemorySize,
                         EMBO_SMEM);

    // 0: mask detect + counter reset
    detect_mask_kernel<<<1, 256>>>((const unsigned int*)mA);
    // 1: compact edges for even layers
    compact_kernel<<<3125, 256>>>(eA, mA, 0);
    // 2: input embedding (also zeroes g_agg)
    embed_in_kernel<<<148, 512, EMBI_SMEM>>>(h_in, Wi, bi);
    // 3: layer 0 edge kernel  <-- ncu capture slot
    edge_kernel<<<148, 512, EDGE_SMEM_BYTES>>>(
        0, ew1, eb1, ew2, eb2, 1.0f);
    // remaining compactions (needed from node0 / edge1 onward)
    compact_nodes_kernel<<<196, 256>>>(mA, 0);
    node_kernel<<<148, 512, NODE_SMEM_BYTES>>>(0, nw1, nb1, nw2, nb2);
    compact_kernel<<<3125, 256>>>(eB, mB, 1);
    compact_nodes_kernel<<<196, 256>>>(mB, 1);

    for (int i = 1; i < 4; i++) {
        int li = i % 2;
        float C = (li == 0) ? 1.0f : (2.0f / 64.0f);
        edge_kernel<<<148, 512, EDGE_SMEM_BYTES>>>(
            li, ew1 + i * 256 * 64, eb1 + i * 64,
            ew2 + i * 64 * 64, eb2 + i * 64, C);
        node_kernel<<<148, 512, NODE_SMEM_BYTES>>>(
            li, nw1 + i * 192 * 128, nb1 + i * 128,
            nw2 + i * 128 * 128, nb2 + i * 128);
    }

    embed_out_kernel<<<148, 512, EMBO_SMEM>>>(Wo, bo, out);
}

// round 13
// speedup vs baseline: 1.2013x; 1.1250x over previous
#include <cuda_runtime.h>
#include <cuda_bf16.h>

typedef unsigned long long u64;

#define N_NODES 50000
#define N_EDGES 800000
#define HID 128
#define EH 64
#define FSTR 132            // floats per edge row in feat buffer (bank-spread)
#define EK_WARPS 8
#define EPW 16              // edges per warp group

// ---------------- scratch (no allocs allowed) ----------------
__device__ float g_h[N_NODES * HID];
__device__ float g_agg[N_NODES * EH];
__device__ int   g_mask_u8;
__device__ int   g_ne_c[2];
__device__ int   g_rows_c[2][N_EDGES];
__device__ int   g_cols_c[2][N_EDGES];
__device__ int   g_nn_c[2];
__device__ int   g_nodes_c[2][N_NODES];

__device__ __forceinline__ float silu(float x) { return x / (1.0f + __expf(-x)); }
__device__ __forceinline__ u64 ffma2(u64 a, u64 b, u64 c) {
    u64 d; asm("fma.rn.f32x2 %0, %1, %2, %3;" : "=l"(d) : "l"(a), "l"(b), "l"(c)); return d;
}
__device__ __forceinline__ float lo32(u64 a) { return __uint_as_float((unsigned)a); }
__device__ __forceinline__ float hi32(u64 a) { return __uint_as_float((unsigned)(a >> 32)); }
__device__ __forceinline__ u64 packf2(float lo, float hi) {
    return (u64)__float_as_uint(lo) | ((u64)__float_as_uint(hi) << 32);
}
__device__ __forceinline__ void cp16(unsigned d, const void* s) {
    asm volatile("cp.async.cg.shared.global [%0], [%1], 16;" :: "r"(d), "l"(s));
}
__device__ __forceinline__ void cp_commit() { asm volatile("cp.async.commit_group;"); }
template<int N> __device__ __forceinline__ void cp_wait() {
    asm volatile("cp.async.wait_group %0;" :: "n"(N));
}
__device__ __forceinline__ void red2(float* a, float x, float y) {
    asm volatile("red.global.add.v2.f32 [%0], {%1, %2};" :: "l"(a), "f"(x), "f"(y) : "memory");
}

// ---------------- mask dtype detection + counter reset ----------------
__global__ void detect_mask_kernel(const unsigned int* __restrict__ m) {
    if (threadIdx.x < 2) { g_ne_c[threadIdx.x] = 0; g_nn_c[threadIdx.x] = 0; }
    int bad = 0;
    for (int i = threadIdx.x; i < N_NODES / 4; i += blockDim.x)
        if (m[i] > 1u) bad = 1;
    bad = __syncthreads_or(bad);
    if (threadIdx.x == 0) g_mask_u8 = bad;
}

// ---------------- edge compaction ----------------
__global__ void __launch_bounds__(256)
compact_kernel(const int* __restrict__ edges, const void* __restrict__ mask, int li) {
    int e = blockIdx.x * 256 + threadIdx.x, lane = threadIdx.x & 31;
    int mu8 = g_mask_u8;
    bool valid = false; int rv = 0, cv = 0;
    if (e < N_EDGES) {
        rv = edges[e]; cv = edges[e + N_EDGES];
        valid = mu8 ? (((const unsigned char*)mask)[rv] != 0)
                    : (((const int*)mask)[rv] != 0);
    }
    unsigned bal = __ballot_sync(0xffffffffu, valid);
    int base = 0;
    if (lane == 0 && bal) base = atomicAdd(&g_ne_c[li], __popc(bal));
    base = __shfl_sync(0xffffffffu, base, 0);
    if (valid) {
        int p = base + __popc(bal & ((1u << lane) - 1u));
        g_rows_c[li][p] = rv; g_cols_c[li][p] = cv;
    }
}

// ---------------- node compaction ----------------
__global__ void __launch_bounds__(256)
compact_nodes_kernel(const void* __restrict__ mask, int li) {
    int n = blockIdx.x * 256 + threadIdx.x, lane = threadIdx.x & 31;
    int mu8 = g_mask_u8;
    bool valid = false;
    if (n < N_NODES)
        valid = mu8 ? (((const unsigned char*)mask)[n] != 0)
                    : (((const int*)mask)[n] != 0);
    unsigned bal = __ballot_sync(0xffffffffu, valid);
    int base = 0;
    if (lane == 0 && bal) base = atomicAdd(&g_nn_c[li], __popc(bal));
    base = __shfl_sync(0xffffffffu, base, 0);
    if (valid)
        g_nodes_c[li][base + __popc(bal & ((1u << lane) - 1u))] = n;
}

// ---------------- input embedding (FFMA2) + agg zero-init ----------------
__global__ void __launch_bounds__(512, 1)
embed_in_kernel(const float* __restrict__ h_in, const float* __restrict__ W,
                const float* __restrict__ b) {
    extern __shared__ char smraw[];
    u64* Wp = (u64*)smraw;
    float* bs = (float*)(Wp + 4096);
    float* xAll = bs + 128;
    int tid = threadIdx.x;
    for (int i = tid; i < 4096; i += 512) {
        int kk = i >> 7, c = i & 127;
        Wp[i] = packf2(W[(2 * kk) * 128 + c], W[(2 * kk + 1) * 128 + c]);
    }
    if (tid < 128) bs[tid] = b[tid];
    __syncthreads();
    int wid = tid >> 5, lane = tid & 31;
    float* xS = xAll + wid * 288;
    int c0 = 2 * lane, c1 = 64 + 2 * lane;
    float bb[4] = {bs[c0], bs[c0 + 1], bs[c1], bs[c1 + 1]};
    for (int t = blockIdx.x * 16 + wid; t < N_NODES / 4; t += gridDim.x * 16) {
        int r0 = 4 * t;
        for (int i = lane; i < 64; i += 32) {
            int rr = i >> 4, v = i & 15;
            *(float4*)(xS + rr * 72 + 4 * v) =
                *(const float4*)(h_in + (r0 + rr) * 64 + 4 * v);
        }
        for (int i = lane; i < 64; i += 32)
            *(float4*)(g_agg + (size_t)r0 * 64 + 4 * i) = make_float4(0.f, 0.f, 0.f, 0.f);
        __syncwarp();
        u64 acc[16];
#pragma unroll
        for (int j = 0; j < 16; j++) acc[j] = 0ull;
#pragma unroll 4
        for (int kk = 0; kk < 32; kk++) {
            const u64* wr = Wp + kk * 128;
            ulonglong2 wA = *(const ulonglong2*)(wr + c0);
            ulonglong2 wB = *(const ulonglong2*)(wr + c1);
#pragma unroll
            for (int j = 0; j < 4; j++) {
                u64 f = *(const u64*)(xS + j * 72 + 2 * kk);
                acc[4*j]   = ffma2(f, wA.x, acc[4*j]);
                acc[4*j+1] = ffma2(f, wA.y, acc[4*j+1]);
                acc[4*j+2] = ffma2(f, wB.x, acc[4*j+2]);
                acc[4*j+3] = ffma2(f, wB.y, acc[4*j+3]);
            }
        }
#pragma unroll
        for (int j = 0; j < 4; j++) {
            float2 oA, oB;
            oA.x = lo32(acc[4*j])   + hi32(acc[4*j])   + bb[0];
            oA.y = lo32(acc[4*j+1]) + hi32(acc[4*j+1]) + bb[1];
            oB.x = lo32(acc[4*j+2]) + hi32(acc[4*j+2]) + bb[2];
            oB.y = lo32(acc[4*j+3]) + hi32(acc[4*j+3]) + bb[3];
            *(float2*)(g_h + (size_t)(r0 + j) * 128 + c0) = oA;
            *(float2*)(g_h + (size_t)(r0 + j) * 128 + c1) = oB;
        }
        __syncwarp();
    }
}
#define EMBI_SMEM (4096 * 8 + 128 * 4 + 16 * 288 * 4)

// ---------------- output embedding (FFMA2) ----------------
__global__ void __launch_bounds__(512, 1)
embed_out_kernel(const float* __restrict__ W, const float* __restrict__ b,
                 float* __restrict__ out) {
    extern __shared__ char smraw[];
    u64* Wp = (u64*)smraw;
    float* bs = (float*)(Wp + 4096);
    float* xAll = bs + 64;
    int tid = threadIdx.x;
    for (int i = tid; i < 4096; i += 512) {
        int kk = i >> 6, c = i & 63;
        Wp[i] = packf2(W[(2 * kk) * 64 + c], W[(2 * kk + 1) * 64 + c]);
    }
    if (tid < 64) bs[tid] = b[tid];
    __syncthreads();
    int wid = tid >> 5, lane = tid & 31;
    float* xS = xAll + wid * 1088;
    int c0 = 2 * lane;
    float bb0 = bs[c0], bb1 = bs[c0 + 1];
    for (int t = blockIdx.x * 16 + wid; t < N_NODES / 8; t += gridDim.x * 16) {
        int r0 = 8 * t;
        for (int i = lane; i < 256; i += 32) {
            int rr = i >> 5, v = i & 31;
            *(float4*)(xS + rr * 136 + 4 * v) =
                *(const float4*)(g_h + (size_t)(r0 + rr) * 128 + 4 * v);
        }
        __syncwarp();
        u64 acc[16];
#pragma unroll
        for (int j = 0; j < 16; j++) acc[j] = 0ull;
#pragma unroll 4
        for (int kk = 0; kk < 64; kk++) {
            ulonglong2 w = *(const ulonglong2*)(Wp + kk * 64 + c0);
#pragma unroll
            for (int j = 0; j < 8; j++) {
                u64 f = *(const u64*)(xS + j * 136 + 2 * kk);
                acc[2*j]   = ffma2(f, w.x, acc[2*j]);
                acc[2*j+1] = ffma2(f, w.y, acc[2*j+1]);
            }
        }
#pragma unroll
        for (int j = 0; j < 8; j++) {
            float2 o;
            o.x = lo32(acc[2*j])   + hi32(acc[2*j])   + bb0;
            o.y = lo32(acc[2*j+1]) + hi32(acc[2*j+1]) + bb1;
            *(float2*)(out + (size_t)(r0 + j) * 64 + c0) = o;
        }
        __syncwarp();
    }
}
#define EMBO_SMEM (4096 * 8 + 64 * 4 + 16 * 1088 * 4)

// ---------------- edge MLP inner block: 4 edges/lane x 8 cols/lane ----------------
// acc layout: acc[j*8 + {0..7}] = cols {2cg,2cg+1, 16+2cg,+1, 32+2cg,+1, 48+2cg,+1}
template<int NKK>
__device__ __forceinline__ void mlpB(const float* f0, const float* f1,
                                     const float* f2, const float* f3,
                                     const u64* Wp, int cg, u64* acc) {
#pragma unroll 2
    for (int kp = 0; kp < NKK / 2; kp++) {
        ulonglong2 p0 = *(const ulonglong2*)(f0 + 4 * kp);
        ulonglong2 p1 = *(const ulonglong2*)(f1 + 4 * kp);
        ulonglong2 p2 = *(const ulonglong2*)(f2 + 4 * kp);
        ulonglong2 p3 = *(const ulonglong2*)(f3 + 4 * kp);
#pragma unroll
        for (int h = 0; h < 2; h++) {
            const u64* wr = Wp + (2 * kp + h) * 64;
            ulonglong2 w0 = *(const ulonglong2*)(wr + 2 * cg);
            ulonglong2 w1 = *(const ulonglong2*)(wr + 16 + 2 * cg);
            ulonglong2 w2 = *(const ulonglong2*)(wr + 32 + 2 * cg);
            ulonglong2 w3 = *(const ulonglong2*)(wr + 48 + 2 * cg);
            u64 F0 = h ? p0.y : p0.x;
            u64 F1 = h ? p1.y : p1.x;
            u64 F2 = h ? p2.y : p2.x;
            u64 F3 = h ? p3.y : p3.x;
            acc[0] = ffma2(F0, w0.x, acc[0]);   acc[1] = ffma2(F0, w0.y, acc[1]);
            acc[2] = ffma2(F0, w1.x, acc[2]);   acc[3] = ffma2(F0, w1.y, acc[3]);
            acc[4] = ffma2(F0, w2.x, acc[4]);   acc[5] = ffma2(F0, w2.y, acc[5]);
            acc[6] = ffma2(F0, w3.x, acc[6]);   acc[7] = ffma2(F0, w3.y, acc[7]);
            acc[8] = ffma2(F1, w0.x, acc[8]);   acc[9] = ffma2(F1, w0.y, acc[9]);
            acc[10] = ffma2(F1, w1.x, acc[10]); acc[11] = ffma2(F1, w1.y, acc[11]);
            acc[12] = ffma2(F1, w2.x, acc[12]); acc[13] = ffma2(F1, w2.y, acc[13]);
            acc[14] = ffma2(F1, w3.x, acc[14]); acc[15] = ffma2(F1, w3.y, acc[15]);
            acc[16] = ffma2(F2, w0.x, acc[16]); acc[17] = ffma2(F2, w0.y, acc[17]);
            acc[18] = ffma2(F2, w1.x, acc[18]); acc[19] = ffma2(F2, w1.y, acc[19]);
            acc[20] = ffma2(F2, w2.x, acc[20]); acc[21] = ffma2(F2, w2.y, acc[21]);
            acc[22] = ffma2(F2, w3.x, acc[22]); acc[23] = ffma2(F2, w3.y, acc[23]);
            acc[24] = ffma2(F3, w0.x, acc[24]); acc[25] = ffma2(F3, w0.y, acc[25]);
            acc[26] = ffma2(F3, w1.x, acc[26]); acc[27] = ffma2(F3, w1.y, acc[27]);
            acc[28] = ffma2(F3, w2.x, acc[28]); acc[29] = ffma2(F3, w2.y, acc[29]);
            acc[30] = ffma2(F3, w3.x, acc[30]); acc[31] = ffma2(F3, w3.y, acc[31]);
        }
    }
}

// ---------------- edge kernel (FFMA2, 16 edges/warp, cp.async pipeline) ----------------
__global__ void __launch_bounds__(256, 1)
edge_kernel(int li,
            const float* __restrict__ W1, const float* __restrict__ b1,
            const float* __restrict__ W2, const float* __restrict__ b2,
            float C) {
    extern __shared__ char smraw[];
    u64* Wp1 = (u64*)smraw;                 // 8192 u64 = 64KB
    u64* Wp2 = Wp1 + 8192;                  // 2048 u64 = 16KB
    float* b1s = (float*)(Wp2 + 2048);      // 64
    float* b2s = b1s + 64;                  // 64
    float* bufA_all = b2s + 64;             // 8 warps * 16 edges * FSTR
    float* bufB_all = bufA_all + EK_WARPS * EPW * FSTR;
    __shared__ int idxS[EK_WARPS][2][32];

    int tid = threadIdx.x;
    for (int i = tid; i < 8192; i += 256) {
        int kk = i >> 6, c = i & 63;
        Wp1[i] = packf2(W1[(2 * kk) * 64 + c], W1[(2 * kk + 1) * 64 + c]);
    }
    for (int i = tid; i < 2048; i += 256) {
        int kk = i >> 6, c = i & 63;
        Wp2[i] = packf2(W2[(2 * kk) * 64 + c], W2[(2 * kk + 1) * 64 + c]);
    }
    if (tid < 64) { b1s[tid] = b1[tid]; b2s[tid] = b2[tid]; }
    __syncthreads();

    int wid = tid >> 5, lane = tid & 31;
    int er = lane >> 3, cg = lane & 7;
    float* bufA = bufA_all + wid * (EPW * FSTR);
    float* bufB = bufB_all + wid * (EPW * FSTR);
    unsigned bufA_s = (unsigned)__cvta_generic_to_shared(bufA);
    unsigned bufB_s = (unsigned)__cvta_generic_to_shared(bufB);

    int colb[4] = {2 * cg, 16 + 2 * cg, 32 + 2 * cg, 48 + 2 * cg};
    float bb1[8], bb2[8];
#pragma unroll
    for (int q = 0; q < 4; q++) {
        bb1[2 * q] = b1s[colb[q]]; bb1[2 * q + 1] = b1s[colb[q] + 1];
        bb2[2 * q] = b2s[colb[q]]; bb2[2 * q + 1] = b2s[colb[q] + 1];
    }
    // this lane's 4 edges: 4*er + j
    const float* fA0 = bufA + (4 * er + 0) * FSTR;
    const float* fA1 = bufA + (4 * er + 1) * FSTR;
    const float* fA2 = bufA + (4 * er + 2) * FSTR;
    const float* fA3 = bufA + (4 * er + 3) * FSTR;
    const float* fB0 = bufB + (4 * er + 0) * FSTR;
    const float* fB1 = bufB + (4 * er + 1) * FSTR;
    const float* fB2 = bufB + (4 * er + 2) * FSTR;
    const float* fB3 = bufB + (4 * er + 3) * FSTR;

    int nE = g_ne_c[li];
    const int* rows = g_rows_c[li];
    const int* cols = g_cols_c[li];
    int ngroups = (nE + EPW - 1) >> 4;
    int nw = gridDim.x * EK_WARPS;
    int g = blockIdx.x * EK_WARPS + wid;
    int cur = 0;

    if (g < ngroups) {
        int* idx = idxS[wid][0];
        {
            int e = g * EPW + (lane & 15);
            if (e >= nE) e = nE - 1;
            idx[lane] = (lane < 16) ? rows[e] : cols[e];
        }
        __syncwarp();
#pragma unroll
        for (int e = 0; e < EPW; e++)
            cp16(bufA_s + (e * FSTR + 4 * lane) * 4,
                 g_h + (size_t)idx[e] * 128 + 4 * lane);
    }
    cp_commit();

    for (; g < ngroups; g += nw) {
        int* idx = idxS[wid][cur];
        // prefetch cols(current) -> bufB
#pragma unroll
        for (int e = 0; e < EPW; e++)
            cp16(bufB_s + (e * FSTR + 4 * lane) * 4,
                 g_h + (size_t)idx[16 + e] * 128 + 4 * lane);
        cp_commit();
        cp_wait<1>(); __syncwarp();          // bufA (rows) ready

        u64 acc[32];
#pragma unroll
        for (int j = 0; j < 32; j++) acc[j] = 0ull;
        mlpB<64>(fA0, fA1, fA2, fA3, Wp1, cg, acc);      // layer1, k 0..127
        __syncwarp();                                    // bufA reads done

        int gn = g + nw;
        int* idxn = idxS[wid][cur ^ 1];
        if (gn < ngroups) {
            {
                int e = gn * EPW + (lane & 15);
                if (e >= nE) e = nE - 1;
                idxn[lane] = (lane < 16) ? rows[e] : cols[e];
            }
            __syncwarp();
#pragma unroll
            for (int e = 0; e < EPW; e++)
                cp16(bufA_s + (e * FSTR + 4 * lane) * 4,
                     g_h + (size_t)idxn[e] * 128 + 4 * lane);
        }
        cp_commit();
        cp_wait<1>(); __syncwarp();          // bufB (cols) ready

        mlpB<64>(fB0, fB1, fB2, fB3, Wp1 + 4096, cg, acc);  // layer1, k 128..255
        __syncwarp();

        // finalize layer1: m = silu(lo+hi+b1) into bufB
#pragma unroll
        for (int j = 0; j < 4; j++) {
            float* mrow = bufB + (4 * er + j) * FSTR;
#pragma unroll
            for (int q = 0; q < 4; q++) {
                float2 m;
                m.x = silu(lo32(acc[j*8+2*q])   + hi32(acc[j*8+2*q])   + bb1[2*q]);
                m.y = silu(lo32(acc[j*8+2*q+1]) + hi32(acc[j*8+2*q+1]) + bb1[2*q+1]);
                *(float2*)(mrow + colb[q]) = m;
            }
        }
        __syncwarp();

        // layer2 (64 -> 64)
#pragma unroll
        for (int j = 0; j < 32; j++) acc[j] = 0ull;
        mlpB<32>(fB0, fB1, fB2, fB3, Wp2, cg, acc);

        // scatter: agg[row] += silu(out)*C
        int e0g = g * EPW;
#pragma unroll
        for (int j = 0; j < 4; j++) {
            int e = 4 * er + j;
            if (e0g + e < nE) {
                float* a = g_agg + (size_t)idx[e] * 64;
#pragma unroll
                for (int q = 0; q < 4; q++)
                    red2(a + colb[q],
                         silu(lo32(acc[j*8+2*q])   + hi32(acc[j*8+2*q])   + bb2[2*q])   * C,
                         silu(lo32(acc[j*8+2*q+1]) + hi32(acc[j*8+2*q+1]) + bb2[2*q+1]) * C);
            }
        }
        __syncwarp();   // bufB reads done before next cols prefetch
        cur ^= 1;
    }
}
#define EDGE_SMEM_BYTES (8192*8 + 2048*8 + 128*4 + 2*EK_WARPS*EPW*FSTR*4)

// ---------------- node kernel (FFMA2, 4 compacted rows/warp; re-zeroes agg) ----------------
__global__ void __launch_bounds__(512, 1)
node_kernel(int li, const float* __restrict__ W1, const float* __restrict__ b1,
            const float* __restrict__ W2, const float* __restrict__ b2) {
    extern __shared__ char smraw[];
    u64* Wp1 = (u64*)smraw;
    u64* Wp2 = Wp1 + 12288;
    float* b1s = (float*)(Wp2 + 8192);
    float* b2s = b1s + 128;
    float* xAll = b2s + 128;
    int tid = threadIdx.x;
    for (int i = tid; i < 12288; i += 512) {
        int kk = i >> 7, c = i & 127;
        Wp1[i] = packf2(W1[(2 * kk) * 128 + c], W1[(2 * kk + 1) * 128 + c]);
    }
    for (int i = tid; i < 8192; i += 512) {
        int kk = i >> 7, c = i & 127;
        Wp2[i] = packf2(W2[(2 * kk) * 128 + c], W2[(2 * kk + 1) * 128 + c]);
    }
    if (tid < 128) { b1s[tid] = b1[tid]; b2s[tid] = b2[tid]; }
    __syncthreads();
    int wid = tid >> 5, lane = tid & 31;
    float* xS = xAll + wid * 800;
    int c0 = 2 * lane, c1 = 64 + 2 * lane;
    float bb1[4] = {b1s[c0], b1s[c0+1], b1s[c1], b1s[c1+1]};
    float bb2[4] = {b2s[c0], b2s[c0+1], b2s[c1], b2s[c1+1]};

    int nn = g_nn_c[li];
    const int* list = g_nodes_c[li];
    int ntiles = (nn + 3) >> 2;
    for (int t = blockIdx.x * 16 + wid; t < ntiles; t += gridDim.x * 16) {
        int rid[4]; bool rv[4];
#pragma unroll
        for (int j = 0; j < 4; j++) {
            int p = 4 * t + j;
            rv[j] = p < nn;
            rid[j] = list[rv[j] ? p : (nn - 1)];
        }
#pragma unroll
        for (int j = 0; j < 4; j++)
            for (int v = lane; v < 48; v += 32) {
                float4 val = (v < 32) ? *(const float4*)(g_h + (size_t)rid[j] * 128 + 4 * v)
                                      : *(const float4*)(g_agg + (size_t)rid[j] * 64 + 4 * (v - 32));
                *(float4*)(xS + j * 200 + 4 * v) = val;
            }
        __syncwarp();
        u64 acc[16];
#pragma unroll
        for (int j = 0; j < 16; j++) acc[j] = 0ull;
#pragma unroll 2
        for (int kk = 0; kk < 96; kk++) {
            const u64* wr = Wp1 + kk * 128;
            ulonglong2 wA = *(const ulonglong2*)(wr + c0);
            ulonglong2 wB = *(const ulonglong2*)(wr + c1);
#pragma unroll
            for (int j = 0; j < 4; j++) {
                u64 f = *(const u64*)(xS + j * 200 + 2 * kk);
                acc[4*j]   = ffma2(f, wA.x, acc[4*j]);
                acc[4*j+1] = ffma2(f, wA.y, acc[4*j+1]);
                acc[4*j+2] = ffma2(f, wB.x, acc[4*j+2]);
                acc[4*j+3] = ffma2(f, wB.y, acc[4*j+3]);
            }
        }
        __syncwarp();
        float res[16];
#pragma unroll
        for (int j = 0; j < 4; j++) {
            res[4*j]   = xS[j * 200 + c0];
            res[4*j+1] = xS[j * 200 + c0 + 1];
            res[4*j+2] = xS[j * 200 + c1];
            res[4*j+3] = xS[j * 200 + c1 + 1];
        }
#pragma unroll
        for (int j = 0; j < 4; j++) {
            float2 mA, mB;
            mA.x = silu(lo32(acc[4*j])   + hi32(acc[4*j])   + bb1[0]);
            mA.y = silu(lo32(acc[4*j+1]) + hi32(acc[4*j+1]) + bb1[1]);
            mB.x = silu(lo32(acc[4*j+2]) + hi32(acc[4*j+2]) + bb1[2]);
            mB.y = silu(lo32(acc[4*j+3]) + hi32(acc[4*j+3]) + bb1[3]);
            *(float2*)(xS + j * 200 + c0) = mA;
            *(float2*)(xS + j * 200 + c1) = mB;
        }
        __syncwarp();
#pragma unroll
        for (int j = 0; j < 16; j++) acc[j] = 0ull;
#pragma unroll 2
        for (int kk = 0; kk < 64; kk++) {
            const u64* wr = Wp2 + kk * 128;
            ulonglong2 wA = *(const ulonglong2*)(wr + c0);
            ulonglong2 wB = *(const ulonglong2*)(wr + c1);
#pragma unroll
            for (int j = 0; j < 4; j++) {
                u64 f = *(const u64*)(xS + j * 200 + 2 * kk);
                acc[4*j]   = ffma2(f, wA.x, acc[4*j]);
                acc[4*j+1] = ffma2(f, wA.y, acc[4*j+1]);
                acc[4*j+2] = ffma2(f, wB.x, acc[4*j+2]);
                acc[4*j+3] = ffma2(f, wB.y, acc[4*j+3]);
            }
        }
#pragma unroll
        for (int j = 0; j < 4; j++) {
            if (!rv[j]) continue;
            float2 oA, oB;
            oA.x = res[4*j]   + lo32(acc[4*j])   + hi32(acc[4*j])   + bb2[0];
            oA.y = res[4*j+1] + lo32(acc[4*j+1]) + hi32(acc[4*j+1]) + bb2[1];
            oB.x = res[4*j+2] + lo32(acc[4*j+2]) + hi32(acc[4*j+2]) + bb2[2];
            oB.y = res[4*j+3] + lo32(acc[4*j+3]) + hi32(acc[4*j+3]) + bb2[3];
            *(float2*)(g_h + (size_t)rid[j] * 128 + c0) = oA;
            *(float2*)(g_h + (size_t)rid[j] * 128 + c1) = oB;
        }
#pragma unroll
        for (int j = 0; j < 4; j++)
            if (rv[j] && lane < 16)
                *(float4*)(g_agg + (size_t)rid[j] * 64 + 4 * lane) =
                    make_float4(0.f, 0.f, 0.f, 0.f);
        __syncwarp();
    }
}
#define NODE_SMEM_BYTES (12288*8 + 8192*8 + 256*4 + 16*800*4)

// ---------------- launch (edge at index 3 for ncu capture) ----------------
extern "C" void kernel_launch(void* const* d_in, const int* in_sizes, int n_in,
                              void* d_out, int out_size) {
    const float* h_in = (const float*)d_in[0];
    const int*   eA   = (const int*)d_in[1];
    const int*   eB   = (const int*)d_in[2];
    const void*  mA   = d_in[3];
    const void*  mB   = d_in[4];
    const float* Wi   = (const float*)d_in[5];
    const float* bi   = (const float*)d_in[6];
    const float* Wo   = (const float*)d_in[7];
    const float* bo   = (const float*)d_in[8];
    const float* ew1  = (const float*)d_in[9];
    const float* eb1  = (const float*)d_in[10];
    const float* ew2  = (const float*)d_in[11];
    const float* eb2  = (const float*)d_in[12];
    const float* nw1  = (const float*)d_in[13];
    const float* nb1  = (const float*)d_in[14];
    const float* nw2  = (const float*)d_in[15];
    const float* nb2  = (const float*)d_in[16];
    float* out = (float*)d_out;

    cudaFuncSetAttribute(edge_kernel, cudaFuncAttributeMaxDynamicSharedMemorySize, EDGE_SMEM_BYTES);
    cudaFuncSetAttribute(node_kernel, cudaFuncAttributeMaxDynamicSharedMemorySize, NODE_SMEM_BYTES);
    cudaFuncSetAttribute(embed_in_kernel, cudaFuncAttributeMaxDynamicSharedMemorySize, EMBI_SMEM);
    cudaFuncSetAttribute(embed_out_kernel, cudaFuncAttributeMaxDynamicSharedMemorySize, EMBO_SMEM);

    detect_mask_kernel<<<1, 256>>>((const unsigned int*)mA);
    compact_kernel<<<3125, 256>>>(eA, mA, 0);
    embed_in_kernel<<<148, 512, EMBI_SMEM>>>(h_in, Wi, bi);
    edge_kernel<<<148, 256, EDGE_SMEM_BYTES>>>(0, ew1, eb1, ew2, eb2, 1.0f);   // ncu slot
    compact_nodes_kernel<<<196, 256>>>(mA, 0);
    node_kernel<<<148, 512, NODE_SMEM_BYTES>>>(0, nw1, nb1, nw2, nb2);
    compact_kernel<<<3125, 256>>>(eB, mB, 1);
    compact_nodes_kernel<<<196, 256>>>(mB, 1);

    for (int i = 1; i < 4; i++) {
        int li = i % 2;
        float C = (li == 0) ? 1.0f : (2.0f / 64.0f);
        edge_kernel<<<148, 256, EDGE_SMEM_BYTES>>>(
            li, ew1 + i * 256 * 64, eb1 + i * 64,
            ew2 + i * 64 * 64, eb2 + i * 64, C);
        node_kernel<<<148, 512, NODE_SMEM_BYTES>>>(
            li, nw1 + i * 192 * 128, nb1 + i * 128,
            nw2 + i * 128 * 128, nb2 + i * 128);
    }

    embed_out_kernel<<<148, 512, EMBO_SMEM>>>(Wo, bo, out);
}

// round 14
// speedup vs baseline: 1.9817x; 1.6496x over previous
#include <cuda_runtime.h>
#include <cuda_bf16.h>

typedef unsigned long long u64;

#define N_NODES 50000
#define N_EDGES 800000
#define HID 128
#define EH 64

// ---------------- scratch ----------------
__device__ float g_h[N_NODES * HID];
__device__ __nv_bfloat16 g_hh[N_NODES * HID];   // bf16 hi mirror of g_h
__device__ __nv_bfloat16 g_hl[N_NODES * HID];   // bf16 lo (residual) mirror
__device__ float g_agg[N_NODES * EH];
__device__ int   g_mask_u8;
__device__ int   g_ne_c[2];
__device__ int   g_rows_c[2][N_EDGES];
__device__ int   g_cols_c[2][N_EDGES];
__device__ int   g_nn_c[2];
__device__ int   g_nodes_c[2][N_NODES];

__device__ __forceinline__ float silu(float x) { return x / (1.0f + __expf(-x)); }
__device__ __forceinline__ u64 ffma2(u64 a, u64 b, u64 c) {
    u64 d; asm("fma.rn.f32x2 %0, %1, %2, %3;" : "=l"(d) : "l"(a), "l"(b), "l"(c)); return d;
}
__device__ __forceinline__ float lo32(u64 a) { return __uint_as_float((unsigned)a); }
__device__ __forceinline__ float hi32(u64 a) { return __uint_as_float((unsigned)(a >> 32)); }
__device__ __forceinline__ u64 packf2(float lo, float hi) {
    return (u64)__float_as_uint(lo) | ((u64)__float_as_uint(hi) << 32);
}
__device__ __forceinline__ void cp16(unsigned d, const void* s) {
    asm volatile("cp.async.cg.shared.global [%0], [%1], 16;" :: "r"(d), "l"(s));
}
__device__ __forceinline__ void cp_commit() { asm volatile("cp.async.commit_group;"); }
template<int N> __device__ __forceinline__ void cp_wait() {
    asm volatile("cp.async.wait_group %0;" :: "n"(N));
}
__device__ __forceinline__ void red2(float* a, float x, float y) {
    asm volatile("red.global.add.v2.f32 [%0], {%1, %2};" :: "l"(a), "f"(x), "f"(y) : "memory");
}
// pack (v0 -> low16, v1 -> high16) bf16 hi + residual lo
__device__ __forceinline__ void bf16pair(float a, float b, unsigned& hp, unsigned& lp) {
    __nv_bfloat16 ha = __float2bfloat16_rn(a), hb = __float2bfloat16_rn(b);
    __nv_bfloat16 la = __float2bfloat16_rn(a - __bfloat162float(ha));
    __nv_bfloat16 lb = __float2bfloat16_rn(b - __bfloat162float(hb));
    hp = (unsigned)__bfloat16_as_ushort(ha) | ((unsigned)__bfloat16_as_ushort(hb) << 16);
    lp = (unsigned)__bfloat16_as_ushort(la) | ((unsigned)__bfloat16_as_ushort(lb) << 16);
}
// ---- HMMA helpers (sm_80+ PTX; valid at sm_103 target) ----
__device__ __forceinline__ void mma_bf16(float* d, const unsigned* a, const unsigned* b) {
    asm volatile("mma.sync.aligned.m16n8k16.row.col.f32.bf16.bf16.f32 "
        "{%0,%1,%2,%3}, {%4,%5,%6,%7}, {%8,%9}, {%0,%1,%2,%3};"
        : "+f"(d[0]), "+f"(d[1]), "+f"(d[2]), "+f"(d[3])
        : "r"(a[0]), "r"(a[1]), "r"(a[2]), "r"(a[3]), "r"(b[0]), "r"(b[1]));
}
__device__ __forceinline__ void ldsm4(unsigned* r, unsigned addr) {
    asm volatile("ldmatrix.sync.aligned.m8n8.x4.shared.b16 {%0,%1,%2,%3}, [%4];"
        : "=r"(r[0]), "=r"(r[1]), "=r"(r[2]), "=r"(r[3]) : "r"(addr));
}
__device__ __forceinline__ void ldsm2(unsigned* r, unsigned addr) {
    asm volatile("ldmatrix.sync.aligned.m8n8.x2.shared.b16 {%0,%1}, [%2];"
        : "=r"(r[0]), "=r"(r[1]) : "r"(addr));
}

// ---------------- small kernels ----------------
__global__ void detect_mask_kernel(const unsigned int* __restrict__ m) {
    if (threadIdx.x < 2) { g_ne_c[threadIdx.x] = 0; g_nn_c[threadIdx.x] = 0; }
    int bad = 0;
    for (int i = threadIdx.x; i < N_NODES / 4; i += blockDim.x)
        if (m[i] > 1u) bad = 1;
    bad = __syncthreads_or(bad);
    if (threadIdx.x == 0) g_mask_u8 = bad;
}

__global__ void __launch_bounds__(256)
compact_kernel(const int* __restrict__ edges, const void* __restrict__ mask, int li) {
    int e = blockIdx.x * 256 + threadIdx.x, lane = threadIdx.x & 31;
    int mu8 = g_mask_u8;
    bool valid = false; int rv = 0, cv = 0;
    if (e < N_EDGES) {
        rv = edges[e]; cv = edges[e + N_EDGES];
        valid = mu8 ? (((const unsigned char*)mask)[rv] != 0)
                    : (((const int*)mask)[rv] != 0);
    }
    unsigned bal = __ballot_sync(0xffffffffu, valid);
    int base = 0;
    if (lane == 0 && bal) base = atomicAdd(&g_ne_c[li], __popc(bal));
    base = __shfl_sync(0xffffffffu, base, 0);
    if (valid) {
        int p = base + __popc(bal & ((1u << lane) - 1u));
        g_rows_c[li][p] = rv; g_cols_c[li][p] = cv;
    }
}

__global__ void __launch_bounds__(256)
compact_nodes_kernel(const void* __restrict__ mask, int li) {
    int n = blockIdx.x * 256 + threadIdx.x, lane = threadIdx.x & 31;
    int mu8 = g_mask_u8;
    bool valid = false;
    if (n < N_NODES)
        valid = mu8 ? (((const unsigned char*)mask)[n] != 0)
                    : (((const int*)mask)[n] != 0);
    unsigned bal = __ballot_sync(0xffffffffu, valid);
    int base = 0;
    if (lane == 0 && bal) base = atomicAdd(&g_nn_c[li], __popc(bal));
    base = __shfl_sync(0xffffffffu, base, 0);
    if (valid)
        g_nodes_c[li][base + __popc(bal & ((1u << lane) - 1u))] = n;
}

// ---------------- input embedding (FFMA2) + bf16 mirrors + agg zero ----------------
__global__ void __launch_bounds__(512, 1)
embed_in_kernel(const float* __restrict__ h_in, const float* __restrict__ W,
                const float* __restrict__ b) {
    extern __shared__ char smraw[];
    u64* Wp = (u64*)smraw;
    float* bs = (float*)(Wp + 4096);
    float* xAll = bs + 128;
    int tid = threadIdx.x;
    for (int i = tid; i < 4096; i += 512) {
        int kk = i >> 7, c = i & 127;
        Wp[i] = packf2(W[(2 * kk) * 128 + c], W[(2 * kk + 1) * 128 + c]);
    }
    if (tid < 128) bs[tid] = b[tid];
    __syncthreads();
    int wid = tid >> 5, lane = tid & 31;
    float* xS = xAll + wid * 288;
    int c0 = 2 * lane, c1 = 64 + 2 * lane;
    float bb[4] = {bs[c0], bs[c0 + 1], bs[c1], bs[c1 + 1]};
    for (int t = blockIdx.x * 16 + wid; t < N_NODES / 4; t += gridDim.x * 16) {
        int r0 = 4 * t;
        for (int i = lane; i < 64; i += 32) {
            int rr = i >> 4, v = i & 15;
            *(float4*)(xS + rr * 72 + 4 * v) =
                *(const float4*)(h_in + (r0 + rr) * 64 + 4 * v);
        }
        for (int i = lane; i < 64; i += 32)
            *(float4*)(g_agg + (size_t)r0 * 64 + 4 * i) = make_float4(0.f, 0.f, 0.f, 0.f);
        __syncwarp();
        u64 acc[16];
#pragma unroll
        for (int j = 0; j < 16; j++) acc[j] = 0ull;
#pragma unroll 4
        for (int kk = 0; kk < 32; kk++) {
            const u64* wr = Wp + kk * 128;
            ulonglong2 wA = *(const ulonglong2*)(wr + c0);
            ulonglong2 wB = *(const ulonglong2*)(wr + c1);
#pragma unroll
            for (int j = 0; j < 4; j++) {
                u64 f = *(const u64*)(xS + j * 72 + 2 * kk);
                acc[4*j]   = ffma2(f, wA.x, acc[4*j]);
                acc[4*j+1] = ffma2(f, wA.y, acc[4*j+1]);
                acc[4*j+2] = ffma2(f, wB.x, acc[4*j+2]);
                acc[4*j+3] = ffma2(f, wB.y, acc[4*j+3]);
            }
        }
#pragma unroll
        for (int j = 0; j < 4; j++) {
            float2 oA, oB;
            oA.x = lo32(acc[4*j])   + hi32(acc[4*j])   + bb[0];
            oA.y = lo32(acc[4*j+1]) + hi32(acc[4*j+1]) + bb[1];
            oB.x = lo32(acc[4*j+2]) + hi32(acc[4*j+2]) + bb[2];
            oB.y = lo32(acc[4*j+3]) + hi32(acc[4*j+3]) + bb[3];
            size_t rb = (size_t)(r0 + j) * 128;
            *(float2*)(g_h + rb + c0) = oA;
            *(float2*)(g_h + rb + c1) = oB;
            unsigned hp, lp;
            bf16pair(oA.x, oA.y, hp, lp);
            *(unsigned*)((unsigned short*)g_hh + rb + c0) = hp;
            *(unsigned*)((unsigned short*)g_hl + rb + c0) = lp;
            bf16pair(oB.x, oB.y, hp, lp);
            *(unsigned*)((unsigned short*)g_hh + rb + c1) = hp;
            *(unsigned*)((unsigned short*)g_hl + rb + c1) = lp;
        }
        __syncwarp();
    }
}
#define EMBI_SMEM (4096 * 8 + 128 * 4 + 16 * 288 * 4)

// ---------------- output embedding (FFMA2) ----------------
__global__ void __launch_bounds__(512, 1)
embed_out_kernel(const float* __restrict__ W, const float* __restrict__ b,
                 float* __restrict__ out) {
    extern __shared__ char smraw[];
    u64* Wp = (u64*)smraw;
    float* bs = (float*)(Wp + 4096);
    float* xAll = bs + 64;
    int tid = threadIdx.x;
    for (int i = tid; i < 4096; i += 512) {
        int kk = i >> 6, c = i & 63;
        Wp[i] = packf2(W[(2 * kk) * 64 + c], W[(2 * kk + 1) * 64 + c]);
    }
    if (tid < 64) bs[tid] = b[tid];
    __syncthreads();
    int wid = tid >> 5, lane = tid & 31;
    float* xS = xAll + wid * 1088;
    int c0 = 2 * lane;
    float bb0 = bs[c0], bb1 = bs[c0 + 1];
    for (int t = blockIdx.x * 16 + wid; t < N_NODES / 8; t += gridDim.x * 16) {
        int r0 = 8 * t;
        for (int i = lane; i < 256; i += 32) {
            int rr = i >> 5, v = i & 31;
            *(float4*)(xS + rr * 136 + 4 * v) =
                *(const float4*)(g_h + (size_t)(r0 + rr) * 128 + 4 * v);
        }
        __syncwarp();
        u64 acc[16];
#pragma unroll
        for (int j = 0; j < 16; j++) acc[j] = 0ull;
#pragma unroll 4
        for (int kk = 0; kk < 64; kk++) {
            ulonglong2 w = *(const ulonglong2*)(Wp + kk * 64 + c0);
#pragma unroll
            for (int j = 0; j < 8; j++) {
                u64 f = *(const u64*)(xS + j * 136 + 2 * kk);
                acc[2*j]   = ffma2(f, w.x, acc[2*j]);
                acc[2*j+1] = ffma2(f, w.y, acc[2*j+1]);
            }
        }
#pragma unroll
        for (int j = 0; j < 8; j++) {
            float2 o;
            o.x = lo32(acc[2*j])   + hi32(acc[2*j])   + bb0;
            o.y = lo32(acc[2*j+1]) + hi32(acc[2*j+1]) + bb1;
            *(float2*)(out + (size_t)(r0 + j) * 64 + c0) = o;
        }
        __syncwarp();
    }
}
#define EMBO_SMEM (4096 * 8 + 64 * 4 + 16 * 1088 * 4)

// ================= HMMA edge kernel =================
// CTA: 256 thr / 8 warps / 128-edge tile; warp = 16 edges x 64 cols.
// smem byte offsets:
#define SO_BIAS1 0
#define SO_BIAS2 256
#define SO_IDX   512         // int[2][256]
#define SO_W1H   2560        // [64 n][256 k] bf16, row stride 528
#define SO_W1L   36352
#define SO_W2H   70144       // [64 n][64 k]  bf16, row stride 144
#define SO_W2L   79360
#define SO_AH    88576       // feat rows-half hi: [128 e][128 k] stride 272
#define SO_AL    123392
#define SO_BH    158208      // feat cols-half
#define SO_BL    193024
#define EDGE_SMEM_BYTES 227840

__device__ __forceinline__ void gatherCTA(unsigned dstH, unsigned dstL,
                                          const int* idxh) {
    int tid = threadIdx.x;
#pragma unroll
    for (int i = tid; i < 2048; i += 256) {
        int e = i >> 4, c = i & 15;
        size_t src = (size_t)idxh[e] * 128 + c * 8;
        unsigned off = (unsigned)e * 272u + (unsigned)c * 16u;
        cp16(dstH + off, g_hh + src);
        cp16(dstL + off, g_hl + src);
    }
}

__global__ void __launch_bounds__(256, 1)
edge_kernel(int li, const float* __restrict__ W1, const float* __restrict__ b1,
            const float* __restrict__ W2, const float* __restrict__ b2, float C) {
    extern __shared__ char sm[];
    unsigned smb = (unsigned)__cvta_generic_to_shared(sm);
    int tid = threadIdx.x, wid = tid >> 5, lane = tid & 31;

    // weights -> smem as W^T [n][k], split bf16
    for (int i = tid; i < 256 * 64; i += 256) {
        int k = i >> 6, n = i & 63;
        float f = W1[i];
        __nv_bfloat16 hb = __float2bfloat16_rn(f);
        unsigned off = (unsigned)n * 528u + (unsigned)k * 2u;
        *(unsigned short*)(sm + SO_W1H + off) = __bfloat16_as_ushort(hb);
        *(unsigned short*)(sm + SO_W1L + off) =
            __bfloat16_as_ushort(__float2bfloat16_rn(f - __bfloat162float(hb)));
    }
    for (int i = tid; i < 64 * 64; i += 256) {
        int k = i >> 6, n = i & 63;
        float f = W2[i];
        __nv_bfloat16 hb = __float2bfloat16_rn(f);
        unsigned off = (unsigned)n * 144u + (unsigned)k * 2u;
        *(unsigned short*)(sm + SO_W2H + off) = __bfloat16_as_ushort(hb);
        *(unsigned short*)(sm + SO_W2L + off) =
            __bfloat16_as_ushort(__float2bfloat16_rn(f - __bfloat162float(hb)));
    }
    if (tid < 64) {
        ((float*)(sm + SO_BIAS1))[tid] = b1[tid];
        ((float*)(sm + SO_BIAS2))[tid] = b2[tid];
    }

    const float* b1s = (const float*)(sm + SO_BIAS1);
    const float* b2s = (const float*)(sm + SO_BIAS2);
    int* idxAll = (int*)(sm + SO_IDX);

    int nE = g_ne_c[li];
    if (nE <= 0) return;
    const int* rows = g_rows_c[li];
    const int* cols = g_cols_c[li];
    int ntiles = (nE + 127) >> 7;

    // per-lane ldmatrix offsets
    unsigned e0 = (unsigned)wid * 16u;
    unsigned aoff = (e0 + (unsigned)(lane & 15)) * 272u + (unsigned)((lane >> 4) << 3) * 2u;
    unsigned boff1 = (unsigned)(lane & 7) * 528u + (unsigned)(((lane >> 3) & 1) << 3) * 2u;
    unsigned boff2 = (unsigned)(lane & 7) * 144u + (unsigned)(((lane >> 3) & 1) << 3) * 2u;
    unsigned AH = smb + SO_AH, AL = smb + SO_AL;
    unsigned BH = smb + SO_BH, BL = smb + SO_BL;
    unsigned W1Hs = smb + SO_W1H + boff1, W1Ls = smb + SO_W1L + boff1;
    unsigned W2Hs = smb + SO_W2H + boff2, W2Ls = smb + SO_W2L + boff2;
    int g = lane >> 2, q = lane & 3;

    int t = blockIdx.x, cur = 0;
    if (t < ntiles) {
        int e = t * 128 + (tid & 127);
        if (e >= nE) e = nE - 1;
        idxAll[tid] = (tid < 128) ? rows[e] : cols[e];
    }
    __syncthreads();
    if (t < ntiles) gatherCTA(AH, AL, idxAll);
    cp_commit();

    for (; t < ntiles; t += gridDim.x) {
        int* idx = idxAll + cur * 256;
        gatherCTA(BH, BL, idx + 128);       // cols half of current tile
        cp_commit();
        cp_wait<1>(); __syncthreads();      // rows half ready

        float acc[32];
#pragma unroll
        for (int j = 0; j < 32; j++) acc[j] = 0.f;

        // ---- layer1 pass1: k 0..127 (rows features) ----
#pragma unroll
        for (int s = 0; s < 8; s++) {
            unsigned k2 = (unsigned)(16 * s) * 2u;
            unsigned ah[4], al[4];
            ldsm4(ah, AH + aoff + k2);
            ldsm4(al, AL + aoff + k2);
#pragma unroll
            for (int n = 0; n < 8; n++) {
                unsigned bh[2], bl[2];
                ldsm2(bh, W1Hs + (unsigned)n * 4224u + k2);
                ldsm2(bl, W1Ls + (unsigned)n * 4224u + k2);
                float* d = acc + n * 4;
                mma_bf16(d, ah, bh);
                mma_bf16(d, ah, bl);
                mma_bf16(d, al, bh);
            }
        }
        // store next-tile idx, free rows buffer
        int tn = t + gridDim.x;
        int* idxn = idxAll + (cur ^ 1) * 256;
        if (tn < ntiles) {
            int e = tn * 128 + (tid & 127);
            if (e >= nE) e = nE - 1;
            idxn[tid] = (tid < 128) ? rows[e] : cols[e];
        }
        __syncthreads();                    // pass1 done + idxn visible
        if (tn < ntiles) gatherCTA(AH, AL, idxn);
        cp_commit();
        cp_wait<1>(); __syncthreads();      // cols half ready

        // ---- layer1 pass2: k 128..255 (cols features) ----
#pragma unroll
        for (int s = 0; s < 8; s++) {
            unsigned k2 = (unsigned)(16 * s) * 2u;
            unsigned kw2 = (unsigned)(128 + 16 * s) * 2u;
            unsigned ah[4], al[4];
            ldsm4(ah, BH + aoff + k2);
            ldsm4(al, BL + aoff + k2);
#pragma unroll
            for (int n = 0; n < 8; n++) {
                unsigned bh[2], bl[2];
                ldsm2(bh, W1Hs + (unsigned)n * 4224u + kw2);
                ldsm2(bl, W1Ls + (unsigned)n * 4224u + kw2);
                float* d = acc + n * 4;
                mma_bf16(d, ah, bh);
                mma_bf16(d, ah, bl);
                mma_bf16(d, al, bh);
            }
        }

        // ---- repack: m = silu(acc + b1) -> split-bf16 A fragments (registers) ----
        unsigned mh01[8], ml01[8], mh23[8], ml23[8];
#pragma unroll
        for (int n = 0; n < 8; n++) {
            float bq0 = b1s[8 * n + 2 * q], bq1 = b1s[8 * n + 2 * q + 1];
            float v0 = silu(acc[4*n]   + bq0);
            float v1 = silu(acc[4*n+1] + bq1);
            float v2 = silu(acc[4*n+2] + bq0);
            float v3 = silu(acc[4*n+3] + bq1);
            bf16pair(v0, v1, mh01[n], ml01[n]);
            bf16pair(v2, v3, mh23[n], ml23[n]);
        }

        // ---- layer2: 4 k-steps, A from registers ----
        float acc2[32];
#pragma unroll
        for (int j = 0; j < 32; j++) acc2[j] = 0.f;
#pragma unroll
        for (int s2 = 0; s2 < 4; s2++) {
            unsigned k2 = (unsigned)(16 * s2) * 2u;
            unsigned ah[4] = {mh01[2*s2], mh23[2*s2], mh01[2*s2+1], mh23[2*s2+1]};
            unsigned al[4] = {ml01[2*s2], ml23[2*s2], ml01[2*s2+1], ml23[2*s2+1]};
#pragma unroll
            for (int n = 0; n < 8; n++) {
                unsigned bh[2], bl[2];
                ldsm2(bh, W2Hs + (unsigned)n * 1152u + k2);
                ldsm2(bl, W2Ls + (unsigned)n * 1152u + k2);
                float* d = acc2 + n * 4;
                mma_bf16(d, ah, bh);
                mma_bf16(d, ah, bl);
                mma_bf16(d, al, bh);
            }
        }

        // ---- epilogue: scatter silu(acc2 + b2) * C into g_agg ----
        int eA_ = t * 128 + (int)e0 + g;
        int eB_ = eA_ + 8;
        float* pa = g_agg + (size_t)idx[e0 + g] * 64;
        float* pb = g_agg + (size_t)idx[e0 + 8 + g] * 64;
        bool vA = eA_ < nE, vB = eB_ < nE;
#pragma unroll
        for (int n = 0; n < 8; n++) {
            int col = 8 * n + 2 * q;
            float bq0 = b2s[col], bq1 = b2s[col + 1];
            if (vA) red2(pa + col, silu(acc2[4*n]   + bq0) * C,
                                   silu(acc2[4*n+1] + bq1) * C);
            if (vB) red2(pb + col, silu(acc2[4*n+2] + bq0) * C,
                                   silu(acc2[4*n+3] + bq1) * C);
        }
        __syncthreads();                    // pass2 reads done before next cols gather
        cur ^= 1;
    }
}

// ---------------- node kernel (FFMA2) + bf16 mirror store + agg re-zero ----------------
__global__ void __launch_bounds__(512, 1)
node_kernel(int li, const float* __restrict__ W1, const float* __restrict__ b1,
            const float* __restrict__ W2, const float* __restrict__ b2) {
    extern __shared__ char smraw[];
    u64* Wp1 = (u64*)smraw;
    u64* Wp2 = Wp1 + 12288;
    float* b1s = (float*)(Wp2 + 8192);
    float* b2s = b1s + 128;
    float* xAll = b2s + 128;
    int tid = threadIdx.x;
    for (int i = tid; i < 12288; i += 512) {
        int kk = i >> 7, c = i & 127;
        Wp1[i] = packf2(W1[(2 * kk) * 128 + c], W1[(2 * kk + 1) * 128 + c]);
    }
    for (int i = tid; i < 8192; i += 512) {
        int kk = i >> 7, c = i & 127;
        Wp2[i] = packf2(W2[(2 * kk) * 128 + c], W2[(2 * kk + 1) * 128 + c]);
    }
    if (tid < 128) { b1s[tid] = b1[tid]; b2s[tid] = b2[tid]; }
    __syncthreads();
    int wid = tid >> 5, lane = tid & 31;
    float* xS = xAll + wid * 800;
    int c0 = 2 * lane, c1 = 64 + 2 * lane;
    float bb1[4] = {b1s[c0], b1s[c0+1], b1s[c1], b1s[c1+1]};
    float bb2[4] = {b2s[c0], b2s[c0+1], b2s[c1], b2s[c1+1]};

    int nn = g_nn_c[li];
    const int* list = g_nodes_c[li];
    int ntiles = (nn + 3) >> 2;
    for (int t = blockIdx.x * 16 + wid; t < ntiles; t += gridDim.x * 16) {
        int rid[4]; bool rv[4];
#pragma unroll
        for (int j = 0; j < 4; j++) {
            int p = 4 * t + j;
            rv[j] = p < nn;
            rid[j] = list[rv[j] ? p : (nn - 1)];
        }
#pragma unroll
        for (int j = 0; j < 4; j++)
            for (int v = lane; v < 48; v += 32) {
                float4 val = (v < 32) ? *(const float4*)(g_h + (size_t)rid[j] * 128 + 4 * v)
                                      : *(const float4*)(g_agg + (size_t)rid[j] * 64 + 4 * (v - 32));
                *(float4*)(xS + j * 200 + 4 * v) = val;
            }
        __syncwarp();
        u64 acc[16];
#pragma unroll
        for (int j = 0; j < 16; j++) acc[j] = 0ull;
#pragma unroll 2
        for (int kk = 0; kk < 96; kk++) {
            const u64* wr = Wp1 + kk * 128;
            ulonglong2 wA = *(const ulonglong2*)(wr + c0);
            ulonglong2 wB = *(const ulonglong2*)(wr + c1);
#pragma unroll
            for (int j = 0; j < 4; j++) {
                u64 f = *(const u64*)(xS + j * 200 + 2 * kk);
                acc[4*j]   = ffma2(f, wA.x, acc[4*j]);
                acc[4*j+1] = ffma2(f, wA.y, acc[4*j+1]);
                acc[4*j+2] = ffma2(f, wB.x, acc[4*j+2]);
                acc[4*j+3] = ffma2(f, wB.y, acc[4*j+3]);
            }
        }
        __syncwarp();
        float res[16];
#pragma unroll
        for (int j = 0; j < 4; j++) {
            res[4*j]   = xS[j * 200 + c0];
            res[4*j+1] = xS[j * 200 + c0 + 1];
            res[4*j+2] = xS[j * 200 + c1];
            res[4*j+3] = xS[j * 200 + c1 + 1];
        }
#pragma unroll
        for (int j = 0; j < 4; j++) {
            float2 mA, mB;
            mA.x = silu(lo32(acc[4*j])   + hi32(acc[4*j])   + bb1[0]);
            mA.y = silu(lo32(acc[4*j+1]) + hi32(acc[4*j+1]) + bb1[1]);
            mB.x = silu(lo32(acc[4*j+2]) + hi32(acc[4*j+2]) + bb1[2]);
            mB.y = silu(lo32(acc[4*j+3]) + hi32(acc[4*j+3]) + bb1[3]);
            *(float2*)(xS + j * 200 + c0) = mA;
            *(float2*)(xS + j * 200 + c1) = mB;
        }
        __syncwarp();
#pragma unroll
        for (int j = 0; j < 16; j++) acc[j] = 0ull;
#pragma unroll 2
        for (int kk = 0; kk < 64; kk++) {
            const u64* wr = Wp2 + kk * 128;
            ulonglong2 wA = *(const ulonglong2*)(wr + c0);
            ulonglong2 wB = *(const ulonglong2*)(wr + c1);
#pragma unroll
            for (int j = 0; j < 4; j++) {
                u64 f = *(const u64*)(xS + j * 200 + 2 * kk);
                acc[4*j]   = ffma2(f, wA.x, acc[4*j]);
                acc[4*j+1] = ffma2(f, wA.y, acc[4*j+1]);
                acc[4*j+2] = ffma2(f, wB.x, acc[4*j+2]);
                acc[4*j+3] = ffma2(f, wB.y, acc[4*j+3]);
            }
        }
#pragma unroll
        for (int j = 0; j < 4; j++) {
            if (!rv[j]) continue;
            float2 oA, oB;
            oA.x = res[4*j]   + lo32(acc[4*j])   + hi32(acc[4*j])   + bb2[0];
            oA.y = res[4*j+1] + lo32(acc[4*j+1]) + hi32(acc[4*j+1]) + bb2[1];
            oB.x = res[4*j+2] + lo32(acc[4*j+2]) + hi32(acc[4*j+2]) + bb2[2];
            oB.y = res[4*j+3] + lo32(acc[4*j+3]) + hi32(acc[4*j+3]) + bb2[3];
            size_t rb = (size_t)rid[j] * 128;
            *(float2*)(g_h + rb + c0) = oA;
            *(float2*)(g_h + rb + c1) = oB;
            unsigned hp, lp;
            bf16pair(oA.x, oA.y, hp, lp);
            *(unsigned*)((unsigned short*)g_hh + rb + c0) = hp;
            *(unsigned*)((unsigned short*)g_hl + rb + c0) = lp;
            bf16pair(oB.x, oB.y, hp, lp);
            *(unsigned*)((unsigned short*)g_hh + rb + c1) = hp;
            *(unsigned*)((unsigned short*)g_hl + rb + c1) = lp;
        }
#pragma unroll
        for (int j = 0; j < 4; j++)
            if (rv[j] && lane < 16)
                *(float4*)(g_agg + (size_t)rid[j] * 64 + 4 * lane) =
                    make_float4(0.f, 0.f, 0.f, 0.f);
        __syncwarp();
    }
}
#define NODE_SMEM_BYTES (12288*8 + 8192*8 + 256*4 + 16*800*4)

// ---------------- launch (edge at index 3 for ncu capture) ----------------
extern "C" void kernel_launch(void* const* d_in, const int* in_sizes, int n_in,
                              void* d_out, int out_size) {
    const float* h_in = (const float*)d_in[0];
    const int*   eA   = (const int*)d_in[1];
    const int*   eB   = (const int*)d_in[2];
    const void*  mA   = d_in[3];
    const void*  mB   = d_in[4];
    const float* Wi   = (const float*)d_in[5];
    const float* bi   = (const float*)d_in[6];
    const float* Wo   = (const float*)d_in[7];
    const float* bo   = (const float*)d_in[8];
    const float* ew1  = (const float*)d_in[9];
    const float* eb1  = (const float*)d_in[10];
    const float* ew2  = (const float*)d_in[11];
    const float* eb2  = (const float*)d_in[12];
    const float* nw1  = (const float*)d_in[13];
    const float* nb1  = (const float*)d_in[14];
    const float* nw2  = (const float*)d_in[15];
    const float* nb2  = (const float*)d_in[16];
    float* out = (float*)d_out;

    cudaFuncSetAttribute(edge_kernel, cudaFuncAttributeMaxDynamicSharedMemorySize, EDGE_SMEM_BYTES);
    cudaFuncSetAttribute(node_kernel, cudaFuncAttributeMaxDynamicSharedMemorySize, NODE_SMEM_BYTES);
    cudaFuncSetAttribute(embed_in_kernel, cudaFuncAttributeMaxDynamicSharedMemorySize, EMBI_SMEM);
    cudaFuncSetAttribute(embed_out_kernel, cudaFuncAttributeMaxDynamicSharedMemorySize, EMBO_SMEM);

    detect_mask_kernel<<<1, 256>>>((const unsigned int*)mA);
    compact_kernel<<<3125, 256>>>(eA, mA, 0);
    embed_in_kernel<<<148, 512, EMBI_SMEM>>>(h_in, Wi, bi);
    edge_kernel<<<148, 256, EDGE_SMEM_BYTES>>>(0, ew1, eb1, ew2, eb2, 1.0f);  // ncu slot
    compact_nodes_kernel<<<196, 256>>>(mA, 0);
    node_kernel<<<148, 512, NODE_SMEM_BYTES>>>(0, nw1, nb1, nw2, nb2);
    compact_kernel<<<3125, 256>>>(eB, mB, 1);
    compact_nodes_kernel<<<196, 256>>>(mB, 1);

    for (int i = 1; i < 4; i++) {
        int li = i % 2;
        float C = (li == 0) ? 1.0f : (2.0f / 64.0f);
        edge_kernel<<<148, 256, EDGE_SMEM_BYTES>>>(
            li, ew1 + i * 256 * 64, eb1 + i * 64,
            ew2 + i * 64 * 64, eb2 + i * 64, C);
        node_kernel<<<148, 512, NODE_SMEM_BYTES>>>(
            li, nw1 + i * 192 * 128, nb1 + i * 128,
            nw2 + i * 128 * 128, nb2 + i * 128);
    }

    embed_out_kernel<<<148, 512, EMBO_SMEM>>>(Wo, bo, out);
}

// round 15
// speedup vs baseline: 2.1743x; 1.0972x over previous
#include <cuda_runtime.h>
#include <cuda_bf16.h>

typedef unsigned long long u64;

#define N_NODES 50000
#define N_EDGES 800000
#define HID 128
#define EH 64

// ---------------- scratch ----------------
__device__ float g_h[N_NODES * HID];
__device__ __nv_bfloat16 g_hh[N_NODES * HID];   // bf16 hi mirror of g_h
__device__ __nv_bfloat16 g_hl[N_NODES * HID];   // bf16 lo (residual) mirror
__device__ float g_agg[N_NODES * EH];
__device__ int   g_mask_u8;
__device__ int   g_ne_c[2];
__device__ int   g_rows_c[2][N_EDGES];
__device__ int   g_cols_c[2][N_EDGES];
__device__ int   g_nn_c[2];
__device__ int   g_nodes_c[2][N_NODES];

__device__ __forceinline__ float silu(float x) { return x / (1.0f + __expf(-x)); }
__device__ __forceinline__ u64 ffma2(u64 a, u64 b, u64 c) {
    u64 d; asm("fma.rn.f32x2 %0, %1, %2, %3;" : "=l"(d) : "l"(a), "l"(b), "l"(c)); return d;
}
__device__ __forceinline__ float lo32(u64 a) { return __uint_as_float((unsigned)a); }
__device__ __forceinline__ float hi32(u64 a) { return __uint_as_float((unsigned)(a >> 32)); }
__device__ __forceinline__ u64 packf2(float lo, float hi) {
    return (u64)__float_as_uint(lo) | ((u64)__float_as_uint(hi) << 32);
}
__device__ __forceinline__ void cp16(unsigned d, const void* s) {
    asm volatile("cp.async.cg.shared.global [%0], [%1], 16;" :: "r"(d), "l"(s));
}
__device__ __forceinline__ void cp_commit() { asm volatile("cp.async.commit_group;"); }
template<int N> __device__ __forceinline__ void cp_wait() {
    asm volatile("cp.async.wait_group %0;" :: "n"(N));
}
__device__ __forceinline__ void red2(float* a, float x, float y) {
    asm volatile("red.global.add.v2.f32 [%0], {%1, %2};" :: "l"(a), "f"(x), "f"(y) : "memory");
}
__device__ __forceinline__ void bf16pair(float a, float b, unsigned& hp, unsigned& lp) {
    __nv_bfloat16 ha = __float2bfloat16_rn(a), hb = __float2bfloat16_rn(b);
    __nv_bfloat16 la = __float2bfloat16_rn(a - __bfloat162float(ha));
    __nv_bfloat16 lb = __float2bfloat16_rn(b - __bfloat162float(hb));
    hp = (unsigned)__bfloat16_as_ushort(ha) | ((unsigned)__bfloat16_as_ushort(hb) << 16);
    lp = (unsigned)__bfloat16_as_ushort(la) | ((unsigned)__bfloat16_as_ushort(lb) << 16);
}
// ---- HMMA helpers (sm_80+ PTX) ----
__device__ __forceinline__ void mma_bf16(float* d, const unsigned* a, const unsigned* b) {
    asm volatile("mma.sync.aligned.m16n8k16.row.col.f32.bf16.bf16.f32 "
        "{%0,%1,%2,%3}, {%4,%5,%6,%7}, {%8,%9}, {%0,%1,%2,%3};"
        : "+f"(d[0]), "+f"(d[1]), "+f"(d[2]), "+f"(d[3])
        : "r"(a[0]), "r"(a[1]), "r"(a[2]), "r"(a[3]), "r"(b[0]), "r"(b[1]));
}
__device__ __forceinline__ void ldsm4(unsigned* r, unsigned addr) {
    asm volatile("ldmatrix.sync.aligned.m8n8.x4.shared.b16 {%0,%1,%2,%3}, [%4];"
        : "=r"(r[0]), "=r"(r[1]), "=r"(r[2]), "=r"(r[3]) : "r"(addr));
}
__device__ __forceinline__ void ldsm2(unsigned* r, unsigned addr) {
    asm volatile("ldmatrix.sync.aligned.m8n8.x2.shared.b16 {%0,%1}, [%2];"
        : "=r"(r[0]), "=r"(r[1]) : "r"(addr));
}

// ---------------- small kernels ----------------
__global__ void detect_mask_kernel(const unsigned int* __restrict__ m) {
    if (threadIdx.x < 2) { g_ne_c[threadIdx.x] = 0; g_nn_c[threadIdx.x] = 0; }
    int bad = 0;
    for (int i = threadIdx.x; i < N_NODES / 4; i += blockDim.x)
        if (m[i] > 1u) bad = 1;
    bad = __syncthreads_or(bad);
    if (threadIdx.x == 0) g_mask_u8 = bad;
}

__global__ void __launch_bounds__(256)
compact_kernel(const int* __restrict__ edges, const void* __restrict__ mask, int li) {
    int e = blockIdx.x * 256 + threadIdx.x, lane = threadIdx.x & 31;
    int mu8 = g_mask_u8;
    bool valid = false; int rv = 0, cv = 0;
    if (e < N_EDGES) {
        rv = edges[e]; cv = edges[e + N_EDGES];
        valid = mu8 ? (((const unsigned char*)mask)[rv] != 0)
                    : (((const int*)mask)[rv] != 0);
    }
    unsigned bal = __ballot_sync(0xffffffffu, valid);
    int base = 0;
    if (lane == 0 && bal) base = atomicAdd(&g_ne_c[li], __popc(bal));
    base = __shfl_sync(0xffffffffu, base, 0);
    if (valid) {
        int p = base + __popc(bal & ((1u << lane) - 1u));
        g_rows_c[li][p] = rv; g_cols_c[li][p] = cv;
    }
}

__global__ void __launch_bounds__(256)
compact_nodes_kernel(const void* __restrict__ mask, int li) {
    int n = blockIdx.x * 256 + threadIdx.x, lane = threadIdx.x & 31;
    int mu8 = g_mask_u8;
    bool valid = false;
    if (n < N_NODES)
        valid = mu8 ? (((const unsigned char*)mask)[n] != 0)
                    : (((const int*)mask)[n] != 0);
    unsigned bal = __ballot_sync(0xffffffffu, valid);
    int base = 0;
    if (lane == 0 && bal) base = atomicAdd(&g_nn_c[li], __popc(bal));
    base = __shfl_sync(0xffffffffu, base, 0);
    if (valid)
        g_nodes_c[li][base + __popc(bal & ((1u << lane) - 1u))] = n;
}

// ---------------- input embedding (FFMA2) + bf16 mirrors + agg zero ----------------
__global__ void __launch_bounds__(512, 1)
embed_in_kernel(const float* __restrict__ h_in, const float* __restrict__ W,
                const float* __restrict__ b) {
    extern __shared__ char smraw[];
    u64* Wp = (u64*)smraw;
    float* bs = (float*)(Wp + 4096);
    float* xAll = bs + 128;
    int tid = threadIdx.x;
    for (int i = tid; i < 4096; i += 512) {
        int kk = i >> 7, c = i & 127;
        Wp[i] = packf2(W[(2 * kk) * 128 + c], W[(2 * kk + 1) * 128 + c]);
    }
    if (tid < 128) bs[tid] = b[tid];
    __syncthreads();
    int wid = tid >> 5, lane = tid & 31;
    float* xS = xAll + wid * 288;
    int c0 = 2 * lane, c1 = 64 + 2 * lane;
    float bb[4] = {bs[c0], bs[c0 + 1], bs[c1], bs[c1 + 1]};
    for (int t = blockIdx.x * 16 + wid; t < N_NODES / 4; t += gridDim.x * 16) {
        int r0 = 4 * t;
        for (int i = lane; i < 64; i += 32) {
            int rr = i >> 4, v = i & 15;
            *(float4*)(xS + rr * 72 + 4 * v) =
                *(const float4*)(h_in + (r0 + rr) * 64 + 4 * v);
        }
        for (int i = lane; i < 64; i += 32)
            *(float4*)(g_agg + (size_t)r0 * 64 + 4 * i) = make_float4(0.f, 0.f, 0.f, 0.f);
        __syncwarp();
        u64 acc[16];
#pragma unroll
        for (int j = 0; j < 16; j++) acc[j] = 0ull;
#pragma unroll 4
        for (int kk = 0; kk < 32; kk++) {
            const u64* wr = Wp + kk * 128;
            ulonglong2 wA = *(const ulonglong2*)(wr + c0);
            ulonglong2 wB = *(const ulonglong2*)(wr + c1);
#pragma unroll
            for (int j = 0; j < 4; j++) {
                u64 f = *(const u64*)(xS + j * 72 + 2 * kk);
                acc[4*j]   = ffma2(f, wA.x, acc[4*j]);
                acc[4*j+1] = ffma2(f, wA.y, acc[4*j+1]);
                acc[4*j+2] = ffma2(f, wB.x, acc[4*j+2]);
                acc[4*j+3] = ffma2(f, wB.y, acc[4*j+3]);
            }
        }
#pragma unroll
        for (int j = 0; j < 4; j++) {
            float2 oA, oB;
            oA.x = lo32(acc[4*j])   + hi32(acc[4*j])   + bb[0];
            oA.y = lo32(acc[4*j+1]) + hi32(acc[4*j+1]) + bb[1];
            oB.x = lo32(acc[4*j+2]) + hi32(acc[4*j+2]) + bb[2];
            oB.y = lo32(acc[4*j+3]) + hi32(acc[4*j+3]) + bb[3];
            size_t rb = (size_t)(r0 + j) * 128;
            *(float2*)(g_h + rb + c0) = oA;
            *(float2*)(g_h + rb + c1) = oB;
            unsigned hp, lp;
            bf16pair(oA.x, oA.y, hp, lp);
            *(unsigned*)((unsigned short*)g_hh + rb + c0) = hp;
            *(unsigned*)((unsigned short*)g_hl + rb + c0) = lp;
            bf16pair(oB.x, oB.y, hp, lp);
            *(unsigned*)((unsigned short*)g_hh + rb + c1) = hp;
            *(unsigned*)((unsigned short*)g_hl + rb + c1) = lp;
        }
        __syncwarp();
    }
}
#define EMBI_SMEM (4096 * 8 + 128 * 4 + 16 * 288 * 4)

// ---------------- output embedding (FFMA2) ----------------
__global__ void __launch_bounds__(512, 1)
embed_out_kernel(const float* __restrict__ W, const float* __restrict__ b,
                 float* __restrict__ out) {
    extern __shared__ char smraw[];
    u64* Wp = (u64*)smraw;
    float* bs = (float*)(Wp + 4096);
    float* xAll = bs + 64;
    int tid = threadIdx.x;
    for (int i = tid; i < 4096; i += 512) {
        int kk = i >> 6, c = i & 63;
        Wp[i] = packf2(W[(2 * kk) * 64 + c], W[(2 * kk + 1) * 64 + c]);
    }
    if (tid < 64) bs[tid] = b[tid];
    __syncthreads();
    int wid = tid >> 5, lane = tid & 31;
    float* xS = xAll + wid * 1088;
    int c0 = 2 * lane;
    float bb0 = bs[c0], bb1 = bs[c0 + 1];
    for (int t = blockIdx.x * 16 + wid; t < N_NODES / 8; t += gridDim.x * 16) {
        int r0 = 8 * t;
        for (int i = lane; i < 256; i += 32) {
            int rr = i >> 5, v = i & 31;
            *(float4*)(xS + rr * 136 + 4 * v) =
                *(const float4*)(g_h + (size_t)(r0 + rr) * 128 + 4 * v);
        }
        __syncwarp();
        u64 acc[16];
#pragma unroll
        for (int j = 0; j < 16; j++) acc[j] = 0ull;
#pragma unroll 4
        for (int kk = 0; kk < 64; kk++) {
            ulonglong2 w = *(const ulonglong2*)(Wp + kk * 64 + c0);
#pragma unroll
            for (int j = 0; j < 8; j++) {
                u64 f = *(const u64*)(xS + j * 136 + 2 * kk);
                acc[2*j]   = ffma2(f, w.x, acc[2*j]);
                acc[2*j+1] = ffma2(f, w.y, acc[2*j+1]);
            }
        }
#pragma unroll
        for (int j = 0; j < 8; j++) {
            float2 o;
            o.x = lo32(acc[2*j])   + hi32(acc[2*j])   + bb0;
            o.y = lo32(acc[2*j+1]) + hi32(acc[2*j+1]) + bb1;
            *(float2*)(out + (size_t)(r0 + j) * 64 + c0) = o;
        }
        __syncwarp();
    }
}
#define EMBO_SMEM (4096 * 8 + 64 * 4 + 16 * 1088 * 4)

// ================= HMMA edge kernel (16 warps, N-split) =================
// CTA: 512 thr / 16 warps / 128-edge tile.
// Warp (eg = wid&7, nh = wid>>3): 16 edges (eg*16..) x 32 cols (nh*32..).
#define SO_BIAS1 0
#define SO_BIAS2 256
#define SO_IDX   512         // int[2][256]
#define SO_W1H   2560        // [64 n][256 k] bf16, row stride 528
#define SO_W1L   36352
#define SO_W2H   70144       // [64 n][64 k]  bf16, row stride 144
#define SO_W2L   79360
#define SO_AH    88576       // feat rows-half hi: [128 e][128 k] stride 272
#define SO_AL    123392
#define SO_BH    158208      // feat cols-half (reused as m hi, stride 144)
#define SO_BL    193024      // feat cols-half lo (reused as m lo)
#define EDGE_SMEM_BYTES 227840

__device__ __forceinline__ void gatherCTA(unsigned dstH, unsigned dstL,
                                          const int* idxh) {
    int tid = threadIdx.x;
#pragma unroll
    for (int i = tid; i < 2048; i += 512) {
        int e = i >> 4, c = i & 15;
        size_t src = (size_t)idxh[e] * 128 + c * 8;
        unsigned off = (unsigned)e * 272u + (unsigned)c * 16u;
        cp16(dstH + off, g_hh + src);
        cp16(dstL + off, g_hl + src);
    }
}

__global__ void __launch_bounds__(512, 1)
edge_kernel(int li, const float* __restrict__ W1, const float* __restrict__ b1,
            const float* __restrict__ W2, const float* __restrict__ b2, float C) {
    extern __shared__ char sm[];
    unsigned smb = (unsigned)__cvta_generic_to_shared(sm);
    int tid = threadIdx.x, wid = tid >> 5, lane = tid & 31;

    // weights -> smem as W^T [n][k], split bf16
    for (int i = tid; i < 256 * 64; i += 512) {
        int k = i >> 6, n = i & 63;
        float f = W1[i];
        __nv_bfloat16 hb = __float2bfloat16_rn(f);
        unsigned off = (unsigned)n * 528u + (unsigned)k * 2u;
        *(unsigned short*)(sm + SO_W1H + off) = __bfloat16_as_ushort(hb);
        *(unsigned short*)(sm + SO_W1L + off) =
            __bfloat16_as_ushort(__float2bfloat16_rn(f - __bfloat162float(hb)));
    }
    for (int i = tid; i < 64 * 64; i += 512) {
        int k = i >> 6, n = i & 63;
        float f = W2[i];
        __nv_bfloat16 hb = __float2bfloat16_rn(f);
        unsigned off = (unsigned)n * 144u + (unsigned)k * 2u;
        *(unsigned short*)(sm + SO_W2H + off) = __bfloat16_as_ushort(hb);
        *(unsigned short*)(sm + SO_W2L + off) =
            __bfloat16_as_ushort(__float2bfloat16_rn(f - __bfloat162float(hb)));
    }
    if (tid < 64) {
        ((float*)(sm + SO_BIAS1))[tid] = b1[tid];
        ((float*)(sm + SO_BIAS2))[tid] = b2[tid];
    }

    const float* b1s = (const float*)(sm + SO_BIAS1);
    const float* b2s = (const float*)(sm + SO_BIAS2);
    int* idxAll = (int*)(sm + SO_IDX);

    int nE = g_ne_c[li];
    if (nE <= 0) return;
    const int* rows = g_rows_c[li];
    const int* cols = g_cols_c[li];
    int ntiles = (nE + 127) >> 7;

    int eg = wid & 7, nh = wid >> 3;
    unsigned e0 = (unsigned)eg * 16u;
    unsigned aoff = (e0 + (unsigned)(lane & 15)) * 272u + (unsigned)((lane >> 4) << 3) * 2u;
    unsigned moff = (e0 + (unsigned)(lane & 15)) * 144u + (unsigned)((lane >> 4) << 3) * 2u;
    unsigned boff1 = (unsigned)(lane & 7) * 528u + (unsigned)(((lane >> 3) & 1) << 3) * 2u;
    unsigned boff2 = (unsigned)(lane & 7) * 144u + (unsigned)(((lane >> 3) & 1) << 3) * 2u;
    unsigned AH = smb + SO_AH, AL = smb + SO_AL;
    unsigned BH = smb + SO_BH, BL = smb + SO_BL;
    unsigned W1Hs = smb + SO_W1H + boff1 + (unsigned)nh * 4u * 4224u;
    unsigned W1Ls = smb + SO_W1L + boff1 + (unsigned)nh * 4u * 4224u;
    unsigned W2Hs = smb + SO_W2H + boff2 + (unsigned)nh * 4u * 1152u;
    unsigned W2Ls = smb + SO_W2L + boff2 + (unsigned)nh * 4u * 1152u;
    int g = lane >> 2, q = lane & 3;

    int t = blockIdx.x, cur = 0;
    if (t < ntiles && tid < 256) {
        int e = t * 128 + (tid & 127);
        if (e >= nE) e = nE - 1;
        idxAll[tid] = (tid < 128) ? rows[e] : cols[e];
    }
    __syncthreads();
    if (t < ntiles) gatherCTA(AH, AL, idxAll);
    cp_commit();

    for (; t < ntiles; t += gridDim.x) {
        int* idx = idxAll + cur * 256;
        gatherCTA(BH, BL, idx + 128);       // cols half of current tile
        cp_commit();
        cp_wait<1>(); __syncthreads();      // rows half ready

        float acc[16];
#pragma unroll
        for (int j = 0; j < 16; j++) acc[j] = 0.f;

        // ---- layer1 pass1: k 0..127 (rows features) ----
#pragma unroll
        for (int s = 0; s < 8; s++) {
            unsigned k2 = (unsigned)s * 32u;
            unsigned ah[4], al[4];
            ldsm4(ah, AH + aoff + k2);
            ldsm4(al, AL + aoff + k2);
#pragma unroll
            for (int n = 0; n < 4; n++) {
                unsigned bh[2], bl[2];
                ldsm2(bh, W1Hs + (unsigned)n * 4224u + k2);
                ldsm2(bl, W1Ls + (unsigned)n * 4224u + k2);
                float* d = acc + n * 4;
                mma_bf16(d, ah, bh);
                mma_bf16(d, ah, bl);
                mma_bf16(d, al, bh);
            }
        }
        // next-tile idx + rows gather (rows buffer free after pass1)
        int tn = t + gridDim.x;
        int* idxn = idxAll + (cur ^ 1) * 256;
        if (tn < ntiles && tid < 256) {
            int e = tn * 128 + (tid & 127);
            if (e >= nE) e = nE - 1;
            idxn[tid] = (tid < 128) ? rows[e] : cols[e];
        }
        __syncthreads();                    // pass1 done CTA-wide + idxn visible
        if (tn < ntiles) gatherCTA(AH, AL, idxn);
        cp_commit();
        cp_wait<1>(); __syncthreads();      // cols half ready

        // ---- layer1 pass2: k 128..255 (cols features) ----
#pragma unroll
        for (int s = 0; s < 8; s++) {
            unsigned k2 = (unsigned)s * 32u;
            unsigned kw2 = 256u + k2;
            unsigned ah[4], al[4];
            ldsm4(ah, BH + aoff + k2);
            ldsm4(al, BL + aoff + k2);
#pragma unroll
            for (int n = 0; n < 4; n++) {
                unsigned bh[2], bl[2];
                ldsm2(bh, W1Hs + (unsigned)n * 4224u + kw2);
                ldsm2(bl, W1Ls + (unsigned)n * 4224u + kw2);
                float* d = acc + n * 4;
                mma_bf16(d, ah, bh);
                mma_bf16(d, ah, bl);
                mma_bf16(d, al, bh);
            }
        }
        __syncthreads();                    // pass2 done before m overwrites BH/BL

        // ---- m = silu(acc + b1) -> split bf16, staged in BH/BL (stride 144) ----
#pragma unroll
        for (int n = 0; n < 4; n++) {
            int col = nh * 32 + 8 * n + 2 * q;
            float bq0 = b1s[col], bq1 = b1s[col + 1];
            float v0 = silu(acc[4*n]   + bq0);
            float v1 = silu(acc[4*n+1] + bq1);
            float v2 = silu(acc[4*n+2] + bq0);
            float v3 = silu(acc[4*n+3] + bq1);
            unsigned hp, lp;
            bf16pair(v0, v1, hp, lp);
            *(unsigned*)(sm + SO_BH + (e0 + g) * 144u + col * 2) = hp;
            *(unsigned*)(sm + SO_BL + (e0 + g) * 144u + col * 2) = lp;
            bf16pair(v2, v3, hp, lp);
            *(unsigned*)(sm + SO_BH + (e0 + g + 8) * 144u + col * 2) = hp;
            *(unsigned*)(sm + SO_BL + (e0 + g + 8) * 144u + col * 2) = lp;
        }
        __syncthreads();                    // m visible to both warps of the pair

        // ---- layer2: A = m (ldmatrix from staged buffer) ----
        float acc2[16];
#pragma unroll
        for (int j = 0; j < 16; j++) acc2[j] = 0.f;
#pragma unroll
        for (int s2 = 0; s2 < 4; s2++) {
            unsigned k2 = (unsigned)s2 * 32u;
            unsigned ah[4], al[4];
            ldsm4(ah, BH + moff + k2);
            ldsm4(al, BL + moff + k2);
#pragma unroll
            for (int n = 0; n < 4; n++) {
                unsigned bh[2], bl[2];
                ldsm2(bh, W2Hs + (unsigned)n * 1152u + k2);
                ldsm2(bl, W2Ls + (unsigned)n * 1152u + k2);
                float* d = acc2 + n * 4;
                mma_bf16(d, ah, bh);
                mma_bf16(d, ah, bl);
                mma_bf16(d, al, bh);
            }
        }

        // ---- epilogue: scatter silu(acc2 + b2) * C ----
        int eA_ = t * 128 + (int)e0 + g;
        int eB_ = eA_ + 8;
        float* pa = g_agg + (size_t)idx[e0 + g] * 64;
        float* pb = g_agg + (size_t)idx[e0 + 8 + g] * 64;
        bool vA = eA_ < nE, vB = eB_ < nE;
#pragma unroll
        for (int n = 0; n < 4; n++) {
            int col = nh * 32 + 8 * n + 2 * q;
            float bq0 = b2s[col], bq1 = b2s[col + 1];
            if (vA) red2(pa + col, silu(acc2[4*n]   + bq0) * C,
                                   silu(acc2[4*n+1] + bq1) * C);
            if (vB) red2(pb + col, silu(acc2[4*n+2] + bq0) * C,
                                   silu(acc2[4*n+3] + bq1) * C);
        }
        __syncthreads();                    // layer2 reads done before next cols gather
        cur ^= 1;
    }
}

// ---------------- node kernel (FFMA2) + bf16 mirror store + agg re-zero ----------------
__global__ void __launch_bounds__(512, 1)
node_kernel(int li, const float* __restrict__ W1, const float* __restrict__ b1,
            const float* __restrict__ W2, const float* __restrict__ b2) {
    extern __shared__ char smraw[];
    u64* Wp1 = (u64*)smraw;
    u64* Wp2 = Wp1 + 12288;
    float* b1s = (float*)(Wp2 + 8192);
    float* b2s = b1s + 128;
    float* xAll = b2s + 128;
    int tid = threadIdx.x;
    for (int i = tid; i < 12288; i += 512) {
        int kk = i >> 7, c = i & 127;
        Wp1[i] = packf2(W1[(2 * kk) * 128 + c], W1[(2 * kk + 1) * 128 + c]);
    }
    for (int i = tid; i < 8192; i += 512) {
        int kk = i >> 7, c = i & 127;
        Wp2[i] = packf2(W2[(2 * kk) * 128 + c], W2[(2 * kk + 1) * 128 + c]);
    }
    if (tid < 128) { b1s[tid] = b1[tid]; b2s[tid] = b2[tid]; }
    __syncthreads();
    int wid = tid >> 5, lane = tid & 31;
    float* xS = xAll + wid * 800;
    int c0 = 2 * lane, c1 = 64 + 2 * lane;
    float bb1[4] = {b1s[c0], b1s[c0+1], b1s[c1], b1s[c1+1]};
    float bb2[4] = {b2s[c0], b2s[c0+1], b2s[c1], b2s[c1+1]};

    int nn = g_nn_c[li];
    const int* list = g_nodes_c[li];
    int ntiles = (nn + 3) >> 2;
    for (int t = blockIdx.x * 16 + wid; t < ntiles; t += gridDim.x * 16) {
        int rid[4]; bool rv[4];
#pragma unroll
        for (int j = 0; j < 4; j++) {
            int p = 4 * t + j;
            rv[j] = p < nn;
            rid[j] = list[rv[j] ? p : (nn - 1)];
        }
#pragma unroll
        for (int j = 0; j < 4; j++)
            for (int v = lane; v < 48; v += 32) {
                float4 val = (v < 32) ? *(const float4*)(g_h + (size_t)rid[j] * 128 + 4 * v)
                                      : *(const float4*)(g_agg + (size_t)rid[j] * 64 + 4 * (v - 32));
                *(float4*)(xS + j * 200 + 4 * v) = val;
            }
        __syncwarp();
        u64 acc[16];
#pragma unroll
        for (int j = 0; j < 16; j++) acc[j] = 0ull;
#pragma unroll 2
        for (int kk = 0; kk < 96; kk++) {
            const u64* wr = Wp1 + kk * 128;
            ulonglong2 wA = *(const ulonglong2*)(wr + c0);
            ulonglong2 wB = *(const ulonglong2*)(wr + c1);
#pragma unroll
            for (int j = 0; j < 4; j++) {
                u64 f = *(const u64*)(xS + j * 200 + 2 * kk);
                acc[4*j]   = ffma2(f, wA.x, acc[4*j]);
                acc[4*j+1] = ffma2(f, wA.y, acc[4*j+1]);
                acc[4*j+2] = ffma2(f, wB.x, acc[4*j+2]);
                acc[4*j+3] = ffma2(f, wB.y, acc[4*j+3]);
            }
        }
        __syncwarp();
        float res[16];
#pragma unroll
        for (int j = 0; j < 4; j++) {
            res[4*j]   = xS[j * 200 + c0];
            res[4*j+1] = xS[j * 200 + c0 + 1];
            res[4*j+2] = xS[j * 200 + c1];
            res[4*j+3] = xS[j * 200 + c1 + 1];
        }
#pragma unroll
        for (int j = 0; j < 4; j++) {
            float2 mA, mB;
            mA.x = silu(lo32(acc[4*j])   + hi32(acc[4*j])   + bb1[0]);
            mA.y = silu(lo32(acc[4*j+1]) + hi32(acc[4*j+1]) + bb1[1]);
            mB.x = silu(lo32(acc[4*j+2]) + hi32(acc[4*j+2]) + bb1[2]);
            mB.y = silu(lo32(acc[4*j+3]) + hi32(acc[4*j+3]) + bb1[3]);
            *(float2*)(xS + j * 200 + c0) = mA;
            *(float2*)(xS + j * 200 + c1) = mB;
        }
        __syncwarp();
#pragma unroll
        for (int j = 0; j < 16; j++) acc[j] = 0ull;
#pragma unroll 2
        for (int kk = 0; kk < 64; kk++) {
            const u64* wr = Wp2 + kk * 128;
            ulonglong2 wA = *(const ulonglong2*)(wr + c0);
            ulonglong2 wB = *(const ulonglong2*)(wr + c1);
#pragma unroll
            for (int j = 0; j < 4; j++) {
                u64 f = *(const u64*)(xS + j * 200 + 2 * kk);
                acc[4*j]   = ffma2(f, wA.x, acc[4*j]);
                acc[4*j+1] = ffma2(f, wA.y, acc[4*j+1]);
                acc[4*j+2] = ffma2(f, wB.x, acc[4*j+2]);
                acc[4*j+3] = ffma2(f, wB.y, acc[4*j+3]);
            }
        }
#pragma unroll
        for (int j = 0; j < 4; j++) {
            if (!rv[j]) continue;
            float2 oA, oB;
            oA.x = res[4*j]   + lo32(acc[4*j])   + hi32(acc[4*j])   + bb2[0];
            oA.y = res[4*j+1] + lo32(acc[4*j+1]) + hi32(acc[4*j+1]) + bb2[1];
            oB.x = res[4*j+2] + lo32(acc[4*j+2]) + hi32(acc[4*j+2]) + bb2[2];
            oB.y = res[4*j+3] + lo32(acc[4*j+3]) + hi32(acc[4*j+3]) + bb2[3];
            size_t rb = (size_t)rid[j] * 128;
            *(float2*)(g_h + rb + c0) = oA;
            *(float2*)(g_h + rb + c1) = oB;
            unsigned hp, lp;
            bf16pair(oA.x, oA.y, hp, lp);
            *(unsigned*)((unsigned short*)g_hh + rb + c0) = hp;
            *(unsigned*)((unsigned short*)g_hl + rb + c0) = lp;
            bf16pair(oB.x, oB.y, hp, lp);
            *(unsigned*)((unsigned short*)g_hh + rb + c1) = hp;
            *(unsigned*)((unsigned short*)g_hl + rb + c1) = lp;
        }
#pragma unroll
        for (int j = 0; j < 4; j++)
            if (rv[j] && lane < 16)
                *(float4*)(g_agg + (size_t)rid[j] * 64 + 4 * lane) =
                    make_float4(0.f, 0.f, 0.f, 0.f);
        __syncwarp();
    }
}
#define NODE_SMEM_BYTES (12288*8 + 8192*8 + 256*4 + 16*800*4)

// ---------------- launch (edge at index 3 for ncu capture) ----------------
extern "C" void kernel_launch(void* const* d_in, const int* in_sizes, int n_in,
                              void* d_out, int out_size) {
    const float* h_in = (const float*)d_in[0];
    const int*   eA   = (const int*)d_in[1];
    const int*   eB   = (const int*)d_in[2];
    const void*  mA   = d_in[3];
    const void*  mB   = d_in[4];
    const float* Wi   = (const float*)d_in[5];
    const float* bi   = (const float*)d_in[6];
    const float* Wo   = (const float*)d_in[7];
    const float* bo   = (const float*)d_in[8];
    const float* ew1  = (const float*)d_in[9];
    const float* eb1  = (const float*)d_in[10];
    const float* ew2  = (const float*)d_in[11];
    const float* eb2  = (const float*)d_in[12];
    const float* nw1  = (const float*)d_in[13];
    const float* nb1  = (const float*)d_in[14];
    const float* nw2  = (const float*)d_in[15];
    const float* nb2  = (const float*)d_in[16];
    float* out = (float*)d_out;

    cudaFuncSetAttribute(edge_kernel, cudaFuncAttributeMaxDynamicSharedMemorySize, EDGE_SMEM_BYTES);
    cudaFuncSetAttribute(node_kernel, cudaFuncAttributeMaxDynamicSharedMemorySize, NODE_SMEM_BYTES);
    cudaFuncSetAttribute(embed_in_kernel, cudaFuncAttributeMaxDynamicSharedMemorySize, EMBI_SMEM);
    cudaFuncSetAttribute(embed_out_kernel, cudaFuncAttributeMaxDynamicSharedMemorySize, EMBO_SMEM);

    detect_mask_kernel<<<1, 256>>>((const unsigned int*)mA);
    compact_kernel<<<3125, 256>>>(eA, mA, 0);
    embed_in_kernel<<<148, 512, EMBI_SMEM>>>(h_in, Wi, bi);
    edge_kernel<<<148, 512, EDGE_SMEM_BYTES>>>(0, ew1, eb1, ew2, eb2, 1.0f);  // ncu slot
    compact_nodes_kernel<<<196, 256>>>(mA, 0);
    node_kernel<<<148, 512, NODE_SMEM_BYTES>>>(0, nw1, nb1, nw2, nb2);
    compact_kernel<<<3125, 256>>>(eB, mB, 1);
    compact_nodes_kernel<<<196, 256>>>(mB, 1);

    for (int i = 1; i < 4; i++) {
        int li = i % 2;
        float C = (li == 0) ? 1.0f : (2.0f / 64.0f);
        edge_kernel<<<148, 512, EDGE_SMEM_BYTES>>>(
            li, ew1 + i * 256 * 64, eb1 + i * 64,
            ew2 + i * 64 * 64, eb2 + i * 64, C);
        node_kernel<<<148, 512, NODE_SMEM_BYTES>>>(
            li, nw1 + i * 192 * 128, nb1 + i * 128,
            nw2 + i * 128 * 128, nb2 + i * 128);
    }

    embed_out_kernel<<<148, 512, EMBO_SMEM>>>(Wo, bo, out);
}

// round 16
// speedup vs baseline: 2.2400x; 1.0302x over previous
#include <cuda_runtime.h>
#include <cuda_bf16.h>

typedef unsigned long long u64;

#define N_NODES 50000
#define N_EDGES 800000
#define HID 128
#define EH 64

// ---------------- scratch ----------------
__device__ float g_h[N_NODES * HID];
__device__ __nv_bfloat16 g_hh[N_NODES * HID];   // bf16 hi mirror of g_h
__device__ __nv_bfloat16 g_hl[N_NODES * HID];   // bf16 lo (residual) mirror
__device__ float g_agg[N_NODES * EH];
__device__ int   g_mask_u8;
__device__ int   g_ne_c[2];
__device__ int   g_rows_c[2][N_EDGES];
__device__ int   g_cols_c[2][N_EDGES];
__device__ int   g_nn_c[2];
__device__ int   g_nodes_c[2][N_NODES];

__device__ __forceinline__ float silu(float x) { return x / (1.0f + __expf(-x)); }
__device__ __forceinline__ u64 ffma2(u64 a, u64 b, u64 c) {
    u64 d; asm("fma.rn.f32x2 %0, %1, %2, %3;" : "=l"(d) : "l"(a), "l"(b), "l"(c)); return d;
}
__device__ __forceinline__ float lo32(u64 a) { return __uint_as_float((unsigned)a); }
__device__ __forceinline__ float hi32(u64 a) { return __uint_as_float((unsigned)(a >> 32)); }
__device__ __forceinline__ u64 packf2(float lo, float hi) {
    return (u64)__float_as_uint(lo) | ((u64)__float_as_uint(hi) << 32);
}
__device__ __forceinline__ void cp16(unsigned d, const void* s) {
    asm volatile("cp.async.cg.shared.global [%0], [%1], 16;" :: "r"(d), "l"(s));
}
__device__ __forceinline__ void cp_commit() { asm volatile("cp.async.commit_group;"); }
template<int N> __device__ __forceinline__ void cp_wait() {
    asm volatile("cp.async.wait_group %0;" :: "n"(N));
}
__device__ __forceinline__ void red2(float* a, float x, float y) {
    asm volatile("red.global.add.v2.f32 [%0], {%1, %2};" :: "l"(a), "f"(x), "f"(y) : "memory");
}
__device__ __forceinline__ void bf16pair(float a, float b, unsigned& hp, unsigned& lp) {
    __nv_bfloat16 ha = __float2bfloat16_rn(a), hb = __float2bfloat16_rn(b);
    __nv_bfloat16 la = __float2bfloat16_rn(a - __bfloat162float(ha));
    __nv_bfloat16 lb = __float2bfloat16_rn(b - __bfloat162float(hb));
    hp = (unsigned)__bfloat16_as_ushort(ha) | ((unsigned)__bfloat16_as_ushort(hb) << 16);
    lp = (unsigned)__bfloat16_as_ushort(la) | ((unsigned)__bfloat16_as_ushort(lb) << 16);
}
// ---- HMMA helpers (sm_80+ PTX) ----
__device__ __forceinline__ void mma_bf16(float* d, const unsigned* a, const unsigned* b) {
    asm volatile("mma.sync.aligned.m16n8k16.row.col.f32.bf16.bf16.f32 "
        "{%0,%1,%2,%3}, {%4,%5,%6,%7}, {%8,%9}, {%0,%1,%2,%3};"
        : "+f"(d[0]), "+f"(d[1]), "+f"(d[2]), "+f"(d[3])
        : "r"(a[0]), "r"(a[1]), "r"(a[2]), "r"(a[3]), "r"(b[0]), "r"(b[1]));
}
__device__ __forceinline__ void ldsm4(unsigned* r, unsigned addr) {
    asm volatile("ldmatrix.sync.aligned.m8n8.x4.shared.b16 {%0,%1,%2,%3}, [%4];"
        : "=r"(r[0]), "=r"(r[1]), "=r"(r[2]), "=r"(r[3]) : "r"(addr));
}
__device__ __forceinline__ void ldsm2(unsigned* r, unsigned addr) {
    asm volatile("ldmatrix.sync.aligned.m8n8.x2.shared.b16 {%0,%1}, [%2];"
        : "=r"(r[0]), "=r"(r[1]) : "r"(addr));
}
// named barrier for one 256-thread half (ids 1,2; 0 reserved for __syncthreads)
__device__ __forceinline__ void barh(int id) {
    asm volatile("bar.sync %0, 256;" :: "r"(id) : "memory");
}

// ---------------- small kernels ----------------
__global__ void detect_mask_kernel(const unsigned int* __restrict__ m) {
    if (threadIdx.x < 2) { g_ne_c[threadIdx.x] = 0; g_nn_c[threadIdx.x] = 0; }
    int bad = 0;
    for (int i = threadIdx.x; i < N_NODES / 4; i += blockDim.x)
        if (m[i] > 1u) bad = 1;
    bad = __syncthreads_or(bad);
    if (threadIdx.x == 0) g_mask_u8 = bad;
}

__global__ void __launch_bounds__(256)
compact_kernel(const int* __restrict__ edges, const void* __restrict__ mask, int li) {
    int e = blockIdx.x * 256 + threadIdx.x, lane = threadIdx.x & 31;
    int mu8 = g_mask_u8;
    bool valid = false; int rv = 0, cv = 0;
    if (e < N_EDGES) {
        rv = edges[e]; cv = edges[e + N_EDGES];
        valid = mu8 ? (((const unsigned char*)mask)[rv] != 0)
                    : (((const int*)mask)[rv] != 0);
    }
    unsigned bal = __ballot_sync(0xffffffffu, valid);
    int base = 0;
    if (lane == 0 && bal) base = atomicAdd(&g_ne_c[li], __popc(bal));
    base = __shfl_sync(0xffffffffu, base, 0);
    if (valid) {
        int p = base + __popc(bal & ((1u << lane) - 1u));
        g_rows_c[li][p] = rv; g_cols_c[li][p] = cv;
    }
}

__global__ void __launch_bounds__(256)
compact_nodes_kernel(const void* __restrict__ mask, int li) {
    int n = blockIdx.x * 256 + threadIdx.x, lane = threadIdx.x & 31;
    int mu8 = g_mask_u8;
    bool valid = false;
    if (n < N_NODES)
        valid = mu8 ? (((const unsigned char*)mask)[n] != 0)
                    : (((const int*)mask)[n] != 0);
    unsigned bal = __ballot_sync(0xffffffffu, valid);
    int base = 0;
    if (lane == 0 && bal) base = atomicAdd(&g_nn_c[li], __popc(bal));
    base = __shfl_sync(0xffffffffu, base, 0);
    if (valid)
        g_nodes_c[li][base + __popc(bal & ((1u << lane) - 1u))] = n;
}

// ---------------- input embedding (FFMA2) + bf16 mirrors + agg zero ----------------
__global__ void __launch_bounds__(512, 1)
embed_in_kernel(const float* __restrict__ h_in, const float* __restrict__ W,
                const float* __restrict__ b) {
    extern __shared__ char smraw[];
    u64* Wp = (u64*)smraw;
    float* bs = (float*)(Wp + 4096);
    float* xAll = bs + 128;
    int tid = threadIdx.x;
    for (int i = tid; i < 4096; i += 512) {
        int kk = i >> 7, c = i & 127;
        Wp[i] = packf2(W[(2 * kk) * 128 + c], W[(2 * kk + 1) * 128 + c]);
    }
    if (tid < 128) bs[tid] = b[tid];
    __syncthreads();
    int wid = tid >> 5, lane = tid & 31;
    float* xS = xAll + wid * 288;
    int c0 = 2 * lane, c1 = 64 + 2 * lane;
    float bb[4] = {bs[c0], bs[c0 + 1], bs[c1], bs[c1 + 1]};
    for (int t = blockIdx.x * 16 + wid; t < N_NODES / 4; t += gridDim.x * 16) {
        int r0 = 4 * t;
        for (int i = lane; i < 64; i += 32) {
            int rr = i >> 4, v = i & 15;
            *(float4*)(xS + rr * 72 + 4 * v) =
                *(const float4*)(h_in + (r0 + rr) * 64 + 4 * v);
        }
        for (int i = lane; i < 64; i += 32)
            *(float4*)(g_agg + (size_t)r0 * 64 + 4 * i) = make_float4(0.f, 0.f, 0.f, 0.f);
        __syncwarp();
        u64 acc[16];
#pragma unroll
        for (int j = 0; j < 16; j++) acc[j] = 0ull;
#pragma unroll 4
        for (int kk = 0; kk < 32; kk++) {
            const u64* wr = Wp + kk * 128;
            ulonglong2 wA = *(const ulonglong2*)(wr + c0);
            ulonglong2 wB = *(const ulonglong2*)(wr + c1);
#pragma unroll
            for (int j = 0; j < 4; j++) {
                u64 f = *(const u64*)(xS + j * 72 + 2 * kk);
                acc[4*j]   = ffma2(f, wA.x, acc[4*j]);
                acc[4*j+1] = ffma2(f, wA.y, acc[4*j+1]);
                acc[4*j+2] = ffma2(f, wB.x, acc[4*j+2]);
                acc[4*j+3] = ffma2(f, wB.y, acc[4*j+3]);
            }
        }
#pragma unroll
        for (int j = 0; j < 4; j++) {
            float2 oA, oB;
            oA.x = lo32(acc[4*j])   + hi32(acc[4*j])   + bb[0];
            oA.y = lo32(acc[4*j+1]) + hi32(acc[4*j+1]) + bb[1];
            oB.x = lo32(acc[4*j+2]) + hi32(acc[4*j+2]) + bb[2];
            oB.y = lo32(acc[4*j+3]) + hi32(acc[4*j+3]) + bb[3];
            size_t rb = (size_t)(r0 + j) * 128;
            *(float2*)(g_h + rb + c0) = oA;
            *(float2*)(g_h + rb + c1) = oB;
            unsigned hp, lp;
            bf16pair(oA.x, oA.y, hp, lp);
            *(unsigned*)((unsigned short*)g_hh + rb + c0) = hp;
            *(unsigned*)((unsigned short*)g_hl + rb + c0) = lp;
            bf16pair(oB.x, oB.y, hp, lp);
            *(unsigned*)((unsigned short*)g_hh + rb + c1) = hp;
            *(unsigned*)((unsigned short*)g_hl + rb + c1) = lp;
        }
        __syncwarp();
    }
}
#define EMBI_SMEM (4096 * 8 + 128 * 4 + 16 * 288 * 4)

// ---------------- output embedding (FFMA2) ----------------
__global__ void __launch_bounds__(512, 1)
embed_out_kernel(const float* __restrict__ W, const float* __restrict__ b,
                 float* __restrict__ out) {
    extern __shared__ char smraw[];
    u64* Wp = (u64*)smraw;
    float* bs = (float*)(Wp + 4096);
    float* xAll = bs + 64;
    int tid = threadIdx.x;
    for (int i = tid; i < 4096; i += 512) {
        int kk = i >> 6, c = i & 63;
        Wp[i] = packf2(W[(2 * kk) * 64 + c], W[(2 * kk + 1) * 64 + c]);
    }
    if (tid < 64) bs[tid] = b[tid];
    __syncthreads();
    int wid = tid >> 5, lane = tid & 31;
    float* xS = xAll + wid * 1088;
    int c0 = 2 * lane;
    float bb0 = bs[c0], bb1 = bs[c0 + 1];
    for (int t = blockIdx.x * 16 + wid; t < N_NODES / 8; t += gridDim.x * 16) {
        int r0 = 8 * t;
        for (int i = lane; i < 256; i += 32) {
            int rr = i >> 5, v = i & 31;
            *(float4*)(xS + rr * 136 + 4 * v) =
                *(const float4*)(g_h + (size_t)(r0 + rr) * 128 + 4 * v);
        }
        __syncwarp();
        u64 acc[16];
#pragma unroll
        for (int j = 0; j < 16; j++) acc[j] = 0ull;
#pragma unroll 4
        for (int kk = 0; kk < 64; kk++) {
            ulonglong2 w = *(const ulonglong2*)(Wp + kk * 64 + c0);
#pragma unroll
            for (int j = 0; j < 8; j++) {
                u64 f = *(const u64*)(xS + j * 136 + 2 * kk);
                acc[2*j]   = ffma2(f, w.x, acc[2*j]);
                acc[2*j+1] = ffma2(f, w.y, acc[2*j+1]);
            }
        }
#pragma unroll
        for (int j = 0; j < 8; j++) {
            float2 o;
            o.x = lo32(acc[2*j])   + hi32(acc[2*j])   + bb0;
            o.y = lo32(acc[2*j+1]) + hi32(acc[2*j+1]) + bb1;
            *(float2*)(out + (size_t)(r0 + j) * 64 + c0) = o;
        }
        __syncwarp();
    }
}
#define EMBO_SMEM (4096 * 8 + 64 * 4 + 16 * 1088 * 4)

// ================= HMMA edge kernel: two independent 256-thread halves =================
// Each half runs its own stream of 64-edge tiles with private buffers + named barrier.
// Warp in half: eg = wid_l & 3 (16-edge group), nh = wid_l >> 2 (32-col half).
#define SO_BIAS1 0
#define SO_BIAS2 256
#define SO_IDX   512         // int[2 halves][2 buf][128]
#define SO_W1H   4608        // [64 n][256 k] bf16, row stride 528
#define SO_W1L   38400
#define SO_W2H   72192       // [64 n][64 k]  bf16, row stride 144
#define SO_W2L   81408
#define SO_FEAT  90624       // per half: AH, AL, BH, BL each 64*272 = 17408
#define HALF_FEAT 69632
#define EDGE_SMEM_BYTES (SO_FEAT + 2 * HALF_FEAT)   // 229888

__device__ __forceinline__ void gather_half(unsigned dstH, unsigned dstL,
                                            const int* idxh, int tid_l) {
#pragma unroll
    for (int i = tid_l; i < 1024; i += 256) {
        int e = i >> 4, c = i & 15;
        size_t src = (size_t)idxh[e] * 128 + c * 8;
        unsigned off = (unsigned)e * 272u + (unsigned)c * 16u;
        cp16(dstH + off, g_hh + src);
        cp16(dstL + off, g_hl + src);
    }
}

__global__ void __launch_bounds__(512, 1)
edge_kernel(int li, const float* __restrict__ W1, const float* __restrict__ b1,
            const float* __restrict__ W2, const float* __restrict__ b2, float C) {
    extern __shared__ char sm[];
    unsigned smb = (unsigned)__cvta_generic_to_shared(sm);
    int tid = threadIdx.x, lane = tid & 31;

    // weights -> smem as W^T [n][k], split bf16 (full CTA)
    for (int i = tid; i < 256 * 64; i += 512) {
        int k = i >> 6, n = i & 63;
        float f = W1[i];
        __nv_bfloat16 hb = __float2bfloat16_rn(f);
        unsigned off = (unsigned)n * 528u + (unsigned)k * 2u;
        *(unsigned short*)(sm + SO_W1H + off) = __bfloat16_as_ushort(hb);
        *(unsigned short*)(sm + SO_W1L + off) =
            __bfloat16_as_ushort(__float2bfloat16_rn(f - __bfloat162float(hb)));
    }
    for (int i = tid; i < 64 * 64; i += 512) {
        int k = i >> 6, n = i & 63;
        float f = W2[i];
        __nv_bfloat16 hb = __float2bfloat16_rn(f);
        unsigned off = (unsigned)n * 144u + (unsigned)k * 2u;
        *(unsigned short*)(sm + SO_W2H + off) = __bfloat16_as_ushort(hb);
        *(unsigned short*)(sm + SO_W2L + off) =
            __bfloat16_as_ushort(__float2bfloat16_rn(f - __bfloat162float(hb)));
    }
    if (tid < 64) {
        ((float*)(sm + SO_BIAS1))[tid] = b1[tid];
        ((float*)(sm + SO_BIAS2))[tid] = b2[tid];
    }
    __syncthreads();   // ONLY full-CTA barrier

    const float* b1s = (const float*)(sm + SO_BIAS1);
    const float* b2s = (const float*)(sm + SO_BIAS2);

    int nE = g_ne_c[li];
    if (nE <= 0) return;
    const int* rows = g_rows_c[li];
    const int* cols = g_cols_c[li];
    int ntiles = (nE + 63) >> 6;

    int h = tid >> 8;             // half id 0/1
    int tid_l = tid & 255;
    int wid_l = tid_l >> 5;
    int eg = wid_l & 3, nh = wid_l >> 2;
    int bid = h + 1;              // named barrier id

    unsigned featb = smb + SO_FEAT + (unsigned)h * HALF_FEAT;
    unsigned AH = featb, AL = featb + 17408u;
    unsigned BH = featb + 34816u, BL = featb + 52224u;
    int* idxbase = (int*)(sm + SO_IDX) + h * 256;

    unsigned e0 = (unsigned)eg * 16u;
    unsigned aoff = (e0 + (unsigned)(lane & 15)) * 272u + (unsigned)((lane >> 4) << 3) * 2u;
    unsigned moff = (e0 + (unsigned)(lane & 15)) * 144u + (unsigned)((lane >> 4) << 3) * 2u;
    unsigned boff1 = (unsigned)(lane & 7) * 528u + (unsigned)(((lane >> 3) & 1) << 3) * 2u;
    unsigned boff2 = (unsigned)(lane & 7) * 144u + (unsigned)(((lane >> 3) & 1) << 3) * 2u;
    unsigned W1Hs = smb + SO_W1H + boff1 + (unsigned)nh * 16896u;
    unsigned W1Ls = smb + SO_W1L + boff1 + (unsigned)nh * 16896u;
    unsigned W2Hs = smb + SO_W2H + boff2 + (unsigned)nh * 4608u;
    unsigned W2Ls = smb + SO_W2L + boff2 + (unsigned)nh * 4608u;
    int g = lane >> 2, q = lane & 3;

    int stride = gridDim.x * 2;
    int t = blockIdx.x * 2 + h, cur = 0;
    if (t < ntiles && tid_l < 128) {
        int e = t * 64 + (tid_l & 63);
        if (e >= nE) e = nE - 1;
        idxbase[tid_l] = (tid_l < 64) ? rows[e] : cols[e];
    }
    barh(bid);
    if (t < ntiles) gather_half(AH, AL, idxbase, tid_l);
    cp_commit();

    for (; t < ntiles; t += stride) {
        int* idx = idxbase + cur * 128;
        gather_half(BH, BL, idx + 64, tid_l);   // cols half of current tile
        cp_commit();
        cp_wait<1>(); barh(bid);                // rows half ready

        float acc[16];
#pragma unroll
        for (int j = 0; j < 16; j++) acc[j] = 0.f;

        // ---- layer1 pass1: k 0..127 (rows features) ----
#pragma unroll
        for (int s = 0; s < 8; s++) {
            unsigned k2 = (unsigned)s * 32u;
            unsigned ah[4], al[4];
            ldsm4(ah, AH + aoff + k2);
            ldsm4(al, AL + aoff + k2);
#pragma unroll
            for (int n = 0; n < 4; n++) {
                unsigned bh[2], bl[2];
                ldsm2(bh, W1Hs + (unsigned)n * 4224u + k2);
                ldsm2(bl, W1Ls + (unsigned)n * 4224u + k2);
                float* d = acc + n * 4;
                mma_bf16(d, ah, bh);
                mma_bf16(d, ah, bl);
                mma_bf16(d, al, bh);
            }
        }
        // next-tile idx + rows gather (rows buffer free after pass1)
        int tn = t + stride;
        int* idxn = idxbase + (cur ^ 1) * 128;
        if (tn < ntiles && tid_l < 128) {
            int e = tn * 64 + (tid_l & 63);
            if (e >= nE) e = nE - 1;
            idxn[tid_l] = (tid_l < 64) ? rows[e] : cols[e];
        }
        barh(bid);                              // pass1 done + idxn visible
        if (tn < ntiles) gather_half(AH, AL, idxn, tid_l);
        cp_commit();
        cp_wait<1>(); barh(bid);                // cols half ready

        // ---- layer1 pass2: k 128..255 (cols features) ----
#pragma unroll
        for (int s = 0; s < 8; s++) {
            unsigned k2 = (unsigned)s * 32u;
            unsigned kw2 = 256u + k2;
            unsigned ah[4], al[4];
            ldsm4(ah, BH + aoff + k2);
            ldsm4(al, BL + aoff + k2);
#pragma unroll
            for (int n = 0; n < 4; n++) {
                unsigned bh[2], bl[2];
                ldsm2(bh, W1Hs + (unsigned)n * 4224u + kw2);
                ldsm2(bl, W1Ls + (unsigned)n * 4224u + kw2);
                float* d = acc + n * 4;
                mma_bf16(d, ah, bh);
                mma_bf16(d, ah, bl);
                mma_bf16(d, al, bh);
            }
        }
        barh(bid);                              // pass2 done before m overwrites BH/BL

        // ---- m = silu(acc + b1) -> split bf16, staged in BH/BL (stride 144) ----
#pragma unroll
        for (int n = 0; n < 4; n++) {
            int col = nh * 32 + 8 * n + 2 * q;
            float bq0 = b1s[col], bq1 = b1s[col + 1];
            float v0 = silu(acc[4*n]   + bq0);
            float v1 = silu(acc[4*n+1] + bq1);
            float v2 = silu(acc[4*n+2] + bq0);
            float v3 = silu(acc[4*n+3] + bq1);
            unsigned hp, lp;
            bf16pair(v0, v1, hp, lp);
            *(unsigned*)(sm + (BH - smb) + (e0 + g) * 144u + col * 2) = hp;
            *(unsigned*)(sm + (BL - smb) + (e0 + g) * 144u + col * 2) = lp;
            bf16pair(v2, v3, hp, lp);
            *(unsigned*)(sm + (BH - smb) + (e0 + g + 8) * 144u + col * 2) = hp;
            *(unsigned*)(sm + (BL - smb) + (e0 + g + 8) * 144u + col * 2) = lp;
        }
        barh(bid);                              // m visible across the half

        // ---- layer2: A = m (ldmatrix from staged buffer) ----
        float acc2[16];
#pragma unroll
        for (int j = 0; j < 16; j++) acc2[j] = 0.f;
#pragma unroll
        for (int s2 = 0; s2 < 4; s2++) {
            unsigned k2 = (unsigned)s2 * 32u;
            unsigned ah[4], al[4];
            ldsm4(ah, BH + moff + k2);
            ldsm4(al, BL + moff + k2);
#pragma unroll
            for (int n = 0; n < 4; n++) {
                unsigned bh[2], bl[2];
                ldsm2(bh, W2Hs + (unsigned)n * 1152u + k2);
                ldsm2(bl, W2Ls + (unsigned)n * 1152u + k2);
                float* d = acc2 + n * 4;
                mma_bf16(d, ah, bh);
                mma_bf16(d, ah, bl);
                mma_bf16(d, al, bh);
            }
        }

        // ---- epilogue: scatter silu(acc2 + b2) * C ----
        int eA_ = t * 64 + (int)e0 + g;
        int eB_ = eA_ + 8;
        float* pa = g_agg + (size_t)idx[e0 + g] * 64;
        float* pb = g_agg + (size_t)idx[e0 + 8 + g] * 64;
        bool vA = eA_ < nE, vB = eB_ < nE;
#pragma unroll
        for (int n = 0; n < 4; n++) {
            int col = nh * 32 + 8 * n + 2 * q;
            float bq0 = b2s[col], bq1 = b2s[col + 1];
            if (vA) red2(pa + col, silu(acc2[4*n]   + bq0) * C,
                                   silu(acc2[4*n+1] + bq1) * C);
            if (vB) red2(pb + col, silu(acc2[4*n+2] + bq0) * C,
                                   silu(acc2[4*n+3] + bq1) * C);
        }
        barh(bid);                              // layer2 reads done before next cols gather
        cur ^= 1;
    }
}

// ---------------- node kernel (FFMA2) + bf16 mirror store + agg re-zero ----------------
__global__ void __launch_bounds__(512, 1)
node_kernel(int li, const float* __restrict__ W1, const float* __restrict__ b1,
            const float* __restrict__ W2, const float* __restrict__ b2) {
    extern __shared__ char smraw[];
    u64* Wp1 = (u64*)smraw;
    u64* Wp2 = Wp1 + 12288;
    float* b1s = (float*)(Wp2 + 8192);
    float* b2s = b1s + 128;
    float* xAll = b2s + 128;
    int tid = threadIdx.x;
    for (int i = tid; i < 12288; i += 512) {
        int kk = i >> 7, c = i & 127;
        Wp1[i] = packf2(W1[(2 * kk) * 128 + c], W1[(2 * kk + 1) * 128 + c]);
    }
    for (int i = tid; i < 8192; i += 512) {
        int kk = i >> 7, c = i & 127;
        Wp2[i] = packf2(W2[(2 * kk) * 128 + c], W2[(2 * kk + 1) * 128 + c]);
    }
    if (tid < 128) { b1s[tid] = b1[tid]; b2s[tid] = b2[tid]; }
    __syncthreads();
    int wid = tid >> 5, lane = tid & 31;
    float* xS = xAll + wid * 800;
    int c0 = 2 * lane, c1 = 64 + 2 * lane;
    float bb1[4] = {b1s[c0], b1s[c0+1], b1s[c1], b1s[c1+1]};
    float bb2[4] = {b2s[c0], b2s[c0+1], b2s[c1], b2s[c1+1]};

    int nn = g_nn_c[li];
    const int* list = g_nodes_c[li];
    int ntiles = (nn + 3) >> 2;
    for (int t = blockIdx.x * 16 + wid; t < ntiles; t += gridDim.x * 16) {
        int rid[4]; bool rv[4];
#pragma unroll
        for (int j = 0; j < 4; j++) {
            int p = 4 * t + j;
            rv[j] = p < nn;
            rid[j] = list[rv[j] ? p : (nn - 1)];
        }
#pragma unroll
        for (int j = 0; j < 4; j++)
            for (int v = lane; v < 48; v += 32) {
                float4 val = (v < 32) ? *(const float4*)(g_h + (size_t)rid[j] * 128 + 4 * v)
                                      : *(const float4*)(g_agg + (size_t)rid[j] * 64 + 4 * (v - 32));
                *(float4*)(xS + j * 200 + 4 * v) = val;
            }
        __syncwarp();
        u64 acc[16];
#pragma unroll
        for (int j = 0; j < 16; j++) acc[j] = 0ull;
#pragma unroll 2
        for (int kk = 0; kk < 96; kk++) {
            const u64* wr = Wp1 + kk * 128;
            ulonglong2 wA = *(const ulonglong2*)(wr + c0);
            ulonglong2 wB = *(const ulonglong2*)(wr + c1);
#pragma unroll
            for (int j = 0; j < 4; j++) {
                u64 f = *(const u64*)(xS + j * 200 + 2 * kk);
                acc[4*j]   = ffma2(f, wA.x, acc[4*j]);
                acc[4*j+1] = ffma2(f, wA.y, acc[4*j+1]);
                acc[4*j+2] = ffma2(f, wB.x, acc[4*j+2]);
                acc[4*j+3] = ffma2(f, wB.y, acc[4*j+3]);
            }
        }
        __syncwarp();
        float res[16];
#pragma unroll
        for (int j = 0; j < 4; j++) {
            res[4*j]   = xS[j * 200 + c0];
            res[4*j+1] = xS[j * 200 + c0 + 1];
            res[4*j+2] = xS[j * 200 + c1];
            res[4*j+3] = xS[j * 200 + c1 + 1];
        }
#pragma unroll
        for (int j = 0; j < 4; j++) {
            float2 mA, mB;
            mA.x = silu(lo32(acc[4*j])   + hi32(acc[4*j])   + bb1[0]);
            mA.y = silu(lo32(acc[4*j+1]) + hi32(acc[4*j+1]) + bb1[1]);
            mB.x = silu(lo32(acc[4*j+2]) + hi32(acc[4*j+2]) + bb1[2]);
            mB.y = silu(lo32(acc[4*j+3]) + hi32(acc[4*j+3]) + bb1[3]);
            *(float2*)(xS + j * 200 + c0) = mA;
            *(float2*)(xS + j * 200 + c1) = mB;
        }
        __syncwarp();
#pragma unroll
        for (int j = 0; j < 16; j++) acc[j] = 0ull;
#pragma unroll 2
        for (int kk = 0; kk < 64; kk++) {
            const u64* wr = Wp2 + kk * 128;
            ulonglong2 wA = *(const ulonglong2*)(wr + c0);
            ulonglong2 wB = *(const ulonglong2*)(wr + c1);
#pragma unroll
            for (int j = 0; j < 4; j++) {
                u64 f = *(const u64*)(xS + j * 200 + 2 * kk);
                acc[4*j]   = ffma2(f, wA.x, acc[4*j]);
                acc[4*j+1] = ffma2(f, wA.y, acc[4*j+1]);
                acc[4*j+2] = ffma2(f, wB.x, acc[4*j+2]);
                acc[4*j+3] = ffma2(f, wB.y, acc[4*j+3]);
            }
        }
#pragma unroll
        for (int j = 0; j < 4; j++) {
            if (!rv[j]) continue;
            float2 oA, oB;
            oA.x = res[4*j]   + lo32(acc[4*j])   + hi32(acc[4*j])   + bb2[0];
            oA.y = res[4*j+1] + lo32(acc[4*j+1]) + hi32(acc[4*j+1]) + bb2[1];
            oB.x = res[4*j+2] + lo32(acc[4*j+2]) + hi32(acc[4*j+2]) + bb2[2];
            oB.y = res[4*j+3] + lo32(acc[4*j+3]) + hi32(acc[4*j+3]) + bb2[3];
            size_t rb = (size_t)rid[j] * 128;
            *(float2*)(g_h + rb + c0) = oA;
            *(float2*)(g_h + rb + c1) = oB;
            unsigned hp, lp;
            bf16pair(oA.x, oA.y, hp, lp);
            *(unsigned*)((unsigned short*)g_hh + rb + c0) = hp;
            *(unsigned*)((unsigned short*)g_hl + rb + c0) = lp;
            bf16pair(oB.x, oB.y, hp, lp);
            *(unsigned*)((unsigned short*)g_hh + rb + c1) = hp;
            *(unsigned*)((unsigned short*)g_hl + rb + c1) = lp;
        }
#pragma unroll
        for (int j = 0; j < 4; j++)
            if (rv[j] && lane < 16)
                *(float4*)(g_agg + (size_t)rid[j] * 64 + 4 * lane) =
                    make_float4(0.f, 0.f, 0.f, 0.f);
        __syncwarp();
    }
}
#define NODE_SMEM_BYTES (12288*8 + 8192*8 + 256*4 + 16*800*4)

// ---------------- launch (edge at index 3 for ncu capture) ----------------
extern "C" void kernel_launch(void* const* d_in, const int* in_sizes, int n_in,
                              void* d_out, int out_size) {
    const float* h_in = (const float*)d_in[0];
    const int*   eA   = (const int*)d_in[1];
    const int*   eB   = (const int*)d_in[2];
    const void*  mA   = d_in[3];
    const void*  mB   = d_in[4];
    const float* Wi   = (const float*)d_in[5];
    const float* bi   = (const float*)d_in[6];
    const float* Wo   = (const float*)d_in[7];
    const float* bo   = (const float*)d_in[8];
    const float* ew1  = (const float*)d_in[9];
    const float* eb1  = (const float*)d_in[10];
    const float* ew2  = (const float*)d_in[11];
    const float* eb2  = (const float*)d_in[12];
    const float* nw1  = (const float*)d_in[13];
    const float* nb1  = (const float*)d_in[14];
    const float* nw2  = (const float*)d_in[15];
    const float* nb2  = (const float*)d_in[16];
    float* out = (float*)d_out;

    cudaFuncSetAttribute(edge_kernel, cudaFuncAttributeMaxDynamicSharedMemorySize, EDGE_SMEM_BYTES);
    cudaFuncSetAttribute(node_kernel, cudaFuncAttributeMaxDynamicSharedMemorySize, NODE_SMEM_BYTES);
    cudaFuncSetAttribute(embed_in_kernel, cudaFuncAttributeMaxDynamicSharedMemorySize, EMBI_SMEM);
    cudaFuncSetAttribute(embed_out_kernel, cudaFuncAttributeMaxDynamicSharedMemorySize, EMBO_SMEM);

    detect_mask_kernel<<<1, 256>>>((const unsigned int*)mA);
    compact_kernel<<<3125, 256>>>(eA, mA, 0);
    embed_in_kernel<<<148, 512, EMBI_SMEM>>>(h_in, Wi, bi);
    edge_kernel<<<148, 512, EDGE_SMEM_BYTES>>>(0, ew1, eb1, ew2, eb2, 1.0f);  // ncu slot
    compact_nodes_kernel<<<196, 256>>>(mA, 0);
    node_kernel<<<148, 512, NODE_SMEM_BYTES>>>(0, nw1, nb1, nw2, nb2);
    compact_kernel<<<3125, 256>>>(eB, mB, 1);
    compact_nodes_kernel<<<196, 256>>>(mB, 1);

    for (int i = 1; i < 4; i++) {
        int li = i % 2;
        float C = (li == 0) ? 1.0f : (2.0f / 64.0f);
        edge_kernel<<<148, 512, EDGE_SMEM_BYTES>>>(
            li, ew1 + i * 256 * 64, eb1 + i * 64,
            ew2 + i * 64 * 64, eb2 + i * 64, C);
        node_kernel<<<148, 512, NODE_SMEM_BYTES>>>(
            li, nw1 + i * 192 * 128, nb1 + i * 128,
            nw2 + i * 128 * 128, nb2 + i * 128);
    }

    embed_out_kernel<<<148, 512, EMBO_SMEM>>>(Wo, bo, out);
}